// round 4
// baseline (speedup 1.0000x reference)
#include <cuda_runtime.h>
#include <cstdint>

#define N_NODES 50000
#define N_EDGES 800000
#define NE_TOT  (N_EDGES + N_NODES)   // 850000, self loops appended
#define NG 16

typedef unsigned long long ull;

// ---------------- scratch (static device memory; no allocs allowed) ----------------
__device__ __align__(16) float g_big1[N_NODES * 192];   // 0-63 xl1 | 64-127 xr1 | 128-191 hproj1
__device__ __align__(16) float g_big2[N_NODES * 96];    // 0-31 xl2 | 32-63 xr2 | 64-95 hproj2
__device__ __align__(16) float g_out1[N_NODES * 64];
__device__ __align__(16) float g_h[N_NODES * 64];
__device__ __align__(16) float g_out2[N_NODES * 32];
__device__ int g_deg[N_NODES];
__device__ int g_rowptr[N_NODES + 1];
__device__ int g_fill[N_NODES];
__device__ int g_perm[NE_TOT];
__device__ int g_psrc[NE_TOT];
__device__ __align__(16) float g_Wcat1[128 * 192];
__device__ __align__(16) float g_bcat1[192];
__device__ __align__(16) float g_Wcat2[64 * 96];
__device__ __align__(16) float g_bcat2[96];
__device__ __align__(16) float g_easum[16];
__device__ __align__(16) float g_eself1[64];
__device__ __align__(16) float g_eself2[32];
__device__ __align__(16) float g_bnsum[128];     // [0:64) sum, [64:128) sumsq
__device__ __align__(16) float g_bnsc1[128];     // [0:64) scale, [64:128) shift
__device__ __align__(16) float g_bnsum2[64];
__device__ __align__(16) float g_bnsc2[64];
__device__ __align__(16) float g_psum[NG * 32];
__device__ __align__(16) float g_pmax[NG * 32];
__device__ int g_cnt[NG];

// ---------------- helpers ----------------
__device__ __forceinline__ ull pk2(float a, float b) {
    ull r; asm("mov.b64 %0,{%1,%2};" : "=l"(r) : "f"(a), "f"(b)); return r;
}
__device__ __forceinline__ float2 up2(ull v) {
    float2 r; asm("mov.b64 {%0,%1},%2;" : "=f"(r.x), "=f"(r.y) : "l"(v)); return r;
}
__device__ __forceinline__ ull fma2(ull a, ull b, ull c) {
    ull d; asm("fma.rn.f32x2 %0,%1,%2,%3;" : "=l"(d) : "l"(a), "l"(b), "l"(c)); return d;
}
__device__ __forceinline__ ull add2(ull a, ull b) {
    ull d; asm("add.rn.f32x2 %0,%1,%2;" : "=l"(d) : "l"(a), "l"(b)); return d;
}
__device__ __forceinline__ void atomicMaxF(float* addr, float v) {
    if (v >= 0.f) atomicMax((int*)addr, __float_as_int(v));
    else          atomicMin((unsigned int*)addr, __float_as_uint(v));
}

// ---------------- setup: clears + deg init ----------------
__global__ void setup_kernel() {
    int i  = blockIdx.x * blockDim.x + threadIdx.x;
    int st = gridDim.x * blockDim.x;
    for (int j = i; j < N_NODES; j += st) g_deg[j] = 1;   // self loop counted
    if (i < 16)  g_easum[i] = 0.f;
    if (i < 128) g_bnsum[i] = 0.f;
    if (i < 64)  g_bnsum2[i] = 0.f;
    if (i < NG * 32) { g_psum[i] = 0.f; g_pmax[i] = __int_as_float(0xff800000); }
    if (i < NG)  g_cnt[i] = 0;
}

// ---------------- weight packing ----------------
__global__ void pack1_kernel(const float* __restrict__ Wl, const float* __restrict__ bl,
                             const float* __restrict__ Wr, const float* __restrict__ br,
                             const float* __restrict__ Ws, const float* __restrict__ bs) {
    int i = blockIdx.x * blockDim.x + threadIdx.x;
    if (i < 128 * 64) {
        int k = i >> 6, j = i & 63;
        g_Wcat1[k * 192 + j]       = Wl[i];
        g_Wcat1[k * 192 + 64 + j]  = Wr[i];
        g_Wcat1[k * 192 + 128 + j] = Ws[i];
    }
    if (i < 64) { g_bcat1[i] = bl[i]; g_bcat1[64 + i] = br[i]; g_bcat1[128 + i] = bs[i]; }
}

__global__ void pack2_kernel(const float* __restrict__ Wl, const float* __restrict__ bl,
                             const float* __restrict__ Wr, const float* __restrict__ br,
                             const float* __restrict__ Ws, const float* __restrict__ bs) {
    int i = blockIdx.x * blockDim.x + threadIdx.x;
    if (i < 64 * 32) {
        int k = i >> 5, j = i & 31;
        g_Wcat2[k * 96 + j]      = Wl[i];
        g_Wcat2[k * 96 + 32 + j] = Wr[i];
        g_Wcat2[k * 96 + 64 + j] = Ws[i];
    }
    if (i < 32) { g_bcat2[i] = bl[i]; g_bcat2[32 + i] = br[i]; g_bcat2[64 + i] = bs[i]; }
}

// ---------------- edge_attr column sums (float4, MLP-friendly) ----------------
__global__ void easum_kernel(const float4* __restrict__ ea4) {
    int tid = blockIdx.x * blockDim.x + threadIdx.x;
    int st  = gridDim.x * blockDim.x;              // multiple of 4
    int grp = tid & 3;                             // which float4 of the 16-col row
    float4 s = make_float4(0.f, 0.f, 0.f, 0.f);
    for (int i = tid; i < N_EDGES * 4; i += st) {
        float4 v = ea4[i];
        s.x += v.x; s.y += v.y; s.z += v.z; s.w += v.w;
    }
    __shared__ float sm[16];
    if (threadIdx.x < 16) sm[threadIdx.x] = 0.f;
    __syncthreads();
    atomicAdd(&sm[grp * 4 + 0], s.x);
    atomicAdd(&sm[grp * 4 + 1], s.y);
    atomicAdd(&sm[grp * 4 + 2], s.z);
    atomicAdd(&sm[grp * 4 + 3], s.w);
    __syncthreads();
    if (threadIdx.x < 16) atomicAdd(&g_easum[threadIdx.x], sm[threadIdx.x]);
}

__global__ void eself_kernel(const float* __restrict__ We1, const float* __restrict__ We2) {
    __shared__ float m[16];
    int t = threadIdx.x;
    if (t < 16) m[t] = g_easum[t] * (1.0f / N_EDGES);
    __syncthreads();
    if (t < 64) {
        float s = 0.f;
        #pragma unroll
        for (int k = 0; k < 16; k++) s += m[k] * We1[k * 64 + t];
        g_eself1[t] = s;
    }
    if (t < 32) {
        float s = 0.f;
        #pragma unroll
        for (int k = 0; k < 16; k++) s += m[k] * We2[k * 32 + t];
        g_eself2[t] = s;
    }
}

// ---------------- CSR build ----------------
__global__ void hist_kernel(const int* __restrict__ ei) {
    int i  = blockIdx.x * blockDim.x + threadIdx.x;
    int st = gridDim.x * blockDim.x;
    for (int e = i; e < N_EDGES; e += st)
        atomicAdd(&g_deg[ei[N_EDGES + e]], 1);
}

__global__ void scan_kernel() {   // 1 block, 1024 threads
    __shared__ int sp[1024];
    int t = threadIdx.x;
    const int CH = (N_NODES + 1023) / 1024;  // 49
    int b = t * CH;
    int e = b + CH; if (e > N_NODES) e = N_NODES;
    int s = 0;
    for (int i = b; i < e; i++) s += g_deg[i];
    sp[t] = s;
    __syncthreads();
    for (int off = 1; off < 1024; off <<= 1) {
        int v = (t >= off) ? sp[t - off] : 0;
        __syncthreads();
        sp[t] += v;
        __syncthreads();
    }
    int run = (t > 0) ? sp[t - 1] : 0;
    for (int i = b; i < e; i++) {
        g_rowptr[i] = run;
        g_fill[i]   = run;
        run += g_deg[i];
    }
    if (t == 1023) g_rowptr[N_NODES] = sp[1023];
}

__global__ void scatter_kernel(const int* __restrict__ ei) {
    int i  = blockIdx.x * blockDim.x + threadIdx.x;
    int st = gridDim.x * blockDim.x;
    for (int e = i; e < NE_TOT; e += st) {
        if (e < N_EDGES) {
            int d = ei[N_EDGES + e];
            int s = ei[e];
            int pos = atomicAdd(&g_fill[d], 1);
            g_perm[pos] = e;
            g_psrc[pos] = s;
        } else {
            int n = e - N_EDGES;
            int pos = atomicAdd(&g_fill[n], 1);
            g_perm[pos] = -1;          // self-loop marker
            g_psrc[pos] = n;
        }
    }
}

// ---------------- tiled GEMM with fma.rn.f32x2: C[M,NT] = A[M,K] @ W[K,NT] + bias ----------------
template <int K, int NT>
__device__ __forceinline__ void gemm_body(const float* __restrict__ A,
                                          const float* __restrict__ W,
                                          const float* __restrict__ bias,
                                          float* __restrict__ C, int M) {
    __shared__ __align__(16) float As[16 * 68];   // [k][row], padded: float4-aligned
    __shared__ __align__(8)  float Bs[16 * 100];  // [k][col]
    const int bm = blockIdx.x * 64;
    const int bn = blockIdx.y * 96;
    const int tid = threadIdx.x;
    const int tx = tid & 15, ty = tid >> 4;
    ull acc[4][3];
    #pragma unroll
    for (int i = 0; i < 4; i++)
        #pragma unroll
        for (int j = 0; j < 3; j++) acc[i][j] = 0ull;
    const int ar = tid >> 2, ac = (tid & 3) << 2;
    for (int k0 = 0; k0 < K; k0 += 16) {
        float4 av = make_float4(0.f, 0.f, 0.f, 0.f);
        int row = bm + ar;
        if (row < M) av = *(const float4*)&A[(size_t)row * K + k0 + ac];
        As[(ac + 0) * 68 + ar] = av.x;
        As[(ac + 1) * 68 + ar] = av.y;
        As[(ac + 2) * 68 + ar] = av.z;
        As[(ac + 3) * 68 + ar] = av.w;
        #pragma unroll
        for (int i = 0; i < 6; i++) {
            int idx = tid + (i << 8);
            int r = idx / 96, cc = idx - r * 96;
            Bs[r * 100 + cc] = W[(k0 + r) * NT + bn + cc];
        }
        __syncthreads();
        #pragma unroll
        for (int kk = 0; kk < 16; kk++) {
            float4 a = *(const float4*)&As[kk * 68 + (ty << 2)];
            ull b0 = *(const ull*)&Bs[kk * 100 + tx * 6];
            ull b1 = *(const ull*)&Bs[kk * 100 + tx * 6 + 2];
            ull b2 = *(const ull*)&Bs[kk * 100 + tx * 6 + 4];
            ull ap;
            ap = pk2(a.x, a.x);
            acc[0][0] = fma2(ap, b0, acc[0][0]); acc[0][1] = fma2(ap, b1, acc[0][1]); acc[0][2] = fma2(ap, b2, acc[0][2]);
            ap = pk2(a.y, a.y);
            acc[1][0] = fma2(ap, b0, acc[1][0]); acc[1][1] = fma2(ap, b1, acc[1][1]); acc[1][2] = fma2(ap, b2, acc[1][2]);
            ap = pk2(a.z, a.z);
            acc[2][0] = fma2(ap, b0, acc[2][0]); acc[2][1] = fma2(ap, b1, acc[2][1]); acc[2][2] = fma2(ap, b2, acc[2][2]);
            ap = pk2(a.w, a.w);
            acc[3][0] = fma2(ap, b0, acc[3][0]); acc[3][1] = fma2(ap, b1, acc[3][1]); acc[3][2] = fma2(ap, b2, acc[3][2]);
        }
        __syncthreads();
    }
    #pragma unroll
    for (int i = 0; i < 4; i++) {
        int r = bm + (ty << 2) + i;
        if (r < M) {
            #pragma unroll
            for (int j = 0; j < 3; j++) {
                float2 v = up2(acc[i][j]);
                int cc = bn + tx * 6 + 2 * j;
                C[(size_t)r * NT + cc]     = v.x + bias[cc];
                C[(size_t)r * NT + cc + 1] = v.y + bias[cc + 1];
            }
        }
    }
}

__global__ void gemm1_kernel(const float* __restrict__ A) {
    gemm_body<128, 192>(A, g_Wcat1, g_bcat1, g_big1, N_NODES);
}
__global__ void gemm2_kernel() {
    gemm_body<64, 96>(g_h, g_Wcat2, g_bcat2, g_big2, N_NODES);
}

// ---------------- gather layer 1 (H=2,C=32; 1 warp per dst, 2 ch/lane, We in regs) ----------------
__global__ void __launch_bounds__(256) gather1_kernel(const float* __restrict__ ea,
                                                      const float* __restrict__ We,
                                                      const float* __restrict__ att,
                                                      const float* __restrict__ bias) {
    const int lane = threadIdx.x & 31;
    const int wid  = (blockIdx.x * blockDim.x + threadIdx.x) >> 5;
    const int nw   = (gridDim.x * blockDim.x) >> 5;
    ull wreg[16];
    #pragma unroll
    for (int k = 0; k < 16; k++) wreg[k] = *(const ull*)&We[k * 64 + 2 * lane];
    const float2 a2  = *(const float2*)&att[2 * lane];
    const float2 es2 = *(const float2*)&g_eself1[2 * lane];
    const float2 b2  = *(const float2*)&bias[2 * lane];
    float2 bs = make_float2(0.f, 0.f), bq = make_float2(0.f, 0.f);

    for (int d = wid; d < N_NODES; d += nw) {
        const int beg = g_rowptr[d], end = g_rowptr[d + 1];
        const float2 xr = *(const float2*)&g_big1[(size_t)d * 192 + 64 + 2 * lane];
        float2 acc = make_float2(0.f, 0.f);
        float den = 0.f;
        for (int j = beg; j < end; j++) {
            int pe = g_perm[j];
            int s  = g_psrc[j];
            float2 xl = *(const float2*)&g_big1[(size_t)s * 192 + 2 * lane];
            float2 ev;
            if (pe >= 0) {
                const float4* eap = (const float4*)(ea + (size_t)pe * 16);
                float4 e0 = eap[0], e1 = eap[1], e2 = eap[2], e3 = eap[3];  // uniform, warp-broadcast
                ull c0 = 0ull, c1 = 0ull;
                c0 = fma2(pk2(e0.x, e0.x), wreg[0],  c0);
                c1 = fma2(pk2(e0.y, e0.y), wreg[1],  c1);
                c0 = fma2(pk2(e0.z, e0.z), wreg[2],  c0);
                c1 = fma2(pk2(e0.w, e0.w), wreg[3],  c1);
                c0 = fma2(pk2(e1.x, e1.x), wreg[4],  c0);
                c1 = fma2(pk2(e1.y, e1.y), wreg[5],  c1);
                c0 = fma2(pk2(e1.z, e1.z), wreg[6],  c0);
                c1 = fma2(pk2(e1.w, e1.w), wreg[7],  c1);
                c0 = fma2(pk2(e2.x, e2.x), wreg[8],  c0);
                c1 = fma2(pk2(e2.y, e2.y), wreg[9],  c1);
                c0 = fma2(pk2(e2.z, e2.z), wreg[10], c0);
                c1 = fma2(pk2(e2.w, e2.w), wreg[11], c1);
                c0 = fma2(pk2(e3.x, e3.x), wreg[12], c0);
                c1 = fma2(pk2(e3.y, e3.y), wreg[13], c1);
                c0 = fma2(pk2(e3.z, e3.z), wreg[14], c0);
                c1 = fma2(pk2(e3.w, e3.w), wreg[15], c1);
                ev = up2(add2(c0, c1));
            } else {
                ev = es2;
            }
            float ux = xl.x + xr.x + ev.x;
            float uy = xl.y + xr.y + ev.y;
            ux = ux > 0.f ? ux : 0.2f * ux;
            uy = uy > 0.f ? uy : 0.2f * uy;
            float p = ux * a2.x + uy * a2.y;
            p += __shfl_xor_sync(0xffffffffu, p, 8);   // stays within 16-lane head
            p += __shfl_xor_sync(0xffffffffu, p, 4);
            p += __shfl_xor_sync(0xffffffffu, p, 2);
            p += __shfl_xor_sync(0xffffffffu, p, 1);
            float w = __expf(p);
            acc.x += w * xl.x; acc.y += w * xl.y;
            den += w;
        }
        float inv = 1.0f / (den + 1e-16f);
        float2 o = make_float2(acc.x * inv + b2.x, acc.y * inv + b2.y);
        *(float2*)&g_out1[(size_t)d * 64 + 2 * lane] = o;
        bs.x += o.x; bs.y += o.y;
        bq.x += o.x * o.x; bq.y += o.y * o.y;
    }
    __shared__ float sbs[64], sbq[64];
    if (threadIdx.x < 64) { sbs[threadIdx.x] = 0.f; sbq[threadIdx.x] = 0.f; }
    __syncthreads();
    atomicAdd(&sbs[2 * lane],     bs.x);
    atomicAdd(&sbs[2 * lane + 1], bs.y);
    atomicAdd(&sbq[2 * lane],     bq.x);
    atomicAdd(&sbq[2 * lane + 1], bq.y);
    __syncthreads();
    if (threadIdx.x < 64) {
        atomicAdd(&g_bnsum[threadIdx.x],      sbs[threadIdx.x]);
        atomicAdd(&g_bnsum[64 + threadIdx.x], sbq[threadIdx.x]);
    }
}

// ---------------- gather layer 2 (H=1,C=32; 16-lane group per dst, 2 ch/lane) ----------------
__global__ void __launch_bounds__(256) gather2_kernel(const float* __restrict__ ea,
                                                      const float* __restrict__ We,
                                                      const float* __restrict__ att,
                                                      const float* __restrict__ bias) {
    const int lane = threadIdx.x & 31;
    const int half = lane >> 4;
    const int sub  = lane & 15;
    const int gg   = (((blockIdx.x * blockDim.x + threadIdx.x) >> 5) << 1) + half;
    const int ngr  = ((gridDim.x * blockDim.x) >> 5) << 1;
    const unsigned m = 0xFFFFu << (half * 16);
    ull wreg[16];
    #pragma unroll
    for (int k = 0; k < 16; k++) wreg[k] = *(const ull*)&We[k * 32 + 2 * sub];
    const float2 a2  = *(const float2*)&att[2 * sub];
    const float2 es2 = *(const float2*)&g_eself2[2 * sub];
    const float2 b2  = *(const float2*)&bias[2 * sub];
    float2 bs = make_float2(0.f, 0.f), bq = make_float2(0.f, 0.f);

    for (int d = gg; d < N_NODES; d += ngr) {
        const int beg = g_rowptr[d], end = g_rowptr[d + 1];
        const float2 xr = *(const float2*)&g_big2[(size_t)d * 96 + 32 + 2 * sub];
        float2 acc = make_float2(0.f, 0.f);
        float den = 0.f;
        for (int j = beg; j < end; j++) {
            int pe = g_perm[j];
            int s  = g_psrc[j];
            float2 xl = *(const float2*)&g_big2[(size_t)s * 96 + 2 * sub];
            float2 ev;
            if (pe >= 0) {
                const float4* eap = (const float4*)(ea + (size_t)pe * 16);
                float4 e0 = eap[0], e1 = eap[1], e2 = eap[2], e3 = eap[3];
                ull c0 = 0ull, c1 = 0ull;
                c0 = fma2(pk2(e0.x, e0.x), wreg[0],  c0);
                c1 = fma2(pk2(e0.y, e0.y), wreg[1],  c1);
                c0 = fma2(pk2(e0.z, e0.z), wreg[2],  c0);
                c1 = fma2(pk2(e0.w, e0.w), wreg[3],  c1);
                c0 = fma2(pk2(e1.x, e1.x), wreg[4],  c0);
                c1 = fma2(pk2(e1.y, e1.y), wreg[5],  c1);
                c0 = fma2(pk2(e1.z, e1.z), wreg[6],  c0);
                c1 = fma2(pk2(e1.w, e1.w), wreg[7],  c1);
                c0 = fma2(pk2(e2.x, e2.x), wreg[8],  c0);
                c1 = fma2(pk2(e2.y, e2.y), wreg[9],  c1);
                c0 = fma2(pk2(e2.z, e2.z), wreg[10], c0);
                c1 = fma2(pk2(e2.w, e2.w), wreg[11], c1);
                c0 = fma2(pk2(e3.x, e3.x), wreg[12], c0);
                c1 = fma2(pk2(e3.y, e3.y), wreg[13], c1);
                c0 = fma2(pk2(e3.z, e3.z), wreg[14], c0);
                c1 = fma2(pk2(e3.w, e3.w), wreg[15], c1);
                ev = up2(add2(c0, c1));
            } else {
                ev = es2;
            }
            float ux = xl.x + xr.x + ev.x;
            float uy = xl.y + xr.y + ev.y;
            ux = ux > 0.f ? ux : 0.2f * ux;
            uy = uy > 0.f ? uy : 0.2f * uy;
            float p = ux * a2.x + uy * a2.y;
            p += __shfl_xor_sync(m, p, 8);
            p += __shfl_xor_sync(m, p, 4);
            p += __shfl_xor_sync(m, p, 2);
            p += __shfl_xor_sync(m, p, 1);
            float w = __expf(p);
            acc.x += w * xl.x; acc.y += w * xl.y;
            den += w;
        }
        float inv = 1.0f / (den + 1e-16f);
        float2 o = make_float2(acc.x * inv + b2.x, acc.y * inv + b2.y);
        *(float2*)&g_out2[(size_t)d * 32 + 2 * sub] = o;
        bs.x += o.x; bs.y += o.y;
        bq.x += o.x * o.x; bq.y += o.y * o.y;
    }
    __shared__ float sbs[32], sbq[32];
    if (threadIdx.x < 32) { sbs[threadIdx.x] = 0.f; sbq[threadIdx.x] = 0.f; }
    __syncthreads();
    atomicAdd(&sbs[2 * sub],     bs.x);
    atomicAdd(&sbs[2 * sub + 1], bs.y);
    atomicAdd(&sbq[2 * sub],     bq.x);
    atomicAdd(&sbq[2 * sub + 1], bq.y);
    __syncthreads();
    if (threadIdx.x < 32) {
        atomicAdd(&g_bnsum2[threadIdx.x],      sbs[threadIdx.x]);
        atomicAdd(&g_bnsum2[32 + threadIdx.x], sbq[threadIdx.x]);
    }
}

// ---------------- BN finalize ----------------
__global__ void bnfin1_kernel(const float* __restrict__ g, const float* __restrict__ b) {
    int c = threadIdx.x;
    if (c < 64) {
        float mean = g_bnsum[c] * (1.0f / N_NODES);
        float var  = g_bnsum[64 + c] * (1.0f / N_NODES) - mean * mean;
        float sc   = g[c] * rsqrtf(var + 1e-5f);
        g_bnsc1[c] = sc;
        g_bnsc1[64 + c] = b[c] - mean * sc;
    }
}

__global__ void elu1_kernel() {
    int i = blockIdx.x * blockDim.x + threadIdx.x;
    int st = gridDim.x * blockDim.x;
    for (; i < N_NODES * 64; i += st) {
        int n = i >> 6, c = i & 63;
        float v = g_out1[i] * g_bnsc1[c] + g_bnsc1[64 + c] + g_big1[(size_t)n * 192 + 128 + c];
        g_h[i] = v > 0.f ? v : expm1f(v);
    }
}

__global__ void bnfin2_kernel(const float* __restrict__ g, const float* __restrict__ b) {
    int c = threadIdx.x;
    if (c < 32) {
        float mean = g_bnsum2[c] * (1.0f / N_NODES);
        float var  = g_bnsum2[32 + c] * (1.0f / N_NODES) - mean * mean;
        float sc   = g[c] * rsqrtf(var + 1e-5f);
        g_bnsc2[c] = sc;
        g_bnsc2[32 + c] = b[c] - mean * sc;
    }
}

// ---------------- elu2 + graph pooling (batch sorted) ----------------
__global__ void elu2pool_kernel(const int* __restrict__ batch) {
    __shared__ float ssum[NG * 32];
    __shared__ float smax[NG * 32];
    __shared__ int scnt[NG];
    int tid = threadIdx.x;
    for (int i = tid; i < NG * 32; i += blockDim.x) { ssum[i] = 0.f; smax[i] = __int_as_float(0xff800000); }
    if (tid < NG) scnt[tid] = 0;
    __syncthreads();
    int c = tid & 31;
    for (int n = blockIdx.x * 8 + (tid >> 5); n < N_NODES; n += gridDim.x * 8) {
        float v = g_out2[(size_t)n * 32 + c] * g_bnsc2[c] + g_bnsc2[32 + c] + g_big2[(size_t)n * 96 + 64 + c];
        v = v > 0.f ? v : expm1f(v);
        int g = batch[n];
        atomicAdd(&ssum[g * 32 + c], v);
        if (v >= 0.f) atomicMax((int*)&smax[g * 32 + c], __float_as_int(v));
        else          atomicMin((unsigned int*)&smax[g * 32 + c], __float_as_uint(v));
        if (c == 0) atomicAdd(&scnt[g], 1);
    }
    __syncthreads();
    for (int i = tid; i < NG * 32; i += blockDim.x) {
        atomicAdd(&g_psum[i], ssum[i]);
        atomicMaxF(&g_pmax[i], smax[i]);
    }
    if (tid < NG) atomicAdd(&g_cnt[tid], scnt[tid]);
}

__global__ void finalout_kernel(float* __restrict__ out) {
    int tid = threadIdx.x;
    if (tid < NG * 64) {
        int g = tid >> 6, j = tid & 63;
        int cnt = g_cnt[g];
        float r;
        if (j < 32) r = g_psum[g * 32 + j] / fmaxf((float)cnt, 1.0f);
        else        r = (cnt > 0) ? g_pmax[g * 32 + (j - 32)] : 0.0f;
        out[tid] = r;
    }
}

// ---------------- launch ----------------
extern "C" void kernel_launch(void* const* d_in, const int* in_sizes, int n_in,
                              void* d_out, int out_size) {
    const float* x     = (const float*)d_in[0];
    const int*   ei    = (const int*)d_in[1];
    const float* ea    = (const float*)d_in[2];
    const int*   batch = (const int*)d_in[3];
    const float* s1W = (const float*)d_in[4];
    const float* s1b = (const float*)d_in[5];
    const float* c1Wl = (const float*)d_in[6];
    const float* c1bl = (const float*)d_in[7];
    const float* c1Wr = (const float*)d_in[8];
    const float* c1br = (const float*)d_in[9];
    const float* c1We = (const float*)d_in[10];
    const float* c1att = (const float*)d_in[11];
    const float* c1bias = (const float*)d_in[12];
    const float* bn1g = (const float*)d_in[13];
    const float* bn1b = (const float*)d_in[14];
    const float* s2W = (const float*)d_in[15];
    const float* s2b = (const float*)d_in[16];
    const float* c2Wl = (const float*)d_in[17];
    const float* c2bl = (const float*)d_in[18];
    const float* c2Wr = (const float*)d_in[19];
    const float* c2br = (const float*)d_in[20];
    const float* c2We = (const float*)d_in[21];
    const float* c2att = (const float*)d_in[22];
    const float* c2bias = (const float*)d_in[23];
    const float* bn2g = (const float*)d_in[24];
    const float* bn2b = (const float*)d_in[25];
    float* out = (float*)d_out;

    setup_kernel<<<256, 256>>>();
    pack1_kernel<<<32, 256>>>(c1Wl, c1bl, c1Wr, c1br, s1W, s1b);
    pack2_kernel<<<8, 256>>>(c2Wl, c2bl, c2Wr, c2br, s2W, s2b);
    easum_kernel<<<1024, 256>>>((const float4*)ea);
    hist_kernel<<<512, 256>>>(ei);
    scan_kernel<<<1, 1024>>>();
    scatter_kernel<<<512, 256>>>(ei);
    eself_kernel<<<1, 64>>>(c1We, c2We);

    gemm1_kernel<<<dim3((N_NODES + 63) / 64, 2), 256>>>(x);
    gather1_kernel<<<1024, 256>>>(ea, c1We, c1att, c1bias);
    bnfin1_kernel<<<1, 64>>>(bn1g, bn1b);
    elu1_kernel<<<2048, 256>>>();

    gemm2_kernel<<<dim3((N_NODES + 63) / 64, 1), 256>>>();
    gather2_kernel<<<512, 256>>>(ea, c2We, c2att, c2bias);
    bnfin2_kernel<<<1, 32>>>(bn2g, bn2b);
    elu2pool_kernel<<<256, 256>>>(batch);
    finalout_kernel<<<1, 1024>>>(out);
}

// round 5
// speedup vs baseline: 1.1680x; 1.1680x over previous
#include <cuda_runtime.h>
#include <cstdint>

#define N_NODES 50000
#define N_EDGES 800000
#define NE_TOT  (N_EDGES + N_NODES)   // 850000, self loops appended
#define NG 16

typedef unsigned long long ull;

// ---------------- scratch (static device memory; no allocs allowed) ----------------
__device__ __align__(16) float g_big1[N_NODES * 192];   // 0-63 xl1 | 64-127 xr1 | 128-191 hproj1
__device__ __align__(16) float g_big2[N_NODES * 96];    // 0-31 xl2 | 32-63 xr2 | 64-95 hproj2
__device__ __align__(16) float g_acc1[N_NODES * 64];
__device__ __align__(16) float g_den1[N_NODES * 2];
__device__ __align__(16) float g_out1[N_NODES * 64];
__device__ __align__(16) float g_h[N_NODES * 64];
__device__ __align__(16) float g_acc2[N_NODES * 32];
__device__ __align__(16) float g_den2[N_NODES];
__device__ __align__(16) float g_out2[N_NODES * 32];
__device__ __align__(16) float g_Wcat1[128 * 192];
__device__ __align__(16) float g_bcat1[192];
__device__ __align__(16) float g_Wcat2[64 * 96];
__device__ __align__(16) float g_bcat2[96];
__device__ __align__(16) float g_easum[16];
__device__ __align__(16) float g_eself1[64];
__device__ __align__(16) float g_eself2[32];
__device__ __align__(16) float g_bnsum[128];     // [0:64) sum, [64:128) sumsq
__device__ __align__(16) float g_bnsc1[128];     // [0:64) scale, [64:128) shift
__device__ __align__(16) float g_bnsum2[64];
__device__ __align__(16) float g_bnsc2[64];
__device__ __align__(16) float g_psum[NG * 32];
__device__ __align__(16) float g_pmax[NG * 32];
__device__ int g_cnt[NG];

// ---------------- helpers ----------------
__device__ __forceinline__ ull pk2(float a, float b) {
    ull r; asm("mov.b64 %0,{%1,%2};" : "=l"(r) : "f"(a), "f"(b)); return r;
}
__device__ __forceinline__ float2 up2(ull v) {
    float2 r; asm("mov.b64 {%0,%1},%2;" : "=f"(r.x), "=f"(r.y) : "l"(v)); return r;
}
__device__ __forceinline__ ull fma2(ull a, ull b, ull c) {
    ull d; asm("fma.rn.f32x2 %0,%1,%2,%3;" : "=l"(d) : "l"(a), "l"(b), "l"(c)); return d;
}
__device__ __forceinline__ ull add2(ull a, ull b) {
    ull d; asm("add.rn.f32x2 %0,%1,%2;" : "=l"(d) : "l"(a), "l"(b)); return d;
}
__device__ __forceinline__ float lrelu(float v) { return v > 0.f ? v : 0.2f * v; }
__device__ __forceinline__ void red4(float* p, float4 v) {
    asm volatile("red.global.add.v4.f32 [%0], {%1,%2,%3,%4};"
                 :: "l"(p), "f"(v.x), "f"(v.y), "f"(v.z), "f"(v.w) : "memory");
}
__device__ __forceinline__ void atomicMaxF(float* addr, float v) {
    if (v >= 0.f) atomicMax((int*)addr, __float_as_int(v));
    else          atomicMin((unsigned int*)addr, __float_as_uint(v));
}

// ---------------- clear (vectorized) ----------------
__global__ void clear_kernel() {
    int i  = blockIdx.x * blockDim.x + threadIdx.x;
    int st = gridDim.x * blockDim.x;
    float4 z4 = make_float4(0.f, 0.f, 0.f, 0.f);
    float4* a1 = (float4*)g_acc1;
    float4* a2 = (float4*)g_acc2;
    for (int j = i; j < N_NODES * 16; j += st) a1[j] = z4;
    for (int j = i; j < N_NODES * 8;  j += st) a2[j] = z4;
    float2* d1 = (float2*)g_den1;
    for (int j = i; j < N_NODES; j += st) { d1[j] = make_float2(0.f, 0.f); g_den2[j] = 0.f; }
    if (i < 16)  g_easum[i] = 0.f;
    if (i < 128) g_bnsum[i] = 0.f;
    if (i < 64)  g_bnsum2[i] = 0.f;
    if (i < NG * 32) { g_psum[i] = 0.f; g_pmax[i] = __int_as_float(0xff800000); }
    if (i < NG)  g_cnt[i] = 0;
}

// ---------------- weight packing ----------------
__global__ void pack1_kernel(const float* __restrict__ Wl, const float* __restrict__ bl,
                             const float* __restrict__ Wr, const float* __restrict__ br,
                             const float* __restrict__ Ws, const float* __restrict__ bs) {
    int i = blockIdx.x * blockDim.x + threadIdx.x;
    if (i < 128 * 64) {
        int k = i >> 6, j = i & 63;
        g_Wcat1[k * 192 + j]       = Wl[i];
        g_Wcat1[k * 192 + 64 + j]  = Wr[i];
        g_Wcat1[k * 192 + 128 + j] = Ws[i];
    }
    if (i < 64) { g_bcat1[i] = bl[i]; g_bcat1[64 + i] = br[i]; g_bcat1[128 + i] = bs[i]; }
}

__global__ void pack2_kernel(const float* __restrict__ Wl, const float* __restrict__ bl,
                             const float* __restrict__ Wr, const float* __restrict__ br,
                             const float* __restrict__ Ws, const float* __restrict__ bs) {
    int i = blockIdx.x * blockDim.x + threadIdx.x;
    if (i < 64 * 32) {
        int k = i >> 5, j = i & 31;
        g_Wcat2[k * 96 + j]      = Wl[i];
        g_Wcat2[k * 96 + 32 + j] = Wr[i];
        g_Wcat2[k * 96 + 64 + j] = Ws[i];
    }
    if (i < 32) { g_bcat2[i] = bl[i]; g_bcat2[32 + i] = br[i]; g_bcat2[64 + i] = bs[i]; }
}

// ---------------- edge_attr column sums (float4 grid-stride) ----------------
__global__ void easum_kernel(const float4* __restrict__ ea4) {
    int tid = blockIdx.x * blockDim.x + threadIdx.x;
    int st  = gridDim.x * blockDim.x;
    int grp = tid & 3;
    float4 s = make_float4(0.f, 0.f, 0.f, 0.f);
    #pragma unroll 4
    for (int i = tid; i < N_EDGES * 4; i += st) {
        float4 v = ea4[i];
        s.x += v.x; s.y += v.y; s.z += v.z; s.w += v.w;
    }
    __shared__ float sm[16];
    if (threadIdx.x < 16) sm[threadIdx.x] = 0.f;
    __syncthreads();
    atomicAdd(&sm[grp * 4 + 0], s.x);
    atomicAdd(&sm[grp * 4 + 1], s.y);
    atomicAdd(&sm[grp * 4 + 2], s.z);
    atomicAdd(&sm[grp * 4 + 3], s.w);
    __syncthreads();
    if (threadIdx.x < 16) atomicAdd(&g_easum[threadIdx.x], sm[threadIdx.x]);
}

__global__ void eself_kernel(const float* __restrict__ We1, const float* __restrict__ We2) {
    __shared__ float m[16];
    int t = threadIdx.x;
    if (t < 16) m[t] = g_easum[t] * (1.0f / N_EDGES);
    __syncthreads();
    if (t < 64) {
        float s = 0.f;
        #pragma unroll
        for (int k = 0; k < 16; k++) s += m[k] * We1[k * 64 + t];
        g_eself1[t] = s;
    }
    if (t < 32) {
        float s = 0.f;
        #pragma unroll
        for (int k = 0; k < 16; k++) s += m[k] * We2[k * 32 + t];
        g_eself2[t] = s;
    }
}

// ---------------- tiled GEMM with fma.rn.f32x2 ----------------
template <int K, int NT>
__device__ __forceinline__ void gemm_body(const float* __restrict__ A,
                                          const float* __restrict__ W,
                                          const float* __restrict__ bias,
                                          float* __restrict__ C, int M) {
    __shared__ __align__(16) float As[16 * 68];
    __shared__ __align__(8)  float Bs[16 * 100];
    const int bm = blockIdx.x * 64;
    const int bn = blockIdx.y * 96;
    const int tid = threadIdx.x;
    const int tx = tid & 15, ty = tid >> 4;
    ull acc[4][3];
    #pragma unroll
    for (int i = 0; i < 4; i++)
        #pragma unroll
        for (int j = 0; j < 3; j++) acc[i][j] = 0ull;
    const int ar = tid >> 2, ac = (tid & 3) << 2;
    for (int k0 = 0; k0 < K; k0 += 16) {
        float4 av = make_float4(0.f, 0.f, 0.f, 0.f);
        int row = bm + ar;
        if (row < M) av = *(const float4*)&A[(size_t)row * K + k0 + ac];
        As[(ac + 0) * 68 + ar] = av.x;
        As[(ac + 1) * 68 + ar] = av.y;
        As[(ac + 2) * 68 + ar] = av.z;
        As[(ac + 3) * 68 + ar] = av.w;
        #pragma unroll
        for (int i = 0; i < 6; i++) {
            int idx = tid + (i << 8);
            int r = idx / 96, cc = idx - r * 96;
            Bs[r * 100 + cc] = W[(k0 + r) * NT + bn + cc];
        }
        __syncthreads();
        #pragma unroll
        for (int kk = 0; kk < 16; kk++) {
            float4 a = *(const float4*)&As[kk * 68 + (ty << 2)];
            ull b0 = *(const ull*)&Bs[kk * 100 + tx * 6];
            ull b1 = *(const ull*)&Bs[kk * 100 + tx * 6 + 2];
            ull b2 = *(const ull*)&Bs[kk * 100 + tx * 6 + 4];
            ull ap;
            ap = pk2(a.x, a.x);
            acc[0][0] = fma2(ap, b0, acc[0][0]); acc[0][1] = fma2(ap, b1, acc[0][1]); acc[0][2] = fma2(ap, b2, acc[0][2]);
            ap = pk2(a.y, a.y);
            acc[1][0] = fma2(ap, b0, acc[1][0]); acc[1][1] = fma2(ap, b1, acc[1][1]); acc[1][2] = fma2(ap, b2, acc[1][2]);
            ap = pk2(a.z, a.z);
            acc[2][0] = fma2(ap, b0, acc[2][0]); acc[2][1] = fma2(ap, b1, acc[2][1]); acc[2][2] = fma2(ap, b2, acc[2][2]);
            ap = pk2(a.w, a.w);
            acc[3][0] = fma2(ap, b0, acc[3][0]); acc[3][1] = fma2(ap, b1, acc[3][1]); acc[3][2] = fma2(ap, b2, acc[3][2]);
        }
        __syncthreads();
    }
    #pragma unroll
    for (int i = 0; i < 4; i++) {
        int r = bm + (ty << 2) + i;
        if (r < M) {
            #pragma unroll
            for (int j = 0; j < 3; j++) {
                float2 v = up2(acc[i][j]);
                int cc = bn + tx * 6 + 2 * j;
                C[(size_t)r * NT + cc]     = v.x + bias[cc];
                C[(size_t)r * NT + cc + 1] = v.y + bias[cc + 1];
            }
        }
    }
}

__global__ void gemm1_kernel(const float* __restrict__ A) {
    gemm_body<128, 192>(A, g_Wcat1, g_bcat1, g_big1, N_NODES);
}
__global__ void gemm2_kernel() {
    gemm_body<64, 96>(g_h, g_Wcat2, g_bcat2, g_big2, N_NODES);
}

// ---------------- edge kernel layer 1 (H=2,C=32; 2 edges/warp, We in REGISTERS) ----------------
__global__ void __launch_bounds__(256) edge1_kernel(const int* __restrict__ ei,
                                                    const float* __restrict__ ea,
                                                    const float* __restrict__ We,
                                                    const float* __restrict__ att) {
    const int lane = threadIdx.x & 31;
    const int sub  = lane & 15;          // 0..15 -> 4 channels each
    const int head = sub >> 3;           // 0 or 1
    const int half = lane >> 4;          // edge within pair
    // We columns 4*sub..4*sub+3, all 16 k-steps, in registers (32 ull)
    ull wA[16], wB[16];
    #pragma unroll
    for (int k = 0; k < 16; k++) {
        wA[k] = *(const ull*)&We[k * 64 + 4 * sub];
        wB[k] = *(const ull*)&We[k * 64 + 4 * sub + 2];
    }
    const float4 a4  = *(const float4*)&att[4 * sub];
    const float4 es4 = *(const float4*)&g_eself1[4 * sub];
    const int warp = threadIdx.x >> 5;
    const int nwarps = (gridDim.x * blockDim.x) >> 5;
    const int gw = blockIdx.x * (blockDim.x >> 5) + warp;
    const int npairs = (NE_TOT + 1) >> 1;
    for (int pair = gw; pair < npairs; pair += nwarps) {
        int e = pair * 2 + half;
        bool valid = e < NE_TOT;
        int s = 0, d = 0;
        bool isloop = false;
        if (valid) {
            if (e < N_EDGES) { s = ei[e]; d = ei[N_EDGES + e]; }
            else             { s = d = e - N_EDGES; isloop = true; }
        }
        float4 ev;
        if (valid && !isloop) {
            const float4* eap = (const float4*)(ea + (size_t)e * 16);  // uniform in 16-lane group
            float4 e0 = eap[0], e1 = eap[1], e2 = eap[2], e3 = eap[3];
            ull c0 = 0ull, c1 = 0ull;
            c0 = fma2(pk2(e0.x, e0.x), wA[0],  c0);  c1 = fma2(pk2(e0.x, e0.x), wB[0],  c1);
            c0 = fma2(pk2(e0.y, e0.y), wA[1],  c0);  c1 = fma2(pk2(e0.y, e0.y), wB[1],  c1);
            c0 = fma2(pk2(e0.z, e0.z), wA[2],  c0);  c1 = fma2(pk2(e0.z, e0.z), wB[2],  c1);
            c0 = fma2(pk2(e0.w, e0.w), wA[3],  c0);  c1 = fma2(pk2(e0.w, e0.w), wB[3],  c1);
            c0 = fma2(pk2(e1.x, e1.x), wA[4],  c0);  c1 = fma2(pk2(e1.x, e1.x), wB[4],  c1);
            c0 = fma2(pk2(e1.y, e1.y), wA[5],  c0);  c1 = fma2(pk2(e1.y, e1.y), wB[5],  c1);
            c0 = fma2(pk2(e1.z, e1.z), wA[6],  c0);  c1 = fma2(pk2(e1.z, e1.z), wB[6],  c1);
            c0 = fma2(pk2(e1.w, e1.w), wA[7],  c0);  c1 = fma2(pk2(e1.w, e1.w), wB[7],  c1);
            c0 = fma2(pk2(e2.x, e2.x), wA[8],  c0);  c1 = fma2(pk2(e2.x, e2.x), wB[8],  c1);
            c0 = fma2(pk2(e2.y, e2.y), wA[9],  c0);  c1 = fma2(pk2(e2.y, e2.y), wB[9],  c1);
            c0 = fma2(pk2(e2.z, e2.z), wA[10], c0);  c1 = fma2(pk2(e2.z, e2.z), wB[10], c1);
            c0 = fma2(pk2(e2.w, e2.w), wA[11], c0);  c1 = fma2(pk2(e2.w, e2.w), wB[11], c1);
            c0 = fma2(pk2(e3.x, e3.x), wA[12], c0);  c1 = fma2(pk2(e3.x, e3.x), wB[12], c1);
            c0 = fma2(pk2(e3.y, e3.y), wA[13], c0);  c1 = fma2(pk2(e3.y, e3.y), wB[13], c1);
            c0 = fma2(pk2(e3.z, e3.z), wA[14], c0);  c1 = fma2(pk2(e3.z, e3.z), wB[14], c1);
            c0 = fma2(pk2(e3.w, e3.w), wA[15], c0);  c1 = fma2(pk2(e3.w, e3.w), wB[15], c1);
            float2 lo = up2(c0), hi = up2(c1);
            ev = make_float4(lo.x, lo.y, hi.x, hi.y);
        } else {
            ev = es4;
        }
        float4 xl4 = *(const float4*)&g_big1[(size_t)s * 192 + 4 * sub];
        float4 xr4 = *(const float4*)&g_big1[(size_t)d * 192 + 64 + 4 * sub];
        float4 mm;
        mm.x = lrelu(xl4.x + xr4.x + ev.x);
        mm.y = lrelu(xl4.y + xr4.y + ev.y);
        mm.z = lrelu(xl4.z + xr4.z + ev.z);
        mm.w = lrelu(xl4.w + xr4.w + ev.w);
        float p = mm.x * a4.x + mm.y * a4.y + mm.z * a4.z + mm.w * a4.w;
        p += __shfl_xor_sync(0xffffffffu, p, 4);
        p += __shfl_xor_sync(0xffffffffu, p, 2);
        p += __shfl_xor_sync(0xffffffffu, p, 1);
        float w = __expf(p);
        if (valid) {
            if ((sub & 7) == 0) atomicAdd(&g_den1[d * 2 + head], w);
            float4 r = make_float4(w * xl4.x, w * xl4.y, w * xl4.z, w * xl4.w);
            red4(&g_acc1[(size_t)d * 64 + 4 * sub], r);
        }
    }
}

// ---------------- edge kernel layer 2 (H=1,C=32; 4 edges/warp, We in REGISTERS) ----------------
__global__ void __launch_bounds__(256) edge2_kernel(const int* __restrict__ ei,
                                                    const float* __restrict__ ea,
                                                    const float* __restrict__ We,
                                                    const float* __restrict__ att) {
    const int lane = threadIdx.x & 31;
    const int grp = lane >> 3, sub = lane & 7;    // sub: 4 channels each (32 ch)
    ull wA[16], wB[16];
    #pragma unroll
    for (int k = 0; k < 16; k++) {
        wA[k] = *(const ull*)&We[k * 32 + 4 * sub];
        wB[k] = *(const ull*)&We[k * 32 + 4 * sub + 2];
    }
    const float4 a4  = *(const float4*)&att[4 * sub];
    const float4 es4 = *(const float4*)&g_eself2[4 * sub];
    const int warp = threadIdx.x >> 5;
    const int nwarps = (gridDim.x * blockDim.x) >> 5;
    const int gw = blockIdx.x * (blockDim.x >> 5) + warp;
    const int nquads = (NE_TOT + 3) >> 2;
    for (int q = gw; q < nquads; q += nwarps) {
        int e = q * 4 + grp;
        bool valid = e < NE_TOT;
        int s = 0, d = 0;
        bool isloop = false;
        if (valid) {
            if (e < N_EDGES) { s = ei[e]; d = ei[N_EDGES + e]; }
            else             { s = d = e - N_EDGES; isloop = true; }
        }
        float4 ev;
        if (valid && !isloop) {
            const float4* eap = (const float4*)(ea + (size_t)e * 16);  // uniform in 8-lane group
            float4 e0 = eap[0], e1 = eap[1], e2 = eap[2], e3 = eap[3];
            ull c0 = 0ull, c1 = 0ull;
            c0 = fma2(pk2(e0.x, e0.x), wA[0],  c0);  c1 = fma2(pk2(e0.x, e0.x), wB[0],  c1);
            c0 = fma2(pk2(e0.y, e0.y), wA[1],  c0);  c1 = fma2(pk2(e0.y, e0.y), wB[1],  c1);
            c0 = fma2(pk2(e0.z, e0.z), wA[2],  c0);  c1 = fma2(pk2(e0.z, e0.z), wB[2],  c1);
            c0 = fma2(pk2(e0.w, e0.w), wA[3],  c0);  c1 = fma2(pk2(e0.w, e0.w), wB[3],  c1);
            c0 = fma2(pk2(e1.x, e1.x), wA[4],  c0);  c1 = fma2(pk2(e1.x, e1.x), wB[4],  c1);
            c0 = fma2(pk2(e1.y, e1.y), wA[5],  c0);  c1 = fma2(pk2(e1.y, e1.y), wB[5],  c1);
            c0 = fma2(pk2(e1.z, e1.z), wA[6],  c0);  c1 = fma2(pk2(e1.z, e1.z), wB[6],  c1);
            c0 = fma2(pk2(e1.w, e1.w), wA[7],  c0);  c1 = fma2(pk2(e1.w, e1.w), wB[7],  c1);
            c0 = fma2(pk2(e2.x, e2.x), wA[8],  c0);  c1 = fma2(pk2(e2.x, e2.x), wB[8],  c1);
            c0 = fma2(pk2(e2.y, e2.y), wA[9],  c0);  c1 = fma2(pk2(e2.y, e2.y), wB[9],  c1);
            c0 = fma2(pk2(e2.z, e2.z), wA[10], c0);  c1 = fma2(pk2(e2.z, e2.z), wB[10], c1);
            c0 = fma2(pk2(e2.w, e2.w), wA[11], c0);  c1 = fma2(pk2(e2.w, e2.w), wB[11], c1);
            c0 = fma2(pk2(e3.x, e3.x), wA[12], c0);  c1 = fma2(pk2(e3.x, e3.x), wB[12], c1);
            c0 = fma2(pk2(e3.y, e3.y), wA[13], c0);  c1 = fma2(pk2(e3.y, e3.y), wB[13], c1);
            c0 = fma2(pk2(e3.z, e3.z), wA[14], c0);  c1 = fma2(pk2(e3.z, e3.z), wB[14], c1);
            c0 = fma2(pk2(e3.w, e3.w), wA[15], c0);  c1 = fma2(pk2(e3.w, e3.w), wB[15], c1);
            float2 lo = up2(c0), hi = up2(c1);
            ev = make_float4(lo.x, lo.y, hi.x, hi.y);
        } else {
            ev = es4;
        }
        float4 xl4 = *(const float4*)&g_big2[(size_t)s * 96 + 4 * sub];
        float4 xr4 = *(const float4*)&g_big2[(size_t)d * 96 + 32 + 4 * sub];
        float4 mm;
        mm.x = lrelu(xl4.x + xr4.x + ev.x);
        mm.y = lrelu(xl4.y + xr4.y + ev.y);
        mm.z = lrelu(xl4.z + xr4.z + ev.z);
        mm.w = lrelu(xl4.w + xr4.w + ev.w);
        float p = mm.x * a4.x + mm.y * a4.y + mm.z * a4.z + mm.w * a4.w;
        p += __shfl_xor_sync(0xffffffffu, p, 4);
        p += __shfl_xor_sync(0xffffffffu, p, 2);
        p += __shfl_xor_sync(0xffffffffu, p, 1);
        float w = __expf(p);
        if (valid) {
            if (sub == 0) atomicAdd(&g_den2[d], w);
            float4 r = make_float4(w * xl4.x, w * xl4.y, w * xl4.z, w * xl4.w);
            red4(&g_acc2[(size_t)d * 32 + 4 * sub], r);
        }
    }
}

// ---------------- finalize conv1: out1 = acc/den + bias, accumulate BN stats ----------------
__global__ void final1_kernel(const float* __restrict__ bias) {
    int tid = threadIdx.x;
    int c = tid & 63;
    int h = c >> 5;
    float s = 0.f, q = 0.f;
    for (int n = blockIdx.x * 4 + (tid >> 6); n < N_NODES; n += gridDim.x * 4) {
        float v = g_acc1[(size_t)n * 64 + c] / (g_den1[n * 2 + h] + 1e-16f) + bias[c];
        g_out1[(size_t)n * 64 + c] = v;
        s += v; q += v * v;
    }
    __shared__ float ss[256], sq[256];
    ss[tid] = s; sq[tid] = q;
    __syncthreads();
    if (tid < 64) {
        s = ss[tid] + ss[tid + 64] + ss[tid + 128] + ss[tid + 192];
        q = sq[tid] + sq[tid + 64] + sq[tid + 128] + sq[tid + 192];
        atomicAdd(&g_bnsum[tid], s);
        atomicAdd(&g_bnsum[64 + tid], q);
    }
}

__global__ void bnfin1_kernel(const float* __restrict__ g, const float* __restrict__ b) {
    int c = threadIdx.x;
    if (c < 64) {
        float mean = g_bnsum[c] * (1.0f / N_NODES);
        float var  = g_bnsum[64 + c] * (1.0f / N_NODES) - mean * mean;
        float sc   = g[c] * rsqrtf(var + 1e-5f);
        g_bnsc1[c] = sc;
        g_bnsc1[64 + c] = b[c] - mean * sc;
    }
}

__global__ void elu1_kernel() {
    int i = blockIdx.x * blockDim.x + threadIdx.x;
    int st = gridDim.x * blockDim.x;
    for (; i < N_NODES * 64; i += st) {
        int n = i >> 6, c = i & 63;
        float v = g_out1[i] * g_bnsc1[c] + g_bnsc1[64 + c] + g_big1[(size_t)n * 192 + 128 + c];
        g_h[i] = v > 0.f ? v : expm1f(v);
    }
}

// ---------------- finalize conv2 ----------------
__global__ void final2_kernel(const float* __restrict__ bias) {
    int tid = threadIdx.x;
    int c = tid & 31;
    float s = 0.f, q = 0.f;
    for (int n = blockIdx.x * 8 + (tid >> 5); n < N_NODES; n += gridDim.x * 8) {
        float v = g_acc2[(size_t)n * 32 + c] / (g_den2[n] + 1e-16f) + bias[c];
        g_out2[(size_t)n * 32 + c] = v;
        s += v; q += v * v;
    }
    __shared__ float ss[256], sq[256];
    ss[tid] = s; sq[tid] = q;
    __syncthreads();
    if (tid < 32) {
        s = 0.f; q = 0.f;
        #pragma unroll
        for (int gg = 0; gg < 8; gg++) { s += ss[tid + gg * 32]; q += sq[tid + gg * 32]; }
        atomicAdd(&g_bnsum2[tid], s);
        atomicAdd(&g_bnsum2[32 + tid], q);
    }
}

__global__ void bnfin2_kernel(const float* __restrict__ g, const float* __restrict__ b) {
    int c = threadIdx.x;
    if (c < 32) {
        float mean = g_bnsum2[c] * (1.0f / N_NODES);
        float var  = g_bnsum2[32 + c] * (1.0f / N_NODES) - mean * mean;
        float sc   = g[c] * rsqrtf(var + 1e-5f);
        g_bnsc2[c] = sc;
        g_bnsc2[32 + c] = b[c] - mean * sc;
    }
}

// ---------------- elu2 + graph pooling (batch sorted) ----------------
__global__ void elu2pool_kernel(const int* __restrict__ batch) {
    __shared__ float ssum[NG * 32];
    __shared__ float smax[NG * 32];
    __shared__ int scnt[NG];
    int tid = threadIdx.x;
    for (int i = tid; i < NG * 32; i += blockDim.x) { ssum[i] = 0.f; smax[i] = __int_as_float(0xff800000); }
    if (tid < NG) scnt[tid] = 0;
    __syncthreads();
    int c = tid & 31;
    for (int n = blockIdx.x * 8 + (tid >> 5); n < N_NODES; n += gridDim.x * 8) {
        float v = g_out2[(size_t)n * 32 + c] * g_bnsc2[c] + g_bnsc2[32 + c] + g_big2[(size_t)n * 96 + 64 + c];
        v = v > 0.f ? v : expm1f(v);
        int g = batch[n];
        atomicAdd(&ssum[g * 32 + c], v);
        if (v >= 0.f) atomicMax((int*)&smax[g * 32 + c], __float_as_int(v));
        else          atomicMin((unsigned int*)&smax[g * 32 + c], __float_as_uint(v));
        if (c == 0) atomicAdd(&scnt[g], 1);
    }
    __syncthreads();
    for (int i = tid; i < NG * 32; i += blockDim.x) {
        atomicAdd(&g_psum[i], ssum[i]);
        atomicMaxF(&g_pmax[i], smax[i]);
    }
    if (tid < NG) atomicAdd(&g_cnt[tid], scnt[tid]);
}

__global__ void finalout_kernel(float* __restrict__ out) {
    int tid = threadIdx.x;
    if (tid < NG * 64) {
        int g = tid >> 6, j = tid & 63;
        int cnt = g_cnt[g];
        float r;
        if (j < 32) r = g_psum[g * 32 + j] / fmaxf((float)cnt, 1.0f);
        else        r = (cnt > 0) ? g_pmax[g * 32 + (j - 32)] : 0.0f;
        out[tid] = r;
    }
}

// ---------------- launch ----------------
extern "C" void kernel_launch(void* const* d_in, const int* in_sizes, int n_in,
                              void* d_out, int out_size) {
    const float* x     = (const float*)d_in[0];
    const int*   ei    = (const int*)d_in[1];
    const float* ea    = (const float*)d_in[2];
    const int*   batch = (const int*)d_in[3];
    const float* s1W = (const float*)d_in[4];
    const float* s1b = (const float*)d_in[5];
    const float* c1Wl = (const float*)d_in[6];
    const float* c1bl = (const float*)d_in[7];
    const float* c1Wr = (const float*)d_in[8];
    const float* c1br = (const float*)d_in[9];
    const float* c1We = (const float*)d_in[10];
    const float* c1att = (const float*)d_in[11];
    const float* c1bias = (const float*)d_in[12];
    const float* bn1g = (const float*)d_in[13];
    const float* bn1b = (const float*)d_in[14];
    const float* s2W = (const float*)d_in[15];
    const float* s2b = (const float*)d_in[16];
    const float* c2Wl = (const float*)d_in[17];
    const float* c2bl = (const float*)d_in[18];
    const float* c2Wr = (const float*)d_in[19];
    const float* c2br = (const float*)d_in[20];
    const float* c2We = (const float*)d_in[21];
    const float* c2att = (const float*)d_in[22];
    const float* c2bias = (const float*)d_in[23];
    const float* bn2g = (const float*)d_in[24];
    const float* bn2b = (const float*)d_in[25];
    float* out = (float*)d_out;

    clear_kernel<<<2048, 256>>>();
    pack1_kernel<<<32, 256>>>(c1Wl, c1bl, c1Wr, c1br, s1W, s1b);
    pack2_kernel<<<8, 256>>>(c2Wl, c2bl, c2Wr, c2br, s2W, s2b);
    easum_kernel<<<1024, 256>>>((const float4*)ea);
    eself_kernel<<<1, 64>>>(c1We, c2We);

    gemm1_kernel<<<dim3((N_NODES + 63) / 64, 2), 256>>>(x);
    edge1_kernel<<<2048, 256>>>(ei, ea, c1We, c1att);
    final1_kernel<<<512, 256>>>(c1bias);
    bnfin1_kernel<<<1, 64>>>(bn1g, bn1b);
    elu1_kernel<<<2048, 256>>>();

    gemm2_kernel<<<dim3((N_NODES + 63) / 64, 1), 256>>>();
    edge2_kernel<<<1536, 256>>>(ei, ea, c2We, c2att);
    final2_kernel<<<512, 256>>>(c2bias);
    bnfin2_kernel<<<1, 32>>>(bn2g, bn2b);
    elu2pool_kernel<<<256, 256>>>(batch);
    finalout_kernel<<<1, 1024>>>(out);
}

// round 7
// speedup vs baseline: 1.1758x; 1.0066x over previous
#include <cuda_runtime.h>
#include <cstdint>

#define N_NODES 50000
#define N_EDGES 800000
#define NE_TOT  (N_EDGES + N_NODES)   // 850000, self loops appended
#define NG 16

typedef unsigned long long ull;

// ---------------- scratch ----------------
__device__ __align__(16) float g_big1[N_NODES * 192];   // 0-63 xl1 | 64-127 xr1 | 128-191 hproj1
__device__ __align__(16) float g_big2[N_NODES * 96];    // 0-31 xl2 | 32-63 xr2 | 64-95 hproj2
__device__ __align__(16) float g_acc1[N_NODES * 64];
__device__ __align__(16) float g_den1[N_NODES * 2];
__device__ __align__(16) float g_h[N_NODES * 64];
__device__ __align__(16) float g_acc2[N_NODES * 32];
__device__ __align__(16) float g_den2[N_NODES];
__device__ __align__(16) float g_Wcat1[128 * 192];
__device__ __align__(16) float g_bcat1[192];
__device__ __align__(16) float g_Wcat2[64 * 96];
__device__ __align__(16) float g_bcat2[96];
__device__ __align__(16) float g_easum[16];
__device__ __align__(16) float g_eself1[64];
__device__ __align__(16) float g_eself2[32];
__device__ __align__(16) float g_bnsum[128];     // [0:64) sum, [64:128) sumsq
__device__ __align__(16) float g_bnsc1[128];     // [0:64) scale, [64:128) shift
__device__ __align__(16) float g_bnsum2[64];
__device__ __align__(16) float g_bnsc2[64];
__device__ __align__(16) float g_psum[NG * 32];
__device__ __align__(16) float g_pmax[NG * 32];
__device__ int g_cnt[NG];

// ---------------- helpers ----------------
__device__ __forceinline__ ull pk2(float a, float b) {
    ull r; asm("mov.b64 %0,{%1,%2};" : "=l"(r) : "f"(a), "f"(b)); return r;
}
__device__ __forceinline__ float2 up2(ull v) {
    float2 r; asm("mov.b64 {%0,%1},%2;" : "=f"(r.x), "=f"(r.y) : "l"(v)); return r;
}
__device__ __forceinline__ ull fma2(ull a, ull b, ull c) {
    ull d; asm("fma.rn.f32x2 %0,%1,%2,%3;" : "=l"(d) : "l"(a), "l"(b), "l"(c)); return d;
}
__device__ __forceinline__ ull add2(ull a, ull b) {
    ull d; asm("add.rn.f32x2 %0,%1,%2;" : "=l"(d) : "l"(a), "l"(b)); return d;
}
__device__ __forceinline__ float lrelu(float v) { return v > 0.f ? v : 0.2f * v; }
__device__ __forceinline__ void red2(float* p, float2 v) {
    asm volatile("red.global.add.v2.f32 [%0], {%1,%2};"
                 :: "l"(p), "f"(v.x), "f"(v.y) : "memory");
}
__device__ __forceinline__ void atomicMaxF(float* addr, float v) {
    if (v >= 0.f) atomicMax((int*)addr, __float_as_int(v));
    else          atomicMin((unsigned int*)addr, __float_as_uint(v));
}

// ---------------- clear (vectorized) ----------------
__global__ void clear_kernel() {
    int i  = blockIdx.x * blockDim.x + threadIdx.x;
    int st = gridDim.x * blockDim.x;
    float4 z4 = make_float4(0.f, 0.f, 0.f, 0.f);
    float4* a1 = (float4*)g_acc1;
    float4* a2 = (float4*)g_acc2;
    for (int j = i; j < N_NODES * 16; j += st) a1[j] = z4;
    for (int j = i; j < N_NODES * 8;  j += st) a2[j] = z4;
    float2* d1 = (float2*)g_den1;
    for (int j = i; j < N_NODES; j += st) { d1[j] = make_float2(0.f, 0.f); g_den2[j] = 0.f; }
    if (i < 16)  g_easum[i] = 0.f;
    if (i < 128) g_bnsum[i] = 0.f;
    if (i < 64)  g_bnsum2[i] = 0.f;
    if (i < NG * 32) { g_psum[i] = 0.f; g_pmax[i] = __int_as_float(0xff800000); }
    if (i < NG)  g_cnt[i] = 0;
}

// ---------------- weight packing ----------------
__global__ void pack1_kernel(const float* __restrict__ Wl, const float* __restrict__ bl,
                             const float* __restrict__ Wr, const float* __restrict__ br,
                             const float* __restrict__ Ws, const float* __restrict__ bs) {
    int i = blockIdx.x * blockDim.x + threadIdx.x;
    if (i < 128 * 64) {
        int k = i >> 6, j = i & 63;
        g_Wcat1[k * 192 + j]       = Wl[i];
        g_Wcat1[k * 192 + 64 + j]  = Wr[i];
        g_Wcat1[k * 192 + 128 + j] = Ws[i];
    }
    if (i < 64) { g_bcat1[i] = bl[i]; g_bcat1[64 + i] = br[i]; g_bcat1[128 + i] = bs[i]; }
}

__global__ void pack2_kernel(const float* __restrict__ Wl, const float* __restrict__ bl,
                             const float* __restrict__ Wr, const float* __restrict__ br,
                             const float* __restrict__ Ws, const float* __restrict__ bs) {
    int i = blockIdx.x * blockDim.x + threadIdx.x;
    if (i < 64 * 32) {
        int k = i >> 5, j = i & 31;
        g_Wcat2[k * 96 + j]      = Wl[i];
        g_Wcat2[k * 96 + 32 + j] = Wr[i];
        g_Wcat2[k * 96 + 64 + j] = Ws[i];
    }
    if (i < 32) { g_bcat2[i] = bl[i]; g_bcat2[32 + i] = br[i]; g_bcat2[64 + i] = bs[i]; }
}

// ---------------- edge_attr column sums (float4 grid-stride; proven) ----------------
__global__ void easum_kernel(const float4* __restrict__ ea4) {
    int tid = blockIdx.x * blockDim.x + threadIdx.x;
    int st  = gridDim.x * blockDim.x;
    int grp = tid & 3;
    float4 s = make_float4(0.f, 0.f, 0.f, 0.f);
    #pragma unroll 4
    for (int i = tid; i < N_EDGES * 4; i += st) {
        float4 v = ea4[i];
        s.x += v.x; s.y += v.y; s.z += v.z; s.w += v.w;
    }
    __shared__ float sm[16];
    if (threadIdx.x < 16) sm[threadIdx.x] = 0.f;
    __syncthreads();
    atomicAdd(&sm[grp * 4 + 0], s.x);
    atomicAdd(&sm[grp * 4 + 1], s.y);
    atomicAdd(&sm[grp * 4 + 2], s.z);
    atomicAdd(&sm[grp * 4 + 3], s.w);
    __syncthreads();
    if (threadIdx.x < 16) atomicAdd(&g_easum[threadIdx.x], sm[threadIdx.x]);
}

__global__ void eself_kernel(const float* __restrict__ We1, const float* __restrict__ We2) {
    __shared__ float m[16];
    int t = threadIdx.x;
    if (t < 16) m[t] = g_easum[t] * (1.0f / N_EDGES);
    __syncthreads();
    if (t < 64) {
        float s = 0.f;
        #pragma unroll
        for (int k = 0; k < 16; k++) s += m[k] * We1[k * 64 + t];
        g_eself1[t] = s;
    }
    if (t < 32) {
        float s = 0.f;
        #pragma unroll
        for (int k = 0; k < 16; k++) s += m[k] * We2[k * 32 + t];
        g_eself2[t] = s;
    }
}

// ---------------- tiled GEMM with fma.rn.f32x2 (proven) ----------------
template <int K, int NT>
__device__ __forceinline__ void gemm_body(const float* __restrict__ A,
                                          const float* __restrict__ W,
                                          const float* __restrict__ bias,
                                          float* __restrict__ C, int M) {
    __shared__ __align__(16) float As[16 * 68];
    __shared__ __align__(8)  float Bs[16 * 100];
    const int bm = blockIdx.x * 64;
    const int bn = blockIdx.y * 96;
    const int tid = threadIdx.x;
    const int tx = tid & 15, ty = tid >> 4;
    ull acc[4][3];
    #pragma unroll
    for (int i = 0; i < 4; i++)
        #pragma unroll
        for (int j = 0; j < 3; j++) acc[i][j] = 0ull;
    const int ar = tid >> 2, ac = (tid & 3) << 2;
    for (int k0 = 0; k0 < K; k0 += 16) {
        float4 av = make_float4(0.f, 0.f, 0.f, 0.f);
        int row = bm + ar;
        if (row < M) av = *(const float4*)&A[(size_t)row * K + k0 + ac];
        As[(ac + 0) * 68 + ar] = av.x;
        As[(ac + 1) * 68 + ar] = av.y;
        As[(ac + 2) * 68 + ar] = av.z;
        As[(ac + 3) * 68 + ar] = av.w;
        #pragma unroll
        for (int i = 0; i < 6; i++) {
            int idx = tid + (i << 8);
            int r = idx / 96, cc = idx - r * 96;
            Bs[r * 100 + cc] = W[(k0 + r) * NT + bn + cc];
        }
        __syncthreads();
        #pragma unroll
        for (int kk = 0; kk < 16; kk++) {
            float4 a = *(const float4*)&As[kk * 68 + (ty << 2)];
            ull b0 = *(const ull*)&Bs[kk * 100 + tx * 6];
            ull b1 = *(const ull*)&Bs[kk * 100 + tx * 6 + 2];
            ull b2 = *(const ull*)&Bs[kk * 100 + tx * 6 + 4];
            ull ap;
            ap = pk2(a.x, a.x);
            acc[0][0] = fma2(ap, b0, acc[0][0]); acc[0][1] = fma2(ap, b1, acc[0][1]); acc[0][2] = fma2(ap, b2, acc[0][2]);
            ap = pk2(a.y, a.y);
            acc[1][0] = fma2(ap, b0, acc[1][0]); acc[1][1] = fma2(ap, b1, acc[1][1]); acc[1][2] = fma2(ap, b2, acc[1][2]);
            ap = pk2(a.z, a.z);
            acc[2][0] = fma2(ap, b0, acc[2][0]); acc[2][1] = fma2(ap, b1, acc[2][1]); acc[2][2] = fma2(ap, b2, acc[2][2]);
            ap = pk2(a.w, a.w);
            acc[3][0] = fma2(ap, b0, acc[3][0]); acc[3][1] = fma2(ap, b1, acc[3][1]); acc[3][2] = fma2(ap, b2, acc[3][2]);
        }
        __syncthreads();
    }
    #pragma unroll
    for (int i = 0; i < 4; i++) {
        int r = bm + (ty << 2) + i;
        if (r < M) {
            #pragma unroll
            for (int j = 0; j < 3; j++) {
                float2 v = up2(acc[i][j]);
                int cc = bn + tx * 6 + 2 * j;
                C[(size_t)r * NT + cc]     = v.x + bias[cc];
                C[(size_t)r * NT + cc + 1] = v.y + bias[cc + 1];
            }
        }
    }
}

__global__ void gemm1_kernel(const float* __restrict__ A) {
    gemm_body<128, 192>(A, g_Wcat1, g_bcat1, g_big1, N_NODES);
}
__global__ void gemm2_kernel() {
    gemm_body<64, 96>(g_h, g_Wcat2, g_bcat2, g_big2, N_NODES);
}

// ---------------- edge kernel layer 1 (H=2,C=32; 1 warp per edge, 2 ch/lane) ----------------
__global__ void __launch_bounds__(256) edge1_kernel(const int* __restrict__ ei,
                                                    const float* __restrict__ ea,
                                                    const float* __restrict__ We,
                                                    const float* __restrict__ att) {
    const int lane = threadIdx.x & 31;
    const int head = lane >> 4;
    // lane owns channels 2*lane, 2*lane+1 -> 16 ull of We (32 regs)
    ull wreg[16];
    #pragma unroll
    for (int k = 0; k < 16; k++) wreg[k] = *(const ull*)&We[k * 64 + 2 * lane];
    const float2 a2  = *(const float2*)&att[2 * lane];
    const float2 es2 = *(const float2*)&g_eself1[2 * lane];
    const int gw = (blockIdx.x * blockDim.x + threadIdx.x) >> 5;
    const int nw = (gridDim.x * blockDim.x) >> 5;
    for (int e = gw; e < NE_TOT; e += nw) {
        int s, d;
        bool isloop = e >= N_EDGES;
        if (!isloop) { s = ei[e]; d = ei[N_EDGES + e]; }
        else         { s = d = e - N_EDGES; }
        float2 ev;
        if (!isloop) {
            const float4* eap = (const float4*)(ea + (size_t)e * 16);  // warp-uniform address
            float4 e0 = eap[0], e1 = eap[1], e2 = eap[2], e3 = eap[3];
            ull c0 = 0ull, c1 = 0ull;
            c0 = fma2(pk2(e0.x, e0.x), wreg[0],  c0);  c1 = fma2(pk2(e0.y, e0.y), wreg[1],  c1);
            c0 = fma2(pk2(e0.z, e0.z), wreg[2],  c0);  c1 = fma2(pk2(e0.w, e0.w), wreg[3],  c1);
            c0 = fma2(pk2(e1.x, e1.x), wreg[4],  c0);  c1 = fma2(pk2(e1.y, e1.y), wreg[5],  c1);
            c0 = fma2(pk2(e1.z, e1.z), wreg[6],  c0);  c1 = fma2(pk2(e1.w, e1.w), wreg[7],  c1);
            c0 = fma2(pk2(e2.x, e2.x), wreg[8],  c0);  c1 = fma2(pk2(e2.y, e2.y), wreg[9],  c1);
            c0 = fma2(pk2(e2.z, e2.z), wreg[10], c0);  c1 = fma2(pk2(e2.w, e2.w), wreg[11], c1);
            c0 = fma2(pk2(e3.x, e3.x), wreg[12], c0);  c1 = fma2(pk2(e3.y, e3.y), wreg[13], c1);
            c0 = fma2(pk2(e3.z, e3.z), wreg[14], c0);  c1 = fma2(pk2(e3.w, e3.w), wreg[15], c1);
            ev = up2(add2(c0, c1));
        } else {
            ev = es2;
        }
        float2 xl = *(const float2*)&g_big1[(size_t)s * 192 + 2 * lane];
        float2 xr = *(const float2*)&g_big1[(size_t)d * 192 + 64 + 2 * lane];
        float ux = lrelu(xl.x + xr.x + ev.x);
        float uy = lrelu(xl.y + xr.y + ev.y);
        float p = ux * a2.x + uy * a2.y;
        p += __shfl_xor_sync(0xffffffffu, p, 8);   // reduce within 16-lane head group
        p += __shfl_xor_sync(0xffffffffu, p, 4);
        p += __shfl_xor_sync(0xffffffffu, p, 2);
        p += __shfl_xor_sync(0xffffffffu, p, 1);
        float w = __expf(p);
        if ((lane & 15) == 0) atomicAdd(&g_den1[d * 2 + head], w);
        red2(&g_acc1[(size_t)d * 64 + 2 * lane], make_float2(w * xl.x, w * xl.y));
    }
}

// ---------------- edge kernel layer 2 (H=1,C=32; 2 edges/warp, 2 ch/lane) ----------------
__global__ void __launch_bounds__(256) edge2_kernel(const int* __restrict__ ei,
                                                    const float* __restrict__ ea,
                                                    const float* __restrict__ We,
                                                    const float* __restrict__ att) {
    const int lane = threadIdx.x & 31;
    const int half = lane >> 4;          // edge within pair
    const int sub  = lane & 15;          // owns channels 2*sub, 2*sub+1
    ull wreg[16];
    #pragma unroll
    for (int k = 0; k < 16; k++) wreg[k] = *(const ull*)&We[k * 32 + 2 * sub];
    const float2 a2  = *(const float2*)&att[2 * sub];
    const float2 es2 = *(const float2*)&g_eself2[2 * sub];
    const int gw = (blockIdx.x * blockDim.x + threadIdx.x) >> 5;
    const int nw = (gridDim.x * blockDim.x) >> 5;
    const int npairs = (NE_TOT + 1) >> 1;
    for (int pair = gw; pair < npairs; pair += nw) {
        int e = pair * 2 + half;
        bool valid = e < NE_TOT;
        int s = 0, d = 0;
        bool isloop = false;
        if (valid) {
            if (e < N_EDGES) { s = ei[e]; d = ei[N_EDGES + e]; }
            else             { s = d = e - N_EDGES; isloop = true; }
        }
        float2 ev;
        if (valid && !isloop) {
            const float4* eap = (const float4*)(ea + (size_t)e * 16);  // uniform in 16-lane group
            float4 e0 = eap[0], e1 = eap[1], e2 = eap[2], e3 = eap[3];
            ull c0 = 0ull, c1 = 0ull;
            c0 = fma2(pk2(e0.x, e0.x), wreg[0],  c0);  c1 = fma2(pk2(e0.y, e0.y), wreg[1],  c1);
            c0 = fma2(pk2(e0.z, e0.z), wreg[2],  c0);  c1 = fma2(pk2(e0.w, e0.w), wreg[3],  c1);
            c0 = fma2(pk2(e1.x, e1.x), wreg[4],  c0);  c1 = fma2(pk2(e1.y, e1.y), wreg[5],  c1);
            c0 = fma2(pk2(e1.z, e1.z), wreg[6],  c0);  c1 = fma2(pk2(e1.w, e1.w), wreg[7],  c1);
            c0 = fma2(pk2(e2.x, e2.x), wreg[8],  c0);  c1 = fma2(pk2(e2.y, e2.y), wreg[9],  c1);
            c0 = fma2(pk2(e2.z, e2.z), wreg[10], c0);  c1 = fma2(pk2(e2.w, e2.w), wreg[11], c1);
            c0 = fma2(pk2(e3.x, e3.x), wreg[12], c0);  c1 = fma2(pk2(e3.y, e3.y), wreg[13], c1);
            c0 = fma2(pk2(e3.z, e3.z), wreg[14], c0);  c1 = fma2(pk2(e3.w, e3.w), wreg[15], c1);
            ev = up2(add2(c0, c1));
        } else {
            ev = es2;
        }
        float2 xl = make_float2(0.f, 0.f), xr = make_float2(0.f, 0.f);
        if (valid) {
            xl = *(const float2*)&g_big2[(size_t)s * 96 + 2 * sub];
            xr = *(const float2*)&g_big2[(size_t)d * 96 + 32 + 2 * sub];
        }
        float ux = lrelu(xl.x + xr.x + ev.x);
        float uy = lrelu(xl.y + xr.y + ev.y);
        float p = ux * a2.x + uy * a2.y;
        p += __shfl_xor_sync(0xffffffffu, p, 8);
        p += __shfl_xor_sync(0xffffffffu, p, 4);
        p += __shfl_xor_sync(0xffffffffu, p, 2);
        p += __shfl_xor_sync(0xffffffffu, p, 1);
        float w = __expf(p);
        if (valid) {
            if (sub == 0) atomicAdd(&g_den2[d], w);
            red2(&g_acc2[(size_t)d * 32 + 2 * sub], make_float2(w * xl.x, w * xl.y));
        }
    }
}

// ---------------- BN stats layer 1 (no out1 write; recompute in elu1) ----------------
__global__ void final1_kernel(const float* __restrict__ bias) {
    int tid = threadIdx.x;
    int c = tid & 63;
    int h = c >> 5;
    float bb = bias[c];
    float s = 0.f, q = 0.f;
    for (int n = blockIdx.x * 4 + (tid >> 6); n < N_NODES; n += gridDim.x * 4) {
        float v = g_acc1[(size_t)n * 64 + c] / (g_den1[n * 2 + h] + 1e-16f) + bb;
        s += v; q += v * v;
    }
    __shared__ float ss[256], sq[256];
    ss[tid] = s; sq[tid] = q;
    __syncthreads();
    if (tid < 64) {
        s = ss[tid] + ss[tid + 64] + ss[tid + 128] + ss[tid + 192];
        q = sq[tid] + sq[tid + 64] + sq[tid + 128] + sq[tid + 192];
        atomicAdd(&g_bnsum[tid], s);
        atomicAdd(&g_bnsum[64 + tid], q);
    }
}

__global__ void bnfin1_kernel(const float* __restrict__ g, const float* __restrict__ b) {
    int c = threadIdx.x;
    if (c < 64) {
        float mean = g_bnsum[c] * (1.0f / N_NODES);
        float var  = g_bnsum[64 + c] * (1.0f / N_NODES) - mean * mean;
        float sc   = g[c] * rsqrtf(var + 1e-5f);
        g_bnsc1[c] = sc;
        g_bnsc1[64 + c] = b[c] - mean * sc;
    }
}

__global__ void elu1_kernel(const float* __restrict__ bias) {
    int i = blockIdx.x * blockDim.x + threadIdx.x;
    int st = gridDim.x * blockDim.x;
    for (; i < N_NODES * 64; i += st) {
        int n = i >> 6, c = i & 63;
        float v = g_acc1[i] / (g_den1[n * 2 + (c >> 5)] + 1e-16f) + bias[c];
        float t = v * g_bnsc1[c] + g_bnsc1[64 + c] + g_big1[(size_t)n * 192 + 128 + c];
        g_h[i] = t > 0.f ? t : expm1f(t);
    }
}

// ---------------- BN stats layer 2 ----------------
__global__ void final2_kernel(const float* __restrict__ bias) {
    int tid = threadIdx.x;
    int c = tid & 31;
    float bb = bias[c];
    float s = 0.f, q = 0.f;
    for (int n = blockIdx.x * 8 + (tid >> 5); n < N_NODES; n += gridDim.x * 8) {
        float v = g_acc2[(size_t)n * 32 + c] / (g_den2[n] + 1e-16f) + bb;
        s += v; q += v * v;
    }
    __shared__ float ss[256], sq[256];
    ss[tid] = s; sq[tid] = q;
    __syncthreads();
    if (tid < 32) {
        s = 0.f; q = 0.f;
        #pragma unroll
        for (int gg = 0; gg < 8; gg++) { s += ss[tid + gg * 32]; q += sq[tid + gg * 32]; }
        atomicAdd(&g_bnsum2[tid], s);
        atomicAdd(&g_bnsum2[32 + tid], q);
    }
}

__global__ void bnfin2_kernel(const float* __restrict__ g, const float* __restrict__ b) {
    int c = threadIdx.x;
    if (c < 32) {
        float mean = g_bnsum2[c] * (1.0f / N_NODES);
        float var  = g_bnsum2[32 + c] * (1.0f / N_NODES) - mean * mean;
        float sc   = g[c] * rsqrtf(var + 1e-5f);
        g_bnsc2[c] = sc;
        g_bnsc2[32 + c] = b[c] - mean * sc;
    }
}

// ---------------- elu2 + graph pooling (batch sorted) ----------------
__global__ void elu2pool_kernel(const int* __restrict__ batch, const float* __restrict__ bias) {
    __shared__ float ssum[NG * 32];
    __shared__ float smax[NG * 32];
    __shared__ int scnt[NG];
    int tid = threadIdx.x;
    for (int i = tid; i < NG * 32; i += blockDim.x) { ssum[i] = 0.f; smax[i] = __int_as_float(0xff800000); }
    if (tid < NG) scnt[tid] = 0;
    __syncthreads();
    int c = tid & 31;
    float bb = bias[c];
    for (int n = blockIdx.x * 8 + (tid >> 5); n < N_NODES; n += gridDim.x * 8) {
        float v = g_acc2[(size_t)n * 32 + c] / (g_den2[n] + 1e-16f) + bb;
        v = v * g_bnsc2[c] + g_bnsc2[32 + c] + g_big2[(size_t)n * 96 + 64 + c];
        v = v > 0.f ? v : expm1f(v);
        int g = batch[n];
        atomicAdd(&ssum[g * 32 + c], v);
        if (v >= 0.f) atomicMax((int*)&smax[g * 32 + c], __float_as_int(v));
        else          atomicMin((unsigned int*)&smax[g * 32 + c], __float_as_uint(v));
        if (c == 0) atomicAdd(&scnt[g], 1);
    }
    __syncthreads();
    for (int i = tid; i < NG * 32; i += blockDim.x) {
        atomicAdd(&g_psum[i], ssum[i]);
        atomicMaxF(&g_pmax[i], smax[i]);
    }
    if (tid < NG) atomicAdd(&g_cnt[tid], scnt[tid]);
}

__global__ void finalout_kernel(float* __restrict__ out) {
    int tid = threadIdx.x;
    if (tid < NG * 64) {
        int g = tid >> 6, j = tid & 63;
        int cnt = g_cnt[g];
        float r;
        if (j < 32) r = g_psum[g * 32 + j] / fmaxf((float)cnt, 1.0f);
        else        r = (cnt > 0) ? g_pmax[g * 32 + (j - 32)] : 0.0f;
        out[tid] = r;
    }
}

// ---------------- launch ----------------
extern "C" void kernel_launch(void* const* d_in, const int* in_sizes, int n_in,
                              void* d_out, int out_size) {
    const float* x     = (const float*)d_in[0];
    const int*   ei    = (const int*)d_in[1];
    const float* ea    = (const float*)d_in[2];
    const int*   batch = (const int*)d_in[3];
    const float* s1W = (const float*)d_in[4];
    const float* s1b = (const float*)d_in[5];
    const float* c1Wl = (const float*)d_in[6];
    const float* c1bl = (const float*)d_in[7];
    const float* c1Wr = (const float*)d_in[8];
    const float* c1br = (const float*)d_in[9];
    const float* c1We = (const float*)d_in[10];
    const float* c1att = (const float*)d_in[11];
    const float* c1bias = (const float*)d_in[12];
    const float* bn1g = (const float*)d_in[13];
    const float* bn1b = (const float*)d_in[14];
    const float* s2W = (const float*)d_in[15];
    const float* s2b = (const float*)d_in[16];
    const float* c2Wl = (const float*)d_in[17];
    const float* c2bl = (const float*)d_in[18];
    const float* c2Wr = (const float*)d_in[19];
    const float* c2br = (const float*)d_in[20];
    const float* c2We = (const float*)d_in[21];
    const float* c2att = (const float*)d_in[22];
    const float* c2bias = (const float*)d_in[23];
    const float* bn2g = (const float*)d_in[24];
    const float* bn2b = (const float*)d_in[25];
    float* out = (float*)d_out;

    clear_kernel<<<2048, 256>>>();
    pack1_kernel<<<32, 256>>>(c1Wl, c1bl, c1Wr, c1br, s1W, s1b);
    pack2_kernel<<<8, 256>>>(c2Wl, c2bl, c2Wr, c2br, s2W, s2b);
    easum_kernel<<<1024, 256>>>((const float4*)ea);
    eself_kernel<<<1, 64>>>(c1We, c2We);

    gemm1_kernel<<<dim3((N_NODES + 63) / 64, 2), 256>>>(x);
    edge1_kernel<<<2048, 256>>>(ei, ea, c1We, c1att);
    final1_kernel<<<512, 256>>>(c1bias);
    bnfin1_kernel<<<1, 64>>>(bn1g, bn1b);
    elu1_kernel<<<2048, 256>>>(c1bias);

    gemm2_kernel<<<dim3((N_NODES + 63) / 64, 1), 256>>>();
    edge2_kernel<<<1536, 256>>>(ei, ea, c2We, c2att);
    final2_kernel<<<512, 256>>>(c2bias);
    bnfin2_kernel<<<1, 32>>>(bn2g, bn2b);
    elu2pool_kernel<<<256, 256>>>(batch, c2bias);
    finalout_kernel<<<1, 1024>>>(out);
}

// round 8
// speedup vs baseline: 1.4737x; 1.2534x over previous
#include <cuda_runtime.h>
#include <cstdint>

#define N_NODES 50000
#define N_EDGES 800000
#define NE_TOT  (N_EDGES + N_NODES)   // 850000, self loops appended
#define NG 16

// ---------------- scratch ----------------
__device__ __align__(16) float g_big1[N_NODES * 192];   // 0-63 xl1 | 64-127 xr1 | 128-191 hproj1
__device__ __align__(16) float g_big2[N_NODES * 96];    // 0-31 xl2 | 32-63 xr2 | 64-95 hproj2
__device__ __align__(16) float g_acc1[N_NODES * 64];
__device__ __align__(16) float g_den1[N_NODES * 2];
__device__ __align__(16) float g_h[N_NODES * 64];
__device__ __align__(16) float g_acc2[N_NODES * 32];
__device__ __align__(16) float g_den2[N_NODES];
__device__ __align__(16) float g_Wcat1[128 * 192];
__device__ __align__(16) float g_bcat1[192];
__device__ __align__(16) float g_Wcat2[64 * 96];
__device__ __align__(16) float g_bcat2[96];
__device__ __align__(16) float g_easum[16];
__device__ __align__(16) float g_eself1[64];
__device__ __align__(16) float g_eself2[32];
__device__ __align__(16) float g_bnsum[128];     // [0:64) sum, [64:128) sumsq
__device__ __align__(16) float g_bnsc1[128];     // [0:64) scale, [64:128) shift
__device__ __align__(16) float g_bnsum2[64];
__device__ __align__(16) float g_bnsc2[64];
__device__ __align__(16) float g_psum[NG * 32];
__device__ __align__(16) float g_pmax[NG * 32];
__device__ int g_cnt[NG];

// ---------------- helpers ----------------
__device__ __forceinline__ float lrelu(float v) { return v > 0.f ? v : 0.2f * v; }

__device__ __forceinline__ void red4(float* p, float4 v) {
    asm volatile("red.global.add.v4.f32 [%0], {%1,%2,%3,%4};"
                 :: "l"(p), "f"(v.x), "f"(v.y), "f"(v.z), "f"(v.w) : "memory");
}

__device__ __forceinline__ void atomicMaxF(float* addr, float v) {
    if (v >= 0.f) atomicMax((int*)addr, __float_as_int(v));
    else          atomicMin((unsigned int*)addr, __float_as_uint(v));
}

// ---------------- clear (vectorized) ----------------
__global__ void clear_kernel() {
    int i  = blockIdx.x * blockDim.x + threadIdx.x;
    int st = gridDim.x * blockDim.x;
    float4 z4 = make_float4(0.f, 0.f, 0.f, 0.f);
    float4* a1 = (float4*)g_acc1;
    float4* a2 = (float4*)g_acc2;
    for (int j = i; j < N_NODES * 16; j += st) a1[j] = z4;
    for (int j = i; j < N_NODES * 8;  j += st) a2[j] = z4;
    float2* d1 = (float2*)g_den1;
    for (int j = i; j < N_NODES; j += st) { d1[j] = make_float2(0.f, 0.f); g_den2[j] = 0.f; }
    if (i < 16)  g_easum[i] = 0.f;
    if (i < 128) g_bnsum[i] = 0.f;
    if (i < 64)  g_bnsum2[i] = 0.f;
    if (i < NG * 32) { g_psum[i] = 0.f; g_pmax[i] = __int_as_float(0xff800000); }
    if (i < NG)  g_cnt[i] = 0;
}

// ---------------- weight packing ----------------
__global__ void pack1_kernel(const float* __restrict__ Wl, const float* __restrict__ bl,
                             const float* __restrict__ Wr, const float* __restrict__ br,
                             const float* __restrict__ Ws, const float* __restrict__ bs) {
    int i = blockIdx.x * blockDim.x + threadIdx.x;
    if (i < 128 * 64) {
        int k = i >> 6, j = i & 63;
        g_Wcat1[k * 192 + j]       = Wl[i];
        g_Wcat1[k * 192 + 64 + j]  = Wr[i];
        g_Wcat1[k * 192 + 128 + j] = Ws[i];
    }
    if (i < 64) { g_bcat1[i] = bl[i]; g_bcat1[64 + i] = br[i]; g_bcat1[128 + i] = bs[i]; }
}

__global__ void pack2_kernel(const float* __restrict__ Wl, const float* __restrict__ bl,
                             const float* __restrict__ Wr, const float* __restrict__ br,
                             const float* __restrict__ Ws, const float* __restrict__ bs) {
    int i = blockIdx.x * blockDim.x + threadIdx.x;
    if (i < 64 * 32) {
        int k = i >> 5, j = i & 31;
        g_Wcat2[k * 96 + j]      = Wl[i];
        g_Wcat2[k * 96 + 32 + j] = Wr[i];
        g_Wcat2[k * 96 + 64 + j] = Ws[i];
    }
    if (i < 32) { g_bcat2[i] = bl[i]; g_bcat2[32 + i] = br[i]; g_bcat2[64 + i] = bs[i]; }
}

// ---------------- edge_attr column sums (float4 grid-stride; validated) ----------------
__global__ void easum_kernel(const float4* __restrict__ ea4) {
    int tid = blockIdx.x * blockDim.x + threadIdx.x;
    int st  = gridDim.x * blockDim.x;
    int grp = tid & 3;
    float4 s = make_float4(0.f, 0.f, 0.f, 0.f);
    #pragma unroll 4
    for (int i = tid; i < N_EDGES * 4; i += st) {
        float4 v = ea4[i];
        s.x += v.x; s.y += v.y; s.z += v.z; s.w += v.w;
    }
    __shared__ float sm[16];
    if (threadIdx.x < 16) sm[threadIdx.x] = 0.f;
    __syncthreads();
    atomicAdd(&sm[grp * 4 + 0], s.x);
    atomicAdd(&sm[grp * 4 + 1], s.y);
    atomicAdd(&sm[grp * 4 + 2], s.z);
    atomicAdd(&sm[grp * 4 + 3], s.w);
    __syncthreads();
    if (threadIdx.x < 16) atomicAdd(&g_easum[threadIdx.x], sm[threadIdx.x]);
}

__global__ void eself_kernel(const float* __restrict__ We1, const float* __restrict__ We2) {
    __shared__ float m[16];
    int t = threadIdx.x;
    if (t < 16) m[t] = g_easum[t] * (1.0f / N_EDGES);
    __syncthreads();
    if (t < 64) {
        float s = 0.f;
        #pragma unroll
        for (int k = 0; k < 16; k++) s += m[k] * We1[k * 64 + t];
        g_eself1[t] = s;
    }
    if (t < 32) {
        float s = 0.f;
        #pragma unroll
        for (int k = 0; k < 16; k++) s += m[k] * We2[k * 32 + t];
        g_eself2[t] = s;
    }
}

// ---------------- tiled GEMM (round-3 plain-FFMA version) ----------------
template <int K, int NT>
__device__ __forceinline__ void gemm_body(const float* __restrict__ A,
                                          const float* __restrict__ W,
                                          const float* __restrict__ bias,
                                          float* __restrict__ C, int M) {
    __shared__ __align__(16) float As[16][65];
    __shared__ float Bs[16][100];
    const int bm = blockIdx.x * 64;
    const int bn = blockIdx.y * 96;
    const int tid = threadIdx.x;
    const int tx = tid & 15, ty = tid >> 4;
    float acc[4][6];
    #pragma unroll
    for (int i = 0; i < 4; i++)
        #pragma unroll
        for (int j = 0; j < 6; j++) acc[i][j] = 0.f;
    const int ar = tid >> 2, ac = (tid & 3) << 2;
    for (int k0 = 0; k0 < K; k0 += 16) {
        float4 av = make_float4(0.f, 0.f, 0.f, 0.f);
        int row = bm + ar;
        if (row < M) av = *(const float4*)&A[(size_t)row * K + k0 + ac];
        As[ac][ar] = av.x; As[ac + 1][ar] = av.y; As[ac + 2][ar] = av.z; As[ac + 3][ar] = av.w;
        #pragma unroll
        for (int i = 0; i < 6; i++) {
            int idx = tid + (i << 8);
            int r = idx / 96, cc = idx - r * 96;
            Bs[r][cc] = W[(k0 + r) * NT + bn + cc];
        }
        __syncthreads();
        #pragma unroll
        for (int kk = 0; kk < 16; kk++) {
            float a[4], b[6];
            #pragma unroll
            for (int i = 0; i < 4; i++) a[i] = As[kk][(ty << 2) + i];
            #pragma unroll
            for (int j = 0; j < 6; j++) b[j] = Bs[kk][tx * 6 + j];
            #pragma unroll
            for (int i = 0; i < 4; i++)
                #pragma unroll
                for (int j = 0; j < 6; j++) acc[i][j] += a[i] * b[j];
        }
        __syncthreads();
    }
    #pragma unroll
    for (int i = 0; i < 4; i++) {
        int r = bm + (ty << 2) + i;
        if (r < M) {
            #pragma unroll
            for (int j = 0; j < 6; j++) {
                int cc = bn + tx * 6 + j;
                C[(size_t)r * NT + cc] = acc[i][j] + bias[cc];
            }
        }
    }
}

__global__ void gemm1_kernel(const float* __restrict__ A) {
    gemm_body<128, 192>(A, g_Wcat1, g_bcat1, g_big1, N_NODES);
}
__global__ void gemm2_kernel() {
    gemm_body<64, 96>(g_h, g_Wcat2, g_bcat2, g_big2, N_NODES);
}

// ---------------- edge kernel layer 1 (round-3 smem-We version) ----------------
__global__ void edge1_kernel(const int* __restrict__ ei, const float* __restrict__ ea,
                             const float* __restrict__ We, const float* __restrict__ att) {
    __shared__ __align__(16) float sWe[16 * 64];
    __shared__ __align__(16) float sAtt[64];
    __shared__ __align__(16) float sEself[64];
    for (int i = threadIdx.x; i < 16 * 64; i += blockDim.x) sWe[i] = We[i];
    if (threadIdx.x < 64) { sAtt[threadIdx.x] = att[threadIdx.x]; sEself[threadIdx.x] = g_eself1[threadIdx.x]; }
    __syncthreads();
    const int lane = threadIdx.x & 31;
    const int sub  = lane & 15;          // 0..15 -> 4 channels each
    const int head = sub >> 3;           // 0 or 1
    const int half = lane >> 4;          // edge within pair
    const int warp = threadIdx.x >> 5;
    const int nwarps = (gridDim.x * blockDim.x) >> 5;
    const int gw = blockIdx.x * (blockDim.x >> 5) + warp;
    const int npairs = (NE_TOT + 1) >> 1;
    const float4 a4  = *(const float4*)&sAtt[4 * sub];
    const float4 es4 = *(const float4*)&sEself[4 * sub];
    for (int pair = gw; pair < npairs; pair += nwarps) {
        int e = pair * 2 + half;
        bool valid = e < NE_TOT;
        int s = 0, d = 0;
        bool isloop = false;
        if (valid) {
            if (e < N_EDGES) { s = ei[e]; d = ei[N_EDGES + e]; }
            else             { s = d = e - N_EDGES; isloop = true; }
        }
        int eidx = (valid && !isloop) ? e : 0;
        float eav = ea[(size_t)eidx * 16 + sub];
        float4 e4 = make_float4(0.f, 0.f, 0.f, 0.f);
        #pragma unroll
        for (int k = 0; k < 16; k++) {
            float a = __shfl_sync(0xffffffffu, eav, k, 16);
            float4 w4 = *(const float4*)&sWe[k * 64 + 4 * sub];
            e4.x += a * w4.x; e4.y += a * w4.y; e4.z += a * w4.z; e4.w += a * w4.w;
        }
        if (isloop) e4 = es4;
        const float* xlp = g_big1 + (size_t)s * 192;
        const float* xrp = g_big1 + (size_t)d * 192 + 64;
        float4 xl4 = *(const float4*)&xlp[4 * sub];
        float4 xr4 = *(const float4*)&xrp[4 * sub];
        float4 mm;
        mm.x = lrelu(xl4.x + xr4.x + e4.x);
        mm.y = lrelu(xl4.y + xr4.y + e4.y);
        mm.z = lrelu(xl4.z + xr4.z + e4.z);
        mm.w = lrelu(xl4.w + xr4.w + e4.w);
        float p = mm.x * a4.x + mm.y * a4.y + mm.z * a4.z + mm.w * a4.w;
        p += __shfl_xor_sync(0xffffffffu, p, 4);
        p += __shfl_xor_sync(0xffffffffu, p, 2);
        p += __shfl_xor_sync(0xffffffffu, p, 1);
        float w = __expf(p);
        if (valid) {
            if ((sub & 7) == 0) atomicAdd(&g_den1[d * 2 + head], w);
            float4 r = make_float4(w * xl4.x, w * xl4.y, w * xl4.z, w * xl4.w);
            red4(&g_acc1[(size_t)d * 64 + 4 * sub], r);
        }
    }
}

// ---------------- edge kernel layer 2 (round-3 smem-We version) ----------------
__global__ void edge2_kernel(const int* __restrict__ ei, const float* __restrict__ ea,
                             const float* __restrict__ We, const float* __restrict__ att) {
    __shared__ __align__(16) float sWe[16 * 32];
    __shared__ __align__(16) float sAtt[32];
    __shared__ __align__(16) float sEself[32];
    for (int i = threadIdx.x; i < 512; i += blockDim.x) sWe[i] = We[i];
    if (threadIdx.x < 32) { sAtt[threadIdx.x] = att[threadIdx.x]; sEself[threadIdx.x] = g_eself2[threadIdx.x]; }
    __syncthreads();
    const int lane = threadIdx.x & 31;
    const int grp = lane >> 3, sub = lane & 7;
    const int warp = threadIdx.x >> 5;
    const int nwarps = (gridDim.x * blockDim.x) >> 5;
    const int gw = blockIdx.x * (blockDim.x >> 5) + warp;
    const int nquads = (NE_TOT + 3) >> 2;
    const float4 a4  = *(const float4*)&sAtt[4 * sub];
    const float4 es4 = *(const float4*)&sEself[4 * sub];
    for (int q = gw; q < nquads; q += nwarps) {
        int e = q * 4 + grp;
        bool valid = e < NE_TOT;
        int s = 0, d = 0;
        bool isloop = false;
        if (valid) {
            if (e < N_EDGES) { s = ei[e]; d = ei[N_EDGES + e]; }
            else             { s = d = e - N_EDGES; isloop = true; }
        }
        int eidx = (valid && !isloop) ? e : 0;
        float ev0 = ea[(size_t)eidx * 16 + sub];
        float ev1 = ea[(size_t)eidx * 16 + 8 + sub];
        float4 e4 = make_float4(0.f, 0.f, 0.f, 0.f);
        #pragma unroll
        for (int k = 0; k < 8; k++) {
            float a = __shfl_sync(0xffffffffu, ev0, k, 8);
            float4 w4 = *(const float4*)&sWe[k * 32 + 4 * sub];
            e4.x += a * w4.x; e4.y += a * w4.y; e4.z += a * w4.z; e4.w += a * w4.w;
        }
        #pragma unroll
        for (int k = 0; k < 8; k++) {
            float a = __shfl_sync(0xffffffffu, ev1, k, 8);
            float4 w4 = *(const float4*)&sWe[(8 + k) * 32 + 4 * sub];
            e4.x += a * w4.x; e4.y += a * w4.y; e4.z += a * w4.z; e4.w += a * w4.w;
        }
        if (isloop) e4 = es4;
        const float* xlp = g_big2 + (size_t)s * 96;
        const float* xrp = g_big2 + (size_t)d * 96 + 32;
        float4 xl4 = *(const float4*)&xlp[4 * sub];
        float4 xr4 = *(const float4*)&xrp[4 * sub];
        float4 mm;
        mm.x = lrelu(xl4.x + xr4.x + e4.x);
        mm.y = lrelu(xl4.y + xr4.y + e4.y);
        mm.z = lrelu(xl4.z + xr4.z + e4.z);
        mm.w = lrelu(xl4.w + xr4.w + e4.w);
        float p = mm.x * a4.x + mm.y * a4.y + mm.z * a4.z + mm.w * a4.w;
        p += __shfl_xor_sync(0xffffffffu, p, 4);
        p += __shfl_xor_sync(0xffffffffu, p, 2);
        p += __shfl_xor_sync(0xffffffffu, p, 1);
        float w = __expf(p);
        if (valid) {
            if (sub == 0) atomicAdd(&g_den2[d], w);
            float4 r = make_float4(w * xl4.x, w * xl4.y, w * xl4.z, w * xl4.w);
            red4(&g_acc2[(size_t)d * 32 + 4 * sub], r);
        }
    }
}

// ---------------- BN stats layer 1 (fused: no out1 write; validated round 7) ----------------
__global__ void final1_kernel(const float* __restrict__ bias) {
    int tid = threadIdx.x;
    int c = tid & 63;
    int h = c >> 5;
    float bb = bias[c];
    float s = 0.f, q = 0.f;
    for (int n = blockIdx.x * 4 + (tid >> 6); n < N_NODES; n += gridDim.x * 4) {
        float v = g_acc1[(size_t)n * 64 + c] / (g_den1[n * 2 + h] + 1e-16f) + bb;
        s += v; q += v * v;
    }
    __shared__ float ss[256], sq[256];
    ss[tid] = s; sq[tid] = q;
    __syncthreads();
    if (tid < 64) {
        s = ss[tid] + ss[tid + 64] + ss[tid + 128] + ss[tid + 192];
        q = sq[tid] + sq[tid + 64] + sq[tid + 128] + sq[tid + 192];
        atomicAdd(&g_bnsum[tid], s);
        atomicAdd(&g_bnsum[64 + tid], q);
    }
}

__global__ void bnfin1_kernel(const float* __restrict__ g, const float* __restrict__ b) {
    int c = threadIdx.x;
    if (c < 64) {
        float mean = g_bnsum[c] * (1.0f / N_NODES);
        float var  = g_bnsum[64 + c] * (1.0f / N_NODES) - mean * mean;
        float sc   = g[c] * rsqrtf(var + 1e-5f);
        g_bnsc1[c] = sc;
        g_bnsc1[64 + c] = b[c] - mean * sc;
    }
}

__global__ void elu1_kernel(const float* __restrict__ bias) {
    int i = blockIdx.x * blockDim.x + threadIdx.x;
    int st = gridDim.x * blockDim.x;
    for (; i < N_NODES * 64; i += st) {
        int n = i >> 6, c = i & 63;
        float v = g_acc1[i] / (g_den1[n * 2 + (c >> 5)] + 1e-16f) + bias[c];
        float t = v * g_bnsc1[c] + g_bnsc1[64 + c] + g_big1[(size_t)n * 192 + 128 + c];
        g_h[i] = t > 0.f ? t : expm1f(t);
    }
}

// ---------------- BN stats layer 2 (fused) ----------------
__global__ void final2_kernel(const float* __restrict__ bias) {
    int tid = threadIdx.x;
    int c = tid & 31;
    float bb = bias[c];
    float s = 0.f, q = 0.f;
    for (int n = blockIdx.x * 8 + (tid >> 5); n < N_NODES; n += gridDim.x * 8) {
        float v = g_acc2[(size_t)n * 32 + c] / (g_den2[n] + 1e-16f) + bb;
        s += v; q += v * v;
    }
    __shared__ float ss[256], sq[256];
    ss[tid] = s; sq[tid] = q;
    __syncthreads();
    if (tid < 32) {
        s = 0.f; q = 0.f;
        #pragma unroll
        for (int gg = 0; gg < 8; gg++) { s += ss[tid + gg * 32]; q += sq[tid + gg * 32]; }
        atomicAdd(&g_bnsum2[tid], s);
        atomicAdd(&g_bnsum2[32 + tid], q);
    }
}

__global__ void bnfin2_kernel(const float* __restrict__ g, const float* __restrict__ b) {
    int c = threadIdx.x;
    if (c < 32) {
        float mean = g_bnsum2[c] * (1.0f / N_NODES);
        float var  = g_bnsum2[32 + c] * (1.0f / N_NODES) - mean * mean;
        float sc   = g[c] * rsqrtf(var + 1e-5f);
        g_bnsc2[c] = sc;
        g_bnsc2[32 + c] = b[c] - mean * sc;
    }
}

// ---------------- elu2 + graph pooling (batch sorted; fused recompute) ----------------
__global__ void elu2pool_kernel(const int* __restrict__ batch, const float* __restrict__ bias) {
    __shared__ float ssum[NG * 32];
    __shared__ float smax[NG * 32];
    __shared__ int scnt[NG];
    int tid = threadIdx.x;
    for (int i = tid; i < NG * 32; i += blockDim.x) { ssum[i] = 0.f; smax[i] = __int_as_float(0xff800000); }
    if (tid < NG) scnt[tid] = 0;
    __syncthreads();
    int c = tid & 31;
    float bb = bias[c];
    for (int n = blockIdx.x * 8 + (tid >> 5); n < N_NODES; n += gridDim.x * 8) {
        float v = g_acc2[(size_t)n * 32 + c] / (g_den2[n] + 1e-16f) + bb;
        v = v * g_bnsc2[c] + g_bnsc2[32 + c] + g_big2[(size_t)n * 96 + 64 + c];
        v = v > 0.f ? v : expm1f(v);
        int g = batch[n];
        atomicAdd(&ssum[g * 32 + c], v);
        if (v >= 0.f) atomicMax((int*)&smax[g * 32 + c], __float_as_int(v));
        else          atomicMin((unsigned int*)&smax[g * 32 + c], __float_as_uint(v));
        if (c == 0) atomicAdd(&scnt[g], 1);
    }
    __syncthreads();
    for (int i = tid; i < NG * 32; i += blockDim.x) {
        atomicAdd(&g_psum[i], ssum[i]);
        atomicMaxF(&g_pmax[i], smax[i]);
    }
    if (tid < NG) atomicAdd(&g_cnt[tid], scnt[tid]);
}

__global__ void finalout_kernel(float* __restrict__ out) {
    int tid = threadIdx.x;
    if (tid < NG * 64) {
        int g = tid >> 6, j = tid & 63;
        int cnt = g_cnt[g];
        float r;
        if (j < 32) r = g_psum[g * 32 + j] / fmaxf((float)cnt, 1.0f);
        else        r = (cnt > 0) ? g_pmax[g * 32 + (j - 32)] : 0.0f;
        out[tid] = r;
    }
}

// ---------------- launch ----------------
extern "C" void kernel_launch(void* const* d_in, const int* in_sizes, int n_in,
                              void* d_out, int out_size) {
    const float* x     = (const float*)d_in[0];
    const int*   ei    = (const int*)d_in[1];
    const float* ea    = (const float*)d_in[2];
    const int*   batch = (const int*)d_in[3];
    const float* s1W = (const float*)d_in[4];
    const float* s1b = (const float*)d_in[5];
    const float* c1Wl = (const float*)d_in[6];
    const float* c1bl = (const float*)d_in[7];
    const float* c1Wr = (const float*)d_in[8];
    const float* c1br = (const float*)d_in[9];
    const float* c1We = (const float*)d_in[10];
    const float* c1att = (const float*)d_in[11];
    const float* c1bias = (const float*)d_in[12];
    const float* bn1g = (const float*)d_in[13];
    const float* bn1b = (const float*)d_in[14];
    const float* s2W = (const float*)d_in[15];
    const float* s2b = (const float*)d_in[16];
    const float* c2Wl = (const float*)d_in[17];
    const float* c2bl = (const float*)d_in[18];
    const float* c2Wr = (const float*)d_in[19];
    const float* c2br = (const float*)d_in[20];
    const float* c2We = (const float*)d_in[21];
    const float* c2att = (const float*)d_in[22];
    const float* c2bias = (const float*)d_in[23];
    const float* bn2g = (const float*)d_in[24];
    const float* bn2b = (const float*)d_in[25];
    float* out = (float*)d_out;

    clear_kernel<<<2048, 256>>>();
    pack1_kernel<<<32, 256>>>(c1Wl, c1bl, c1Wr, c1br, s1W, s1b);
    pack2_kernel<<<8, 256>>>(c2Wl, c2bl, c2Wr, c2br, s2W, s2b);
    easum_kernel<<<1024, 256>>>((const float4*)ea);
    eself_kernel<<<1, 64>>>(c1We, c2We);

    gemm1_kernel<<<dim3((N_NODES + 63) / 64, 2), 256>>>(x);
    edge1_kernel<<<2048, 256>>>(ei, ea, c1We, c1att);
    final1_kernel<<<512, 256>>>(c1bias);
    bnfin1_kernel<<<1, 64>>>(bn1g, bn1b);
    elu1_kernel<<<2048, 256>>>(c1bias);

    gemm2_kernel<<<dim3((N_NODES + 63) / 64, 1), 256>>>();
    edge2_kernel<<<1536, 256>>>(ei, ea, c2We, c2att);
    final2_kernel<<<512, 256>>>(c2bias);
    bnfin2_kernel<<<1, 32>>>(bn2g, bn2b);
    elu2pool_kernel<<<256, 256>>>(batch, c2bias);
    finalout_kernel<<<1, 1024>>>(out);
}

// round 10
// speedup vs baseline: 1.4976x; 1.0162x over previous
#include <cuda_runtime.h>
#include <cstdint>

#define N_NODES 50000
#define N_EDGES 800000
#define NE_TOT  (N_EDGES + N_NODES)   // 850000, self loops appended
#define NG 16

typedef unsigned long long ull;

// ---------------- scratch ----------------
__device__ __align__(16) float g_big1[N_NODES * 192];   // 0-63 xl1 | 64-127 xr1 | 128-191 hproj1
__device__ __align__(16) float g_big2[N_NODES * 96];    // 0-31 xl2 | 32-63 xr2 | 64-95 hproj2
__device__ __align__(16) float g_acc1[N_NODES * 64];
__device__ __align__(16) float g_den1[N_NODES * 2];
__device__ __align__(16) float g_h[N_NODES * 64];
__device__ __align__(16) float g_acc2[N_NODES * 32];
__device__ __align__(16) float g_den2[N_NODES];
__device__ __align__(16) float g_Wcat1[128 * 192];
__device__ __align__(16) float g_bcat1[192];
__device__ __align__(16) float g_Wcat2[64 * 96];
__device__ __align__(16) float g_bcat2[96];
__device__ __align__(16) float g_easum[16];
__device__ __align__(16) float g_eself1[64];
__device__ __align__(16) float g_eself2[32];
__device__ __align__(16) float g_bnsum[128];     // [0:64) sum, [64:128) sumsq
__device__ __align__(16) float g_bnsc1[128];     // [0:64) scale, [64:128) shift
__device__ __align__(16) float g_bnsum2[64];
__device__ __align__(16) float g_bnsc2[64];
__device__ __align__(16) float g_psum[NG * 32];
__device__ __align__(16) float g_pmax[NG * 32];
__device__ int g_cnt[NG];

// ---------------- helpers ----------------
__device__ __forceinline__ ull pk2(float a, float b) {
    ull r; asm("mov.b64 %0,{%1,%2};" : "=l"(r) : "f"(a), "f"(b)); return r;
}
__device__ __forceinline__ float2 up2(ull v) {
    float2 r; asm("mov.b64 {%0,%1},%2;" : "=f"(r.x), "=f"(r.y) : "l"(v)); return r;
}
__device__ __forceinline__ ull fma2(ull a, ull b, ull c) {
    ull d; asm("fma.rn.f32x2 %0,%1,%2,%3;" : "=l"(d) : "l"(a), "l"(b), "l"(c)); return d;
}
__device__ __forceinline__ float lrelu(float v) { return v > 0.f ? v : 0.2f * v; }

__device__ __forceinline__ void red4(float* p, float4 v) {
    asm volatile("red.global.add.v4.f32 [%0], {%1,%2,%3,%4};"
                 :: "l"(p), "f"(v.x), "f"(v.y), "f"(v.z), "f"(v.w) : "memory");
}

__device__ __forceinline__ void atomicMaxF(float* addr, float v) {
    if (v >= 0.f) atomicMax((int*)addr, __float_as_int(v));
    else          atomicMin((unsigned int*)addr, __float_as_uint(v));
}

// ---------------- clear (vectorized) ----------------
__global__ void clear_kernel() {
    int i  = blockIdx.x * blockDim.x + threadIdx.x;
    int st = gridDim.x * blockDim.x;
    float4 z4 = make_float4(0.f, 0.f, 0.f, 0.f);
    float4* a1 = (float4*)g_acc1;
    float4* a2 = (float4*)g_acc2;
    for (int j = i; j < N_NODES * 16; j += st) a1[j] = z4;
    for (int j = i; j < N_NODES * 8;  j += st) a2[j] = z4;
    float2* d1 = (float2*)g_den1;
    for (int j = i; j < N_NODES; j += st) { d1[j] = make_float2(0.f, 0.f); g_den2[j] = 0.f; }
    if (i < 16)  g_easum[i] = 0.f;
    if (i < 128) g_bnsum[i] = 0.f;
    if (i < 64)  g_bnsum2[i] = 0.f;
    if (i < NG * 32) { g_psum[i] = 0.f; g_pmax[i] = __int_as_float(0xff800000); }
    if (i < NG)  g_cnt[i] = 0;
}

// ---------------- weight packing ----------------
__global__ void pack1_kernel(const float* __restrict__ Wl, const float* __restrict__ bl,
                             const float* __restrict__ Wr, const float* __restrict__ br,
                             const float* __restrict__ Ws, const float* __restrict__ bs) {
    int i = blockIdx.x * blockDim.x + threadIdx.x;
    if (i < 128 * 64) {
        int k = i >> 6, j = i & 63;
        g_Wcat1[k * 192 + j]       = Wl[i];
        g_Wcat1[k * 192 + 64 + j]  = Wr[i];
        g_Wcat1[k * 192 + 128 + j] = Ws[i];
    }
    if (i < 64) { g_bcat1[i] = bl[i]; g_bcat1[64 + i] = br[i]; g_bcat1[128 + i] = bs[i]; }
}

__global__ void pack2_kernel(const float* __restrict__ Wl, const float* __restrict__ bl,
                             const float* __restrict__ Wr, const float* __restrict__ br,
                             const float* __restrict__ Ws, const float* __restrict__ bs) {
    int i = blockIdx.x * blockDim.x + threadIdx.x;
    if (i < 64 * 32) {
        int k = i >> 5, j = i & 31;
        g_Wcat2[k * 96 + j]      = Wl[i];
        g_Wcat2[k * 96 + 32 + j] = Wr[i];
        g_Wcat2[k * 96 + 64 + j] = Ws[i];
    }
    if (i < 32) { g_bcat2[i] = bl[i]; g_bcat2[32 + i] = br[i]; g_bcat2[64 + i] = bs[i]; }
}

// ---------------- edge_attr column sums (float4 grid-stride; validated) ----------------
__global__ void easum_kernel(const float4* __restrict__ ea4) {
    int tid = blockIdx.x * blockDim.x + threadIdx.x;
    int st  = gridDim.x * blockDim.x;
    int grp = tid & 3;
    float4 s = make_float4(0.f, 0.f, 0.f, 0.f);
    #pragma unroll 4
    for (int i = tid; i < N_EDGES * 4; i += st) {
        float4 v = ea4[i];
        s.x += v.x; s.y += v.y; s.z += v.z; s.w += v.w;
    }
    __shared__ float sm[16];
    if (threadIdx.x < 16) sm[threadIdx.x] = 0.f;
    __syncthreads();
    atomicAdd(&sm[grp * 4 + 0], s.x);
    atomicAdd(&sm[grp * 4 + 1], s.y);
    atomicAdd(&sm[grp * 4 + 2], s.z);
    atomicAdd(&sm[grp * 4 + 3], s.w);
    __syncthreads();
    if (threadIdx.x < 16) atomicAdd(&g_easum[threadIdx.x], sm[threadIdx.x]);
}

__global__ void eself_kernel(const float* __restrict__ We1, const float* __restrict__ We2) {
    __shared__ float m[16];
    int t = threadIdx.x;
    if (t < 16) m[t] = g_easum[t] * (1.0f / N_EDGES);
    __syncthreads();
    if (t < 64) {
        float s = 0.f;
        #pragma unroll
        for (int k = 0; k < 16; k++) s += m[k] * We1[k * 64 + t];
        g_eself1[t] = s;
    }
    if (t < 32) {
        float s = 0.f;
        #pragma unroll
        for (int k = 0; k < 16; k++) s += m[k] * We2[k * 32 + t];
        g_eself2[t] = s;
    }
}

// ---------------- tiled GEMM with fma.rn.f32x2 (isolated A/B vs round-8 FFMA) ----------------
template <int K, int NT>
__device__ __forceinline__ void gemm_body(const float* __restrict__ A,
                                          const float* __restrict__ W,
                                          const float* __restrict__ bias,
                                          float* __restrict__ C, int M) {
    __shared__ __align__(16) float As[16 * 68];
    __shared__ __align__(8)  float Bs[16 * 100];
    const int bm = blockIdx.x * 64;
    const int bn = blockIdx.y * 96;
    const int tid = threadIdx.x;
    const int tx = tid & 15, ty = tid >> 4;
    ull acc[4][3];
    #pragma unroll
    for (int i = 0; i < 4; i++)
        #pragma unroll
        for (int j = 0; j < 3; j++) acc[i][j] = 0ull;
    const int ar = tid >> 2, ac = (tid & 3) << 2;
    for (int k0 = 0; k0 < K; k0 += 16) {
        float4 av = make_float4(0.f, 0.f, 0.f, 0.f);
        int row = bm + ar;
        if (row < M) av = *(const float4*)&A[(size_t)row * K + k0 + ac];
        As[(ac + 0) * 68 + ar] = av.x;
        As[(ac + 1) * 68 + ar] = av.y;
        As[(ac + 2) * 68 + ar] = av.z;
        As[(ac + 3) * 68 + ar] = av.w;
        #pragma unroll
        for (int i = 0; i < 6; i++) {
            int idx = tid + (i << 8);
            int r = idx / 96, cc = idx - r * 96;
            Bs[r * 100 + cc] = W[(k0 + r) * NT + bn + cc];
        }
        __syncthreads();
        #pragma unroll
        for (int kk = 0; kk < 16; kk++) {
            float4 a = *(const float4*)&As[kk * 68 + (ty << 2)];
            ull b0 = *(const ull*)&Bs[kk * 100 + tx * 6];
            ull b1 = *(const ull*)&Bs[kk * 100 + tx * 6 + 2];
            ull b2 = *(const ull*)&Bs[kk * 100 + tx * 6 + 4];
            ull ap;
            ap = pk2(a.x, a.x);
            acc[0][0] = fma2(ap, b0, acc[0][0]); acc[0][1] = fma2(ap, b1, acc[0][1]); acc[0][2] = fma2(ap, b2, acc[0][2]);
            ap = pk2(a.y, a.y);
            acc[1][0] = fma2(ap, b0, acc[1][0]); acc[1][1] = fma2(ap, b1, acc[1][1]); acc[1][2] = fma2(ap, b2, acc[1][2]);
            ap = pk2(a.z, a.z);
            acc[2][0] = fma2(ap, b0, acc[2][0]); acc[2][1] = fma2(ap, b1, acc[2][1]); acc[2][2] = fma2(ap, b2, acc[2][2]);
            ap = pk2(a.w, a.w);
            acc[3][0] = fma2(ap, b0, acc[3][0]); acc[3][1] = fma2(ap, b1, acc[3][1]); acc[3][2] = fma2(ap, b2, acc[3][2]);
        }
        __syncthreads();
    }
    #pragma unroll
    for (int i = 0; i < 4; i++) {
        int r = bm + (ty << 2) + i;
        if (r < M) {
            #pragma unroll
            for (int j = 0; j < 3; j++) {
                float2 v = up2(acc[i][j]);
                int cc = bn + tx * 6 + 2 * j;
                C[(size_t)r * NT + cc]     = v.x + bias[cc];
                C[(size_t)r * NT + cc + 1] = v.y + bias[cc + 1];
            }
        }
    }
}

__global__ void gemm1_kernel(const float* __restrict__ A) {
    gemm_body<128, 192>(A, g_Wcat1, g_bcat1, g_big1, N_NODES);
}
__global__ void gemm2_kernel() {
    gemm_body<64, 96>(g_h, g_Wcat2, g_bcat2, g_big2, N_NODES);
}

// ---------------- edge kernel layer 1 (round-3/8 smem-We version; best known) ----------------
__global__ void edge1_kernel(const int* __restrict__ ei, const float* __restrict__ ea,
                             const float* __restrict__ We, const float* __restrict__ att) {
    __shared__ __align__(16) float sWe[16 * 64];
    __shared__ __align__(16) float sAtt[64];
    __shared__ __align__(16) float sEself[64];
    for (int i = threadIdx.x; i < 16 * 64; i += blockDim.x) sWe[i] = We[i];
    if (threadIdx.x < 64) { sAtt[threadIdx.x] = att[threadIdx.x]; sEself[threadIdx.x] = g_eself1[threadIdx.x]; }
    __syncthreads();
    const int lane = threadIdx.x & 31;
    const int sub  = lane & 15;          // 0..15 -> 4 channels each
    const int head = sub >> 3;           // 0 or 1
    const int half = lane >> 4;          // edge within pair
    const int warp = threadIdx.x >> 5;
    const int nwarps = (gridDim.x * blockDim.x) >> 5;
    const int gw = blockIdx.x * (blockDim.x >> 5) + warp;
    const int npairs = (NE_TOT + 1) >> 1;
    const float4 a4  = *(const float4*)&sAtt[4 * sub];
    const float4 es4 = *(const float4*)&sEself[4 * sub];
    for (int pair = gw; pair < npairs; pair += nwarps) {
        int e = pair * 2 + half;
        bool valid = e < NE_TOT;
        int s = 0, d = 0;
        bool isloop = false;
        if (valid) {
            if (e < N_EDGES) { s = ei[e]; d = ei[N_EDGES + e]; }
            else             { s = d = e - N_EDGES; isloop = true; }
        }
        int eidx = (valid && !isloop) ? e : 0;
        float eav = ea[(size_t)eidx * 16 + sub];
        float4 e4 = make_float4(0.f, 0.f, 0.f, 0.f);
        #pragma unroll
        for (int k = 0; k < 16; k++) {
            float a = __shfl_sync(0xffffffffu, eav, k, 16);
            float4 w4 = *(const float4*)&sWe[k * 64 + 4 * sub];
            e4.x += a * w4.x; e4.y += a * w4.y; e4.z += a * w4.z; e4.w += a * w4.w;
        }
        if (isloop) e4 = es4;
        const float* xlp = g_big1 + (size_t)s * 192;
        const float* xrp = g_big1 + (size_t)d * 192 + 64;
        float4 xl4 = *(const float4*)&xlp[4 * sub];
        float4 xr4 = *(const float4*)&xrp[4 * sub];
        float4 mm;
        mm.x = lrelu(xl4.x + xr4.x + e4.x);
        mm.y = lrelu(xl4.y + xr4.y + e4.y);
        mm.z = lrelu(xl4.z + xr4.z + e4.z);
        mm.w = lrelu(xl4.w + xr4.w + e4.w);
        float p = mm.x * a4.x + mm.y * a4.y + mm.z * a4.z + mm.w * a4.w;
        p += __shfl_xor_sync(0xffffffffu, p, 4);
        p += __shfl_xor_sync(0xffffffffu, p, 2);
        p += __shfl_xor_sync(0xffffffffu, p, 1);
        float w = __expf(p);
        if (valid) {
            if ((sub & 7) == 0) atomicAdd(&g_den1[d * 2 + head], w);
            float4 r = make_float4(w * xl4.x, w * xl4.y, w * xl4.z, w * xl4.w);
            red4(&g_acc1[(size_t)d * 64 + 4 * sub], r);
        }
    }
}

// ---------------- edge kernel layer 2 (round-3/8 smem-We version; best known) ----------------
__global__ void edge2_kernel(const int* __restrict__ ei, const float* __restrict__ ea,
                             const float* __restrict__ We, const float* __restrict__ att) {
    __shared__ __align__(16) float sWe[16 * 32];
    __shared__ __align__(16) float sAtt[32];
    __shared__ __align__(16) float sEself[32];
    for (int i = threadIdx.x; i < 512; i += blockDim.x) sWe[i] = We[i];
    if (threadIdx.x < 32) { sAtt[threadIdx.x] = att[threadIdx.x]; sEself[threadIdx.x] = g_eself2[threadIdx.x]; }
    __syncthreads();
    const int lane = threadIdx.x & 31;
    const int grp = lane >> 3, sub = lane & 7;
    const int warp = threadIdx.x >> 5;
    const int nwarps = (gridDim.x * blockDim.x) >> 5;
    const int gw = blockIdx.x * (blockDim.x >> 5) + warp;
    const int nquads = (NE_TOT + 3) >> 2;
    const float4 a4  = *(const float4*)&sAtt[4 * sub];
    const float4 es4 = *(const float4*)&sEself[4 * sub];
    for (int q = gw; q < nquads; q += nwarps) {
        int e = q * 4 + grp;
        bool valid = e < NE_TOT;
        int s = 0, d = 0;
        bool isloop = false;
        if (valid) {
            if (e < N_EDGES) { s = ei[e]; d = ei[N_EDGES + e]; }
            else             { s = d = e - N_EDGES; isloop = true; }
        }
        int eidx = (valid && !isloop) ? e : 0;
        float ev0 = ea[(size_t)eidx * 16 + sub];
        float ev1 = ea[(size_t)eidx * 16 + 8 + sub];
        float4 e4 = make_float4(0.f, 0.f, 0.f, 0.f);
        #pragma unroll
        for (int k = 0; k < 8; k++) {
            float a = __shfl_sync(0xffffffffu, ev0, k, 8);
            float4 w4 = *(const float4*)&sWe[k * 32 + 4 * sub];
            e4.x += a * w4.x; e4.y += a * w4.y; e4.z += a * w4.z; e4.w += a * w4.w;
        }
        #pragma unroll
        for (int k = 0; k < 8; k++) {
            float a = __shfl_sync(0xffffffffu, ev1, k, 8);
            float4 w4 = *(const float4*)&sWe[(8 + k) * 32 + 4 * sub];
            e4.x += a * w4.x; e4.y += a * w4.y; e4.z += a * w4.z; e4.w += a * w4.w;
        }
        if (isloop) e4 = es4;
        const float* xlp = g_big2 + (size_t)s * 96;
        const float* xrp = g_big2 + (size_t)d * 96 + 32;
        float4 xl4 = *(const float4*)&xlp[4 * sub];
        float4 xr4 = *(const float4*)&xrp[4 * sub];
        float4 mm;
        mm.x = lrelu(xl4.x + xr4.x + e4.x);
        mm.y = lrelu(xl4.y + xr4.y + e4.y);
        mm.z = lrelu(xl4.z + xr4.z + e4.z);
        mm.w = lrelu(xl4.w + xr4.w + e4.w);
        float p = mm.x * a4.x + mm.y * a4.y + mm.z * a4.z + mm.w * a4.w;
        p += __shfl_xor_sync(0xffffffffu, p, 4);
        p += __shfl_xor_sync(0xffffffffu, p, 2);
        p += __shfl_xor_sync(0xffffffffu, p, 1);
        float w = __expf(p);
        if (valid) {
            if (sub == 0) atomicAdd(&g_den2[d], w);
            float4 r = make_float4(w * xl4.x, w * xl4.y, w * xl4.z, w * xl4.w);
            red4(&g_acc2[(size_t)d * 32 + 4 * sub], r);
        }
    }
}

// ---------------- BN stats layer 1 (fused) ----------------
__global__ void final1_kernel(const float* __restrict__ bias) {
    int tid = threadIdx.x;
    int c = tid & 63;
    int h = c >> 5;
    float bb = bias[c];
    float s = 0.f, q = 0.f;
    for (int n = blockIdx.x * 4 + (tid >> 6); n < N_NODES; n += gridDim.x * 4) {
        float v = g_acc1[(size_t)n * 64 + c] / (g_den1[n * 2 + h] + 1e-16f) + bb;
        s += v; q += v * v;
    }
    __shared__ float ss[256], sq[256];
    ss[tid] = s; sq[tid] = q;
    __syncthreads();
    if (tid < 64) {
        s = ss[tid] + ss[tid + 64] + ss[tid + 128] + ss[tid + 192];
        q = sq[tid] + sq[tid + 64] + sq[tid + 128] + sq[tid + 192];
        atomicAdd(&g_bnsum[tid], s);
        atomicAdd(&g_bnsum[64 + tid], q);
    }
}

__global__ void bnfin1_kernel(const float* __restrict__ g, const float* __restrict__ b) {
    int c = threadIdx.x;
    if (c < 64) {
        float mean = g_bnsum[c] * (1.0f / N_NODES);
        float var  = g_bnsum[64 + c] * (1.0f / N_NODES) - mean * mean;
        float sc   = g[c] * rsqrtf(var + 1e-5f);
        g_bnsc1[c] = sc;
        g_bnsc1[64 + c] = b[c] - mean * sc;
    }
}

__global__ void elu1_kernel(const float* __restrict__ bias) {
    int i = blockIdx.x * blockDim.x + threadIdx.x;
    int st = gridDim.x * blockDim.x;
    for (; i < N_NODES * 64; i += st) {
        int n = i >> 6, c = i & 63;
        float v = g_acc1[i] / (g_den1[n * 2 + (c >> 5)] + 1e-16f) + bias[c];
        float t = v * g_bnsc1[c] + g_bnsc1[64 + c] + g_big1[(size_t)n * 192 + 128 + c];
        g_h[i] = t > 0.f ? t : expm1f(t);
    }
}

// ---------------- BN stats layer 2 (fused) ----------------
__global__ void final2_kernel(const float* __restrict__ bias) {
    int tid = threadIdx.x;
    int c = tid & 31;
    float bb = bias[c];
    float s = 0.f, q = 0.f;
    for (int n = blockIdx.x * 8 + (tid >> 5); n < N_NODES; n += gridDim.x * 8) {
        float v = g_acc2[(size_t)n * 32 + c] / (g_den2[n] + 1e-16f) + bb;
        s += v; q += v * v;
    }
    __shared__ float ss[256], sq[256];
    ss[tid] = s; sq[tid] = q;
    __syncthreads();
    if (tid < 32) {
        s = 0.f; q = 0.f;
        #pragma unroll
        for (int gg = 0; gg < 8; gg++) { s += ss[tid + gg * 32]; q += sq[tid + gg * 32]; }
        atomicAdd(&g_bnsum2[tid], s);
        atomicAdd(&g_bnsum2[32 + tid], q);
    }
}

__global__ void bnfin2_kernel(const float* __restrict__ g, const float* __restrict__ b) {
    int c = threadIdx.x;
    if (c < 32) {
        float mean = g_bnsum2[c] * (1.0f / N_NODES);
        float var  = g_bnsum2[32 + c] * (1.0f / N_NODES) - mean * mean;
        float sc   = g[c] * rsqrtf(var + 1e-5f);
        g_bnsc2[c] = sc;
        g_bnsc2[32 + c] = b[c] - mean * sc;
    }
}

// ---------------- elu2 + graph pooling (batch sorted; fused recompute) ----------------
__global__ void elu2pool_kernel(const int* __restrict__ batch, const float* __restrict__ bias) {
    __shared__ float ssum[NG * 32];
    __shared__ float smax[NG * 32];
    __shared__ int scnt[NG];
    int tid = threadIdx.x;
    for (int i = tid; i < NG * 32; i += blockDim.x) { ssum[i] = 0.f; smax[i] = __int_as_float(0xff800000); }
    if (tid < NG) scnt[tid] = 0;
    __syncthreads();
    int c = tid & 31;
    float bb = bias[c];
    for (int n = blockIdx.x * 8 + (tid >> 5); n < N_NODES; n += gridDim.x * 8) {
        float v = g_acc2[(size_t)n * 32 + c] / (g_den2[n] + 1e-16f) + bb;
        v = v * g_bnsc2[c] + g_bnsc2[32 + c] + g_big2[(size_t)n * 96 + 64 + c];
        v = v > 0.f ? v : expm1f(v);
        int g = batch[n];
        atomicAdd(&ssum[g * 32 + c], v);
        if (v >= 0.f) atomicMax((int*)&smax[g * 32 + c], __float_as_int(v));
        else          atomicMin((unsigned int*)&smax[g * 32 + c], __float_as_uint(v));
        if (c == 0) atomicAdd(&scnt[g], 1);
    }
    __syncthreads();
    for (int i = tid; i < NG * 32; i += blockDim.x) {
        atomicAdd(&g_psum[i], ssum[i]);
        atomicMaxF(&g_pmax[i], smax[i]);
    }
    if (tid < NG) atomicAdd(&g_cnt[tid], scnt[tid]);
}

__global__ void finalout_kernel(float* __restrict__ out) {
    int tid = threadIdx.x;
    if (tid < NG * 64) {
        int g = tid >> 6, j = tid & 63;
        int cnt = g_cnt[g];
        float r;
        if (j < 32) r = g_psum[g * 32 + j] / fmaxf((float)cnt, 1.0f);
        else        r = (cnt > 0) ? g_pmax[g * 32 + (j - 32)] : 0.0f;
        out[tid] = r;
    }
}

// ---------------- launch ----------------
extern "C" void kernel_launch(void* const* d_in, const int* in_sizes, int n_in,
                              void* d_out, int out_size) {
    const float* x     = (const float*)d_in[0];
    const int*   ei    = (const int*)d_in[1];
    const float* ea    = (const float*)d_in[2];
    const int*   batch = (const int*)d_in[3];
    const float* s1W = (const float*)d_in[4];
    const float* s1b = (const float*)d_in[5];
    const float* c1Wl = (const float*)d_in[6];
    const float* c1bl = (const float*)d_in[7];
    const float* c1Wr = (const float*)d_in[8];
    const float* c1br = (const float*)d_in[9];
    const float* c1We = (const float*)d_in[10];
    const float* c1att = (const float*)d_in[11];
    const float* c1bias = (const float*)d_in[12];
    const float* bn1g = (const float*)d_in[13];
    const float* bn1b = (const float*)d_in[14];
    const float* s2W = (const float*)d_in[15];
    const float* s2b = (const float*)d_in[16];
    const float* c2Wl = (const float*)d_in[17];
    const float* c2bl = (const float*)d_in[18];
    const float* c2Wr = (const float*)d_in[19];
    const float* c2br = (const float*)d_in[20];
    const float* c2We = (const float*)d_in[21];
    const float* c2att = (const float*)d_in[22];
    const float* c2bias = (const float*)d_in[23];
    const float* bn2g = (const float*)d_in[24];
    const float* bn2b = (const float*)d_in[25];
    float* out = (float*)d_out;

    clear_kernel<<<2048, 256>>>();
    pack1_kernel<<<32, 256>>>(c1Wl, c1bl, c1Wr, c1br, s1W, s1b);
    pack2_kernel<<<8, 256>>>(c2Wl, c2bl, c2Wr, c2br, s2W, s2b);
    easum_kernel<<<1024, 256>>>((const float4*)ea);
    eself_kernel<<<1, 64>>>(c1We, c2We);

    gemm1_kernel<<<dim3((N_NODES + 63) / 64, 2), 256>>>(x);
    edge1_kernel<<<2048, 256>>>(ei, ea, c1We, c1att);
    final1_kernel<<<512, 256>>>(c1bias);
    bnfin1_kernel<<<1, 64>>>(bn1g, bn1b);
    elu1_kernel<<<2048, 256>>>(c1bias);

    gemm2_kernel<<<dim3((N_NODES + 63) / 64, 1), 256>>>();
    edge2_kernel<<<1536, 256>>>(ei, ea, c2We, c2att);
    final2_kernel<<<512, 256>>>(c2bias);
    bnfin2_kernel<<<1, 32>>>(bn2g, bn2b);
    elu2pool_kernel<<<256, 256>>>(batch, c2bias);
    finalout_kernel<<<1, 1024>>>(out);
}

// round 12
// speedup vs baseline: 1.6730x; 1.1171x over previous
#include <cuda_runtime.h>
#include <cstdint>

#define N_NODES 50000
#define N_EDGES 800000
#define NE_TOT  (N_EDGES + N_NODES)   // 850000, self loops appended
#define NG 16

typedef unsigned long long ull;

// ---------------- scratch ----------------
__device__ __align__(16) float g_big1[N_NODES * 192];   // 0-63 xl1 | 64-127 xr1 | 128-191 hproj1
__device__ __align__(16) float g_big2[N_NODES * 96];    // 0-31 xl2 | 32-63 xr2 | 64-95 hproj2
__device__ __align__(16) float g_acc1[N_NODES * 64];
__device__ __align__(16) float g_den1[N_NODES * 2];
__device__ __align__(16) float g_h[N_NODES * 64];
__device__ __align__(16) float g_acc2[N_NODES * 32];
__device__ __align__(16) float g_den2[N_NODES];
__device__ __align__(16) float g_Wcat1[128 * 192];
__device__ __align__(16) float g_bcat1[192];
__device__ __align__(16) float g_Wcat2[64 * 96];
__device__ __align__(16) float g_bcat2[96];
__device__ __align__(16) float g_easum[16];
__device__ __align__(16) float g_eself1[64];
__device__ __align__(16) float g_eself2[32];
__device__ __align__(16) float g_bnsum[128];     // [0:64) sum, [64:128) sumsq
__device__ __align__(16) float g_bnsc1[128];     // [0:64) scale, [64:128) shift
__device__ __align__(16) float g_bnsum2[64];
__device__ __align__(16) float g_bnsc2[64];
__device__ __align__(16) float g_psum[NG * 32];
__device__ __align__(16) float g_pmax[NG * 32];
__device__ int g_cnt[NG];

// ---------------- helpers ----------------
__device__ __forceinline__ ull pk2(float a, float b) {
    ull r; asm("mov.b64 %0,{%1,%2};" : "=l"(r) : "f"(a), "f"(b)); return r;
}
__device__ __forceinline__ float2 up2(ull v) {
    float2 r; asm("mov.b64 {%0,%1},%2;" : "=f"(r.x), "=f"(r.y) : "l"(v)); return r;
}
__device__ __forceinline__ ull fma2(ull a, ull b, ull c) {
    ull d; asm("fma.rn.f32x2 %0,%1,%2,%3;" : "=l"(d) : "l"(a), "l"(b), "l"(c)); return d;
}
__device__ __forceinline__ float lrelu(float v) { return v > 0.f ? v : 0.2f * v; }

__device__ __forceinline__ void red4(float* p, float4 v) {
    asm volatile("red.global.add.v4.f32 [%0], {%1,%2,%3,%4};"
                 :: "l"(p), "f"(v.x), "f"(v.y), "f"(v.z), "f"(v.w) : "memory");
}

__device__ __forceinline__ void atomicMaxF(float* addr, float v) {
    if (v >= 0.f) atomicMax((int*)addr, __float_as_int(v));
    else          atomicMin((unsigned int*)addr, __float_as_uint(v));
}

// ---------------- clear (vectorized) ----------------
__global__ void clear_kernel() {
    int i  = blockIdx.x * blockDim.x + threadIdx.x;
    int st = gridDim.x * blockDim.x;
    float4 z4 = make_float4(0.f, 0.f, 0.f, 0.f);
    float4* a1 = (float4*)g_acc1;
    float4* a2 = (float4*)g_acc2;
    for (int j = i; j < N_NODES * 16; j += st) a1[j] = z4;
    for (int j = i; j < N_NODES * 8;  j += st) a2[j] = z4;
    float2* d1 = (float2*)g_den1;
    for (int j = i; j < N_NODES; j += st) { d1[j] = make_float2(0.f, 0.f); g_den2[j] = 0.f; }
    if (i < 16)  g_easum[i] = 0.f;
    if (i < 128) g_bnsum[i] = 0.f;
    if (i < 64)  g_bnsum2[i] = 0.f;
    if (i < NG * 32) { g_psum[i] = 0.f; g_pmax[i] = __int_as_float(0xff800000); }
    if (i < NG)  g_cnt[i] = 0;
}

// ---------------- weight packing ----------------
__global__ void pack1_kernel(const float* __restrict__ Wl, const float* __restrict__ bl,
                             const float* __restrict__ Wr, const float* __restrict__ br,
                             const float* __restrict__ Ws, const float* __restrict__ bs) {
    int i = blockIdx.x * blockDim.x + threadIdx.x;
    if (i < 128 * 64) {
        int k = i >> 6, j = i & 63;
        g_Wcat1[k * 192 + j]       = Wl[i];
        g_Wcat1[k * 192 + 64 + j]  = Wr[i];
        g_Wcat1[k * 192 + 128 + j] = Ws[i];
    }
    if (i < 64) { g_bcat1[i] = bl[i]; g_bcat1[64 + i] = br[i]; g_bcat1[128 + i] = bs[i]; }
}

__global__ void pack2_kernel(const float* __restrict__ Wl, const float* __restrict__ bl,
                             const float* __restrict__ Wr, const float* __restrict__ br,
                             const float* __restrict__ Ws, const float* __restrict__ bs) {
    int i = blockIdx.x * blockDim.x + threadIdx.x;
    if (i < 64 * 32) {
        int k = i >> 5, j = i & 31;
        g_Wcat2[k * 96 + j]      = Wl[i];
        g_Wcat2[k * 96 + 32 + j] = Wr[i];
        g_Wcat2[k * 96 + 64 + j] = Ws[i];
    }
    if (i < 32) { g_bcat2[i] = bl[i]; g_bcat2[32 + i] = br[i]; g_bcat2[64 + i] = bs[i]; }
}

// ---------------- edge_attr column sums (unroll-4 batched loads for MLP) ----------------
__global__ void easum_kernel(const float4* __restrict__ ea4) {
    const int NT = N_EDGES * 4;
    int tid = blockIdx.x * blockDim.x + threadIdx.x;
    int st  = gridDim.x * blockDim.x;     // multiple of 4
    int grp = tid & 3;
    float4 s = make_float4(0.f, 0.f, 0.f, 0.f);
    int i = tid;
    for (; i + 3 * st < NT; i += 4 * st) {
        float4 v0 = ea4[i];
        float4 v1 = ea4[i + st];
        float4 v2 = ea4[i + 2 * st];
        float4 v3 = ea4[i + 3 * st];
        s.x += v0.x + v1.x + v2.x + v3.x;
        s.y += v0.y + v1.y + v2.y + v3.y;
        s.z += v0.z + v1.z + v2.z + v3.z;
        s.w += v0.w + v1.w + v2.w + v3.w;
    }
    for (; i < NT; i += st) {
        float4 v = ea4[i];
        s.x += v.x; s.y += v.y; s.z += v.z; s.w += v.w;
    }
    __shared__ float sm[16];
    if (threadIdx.x < 16) sm[threadIdx.x] = 0.f;
    __syncthreads();
    atomicAdd(&sm[grp * 4 + 0], s.x);
    atomicAdd(&sm[grp * 4 + 1], s.y);
    atomicAdd(&sm[grp * 4 + 2], s.z);
    atomicAdd(&sm[grp * 4 + 3], s.w);
    __syncthreads();
    if (threadIdx.x < 16) atomicAdd(&g_easum[threadIdx.x], sm[threadIdx.x]);
}

__global__ void eself_kernel(const float* __restrict__ We1, const float* __restrict__ We2) {
    __shared__ float m[16];
    int t = threadIdx.x;
    if (t < 16) m[t] = g_easum[t] * (1.0f / N_EDGES);
    __syncthreads();
    if (t < 64) {
        float s = 0.f;
        #pragma unroll
        for (int k = 0; k < 16; k++) s += m[k] * We1[k * 64 + t];
        g_eself1[t] = s;
    }
    if (t < 32) {
        float s = 0.f;
        #pragma unroll
        for (int k = 0; k < 16; k++) s += m[k] * We2[k * 32 + t];
        g_eself2[t] = s;
    }
}

// ---------------- tiled GEMM with fma.rn.f32x2 (validated round 10) ----------------
template <int K, int NT>
__device__ __forceinline__ void gemm_body(const float* __restrict__ A,
                                          const float* __restrict__ W,
                                          const float* __restrict__ bias,
                                          float* __restrict__ C, int M) {
    __shared__ __align__(16) float As[16 * 68];
    __shared__ __align__(8)  float Bs[16 * 100];
    const int bm = blockIdx.x * 64;
    const int bn = blockIdx.y * 96;
    const int tid = threadIdx.x;
    const int tx = tid & 15, ty = tid >> 4;
    ull acc[4][3];
    #pragma unroll
    for (int i = 0; i < 4; i++)
        #pragma unroll
        for (int j = 0; j < 3; j++) acc[i][j] = 0ull;
    const int ar = tid >> 2, ac = (tid & 3) << 2;
    for (int k0 = 0; k0 < K; k0 += 16) {
        float4 av = make_float4(0.f, 0.f, 0.f, 0.f);
        int row = bm + ar;
        if (row < M) av = *(const float4*)&A[(size_t)row * K + k0 + ac];
        As[(ac + 0) * 68 + ar] = av.x;
        As[(ac + 1) * 68 + ar] = av.y;
        As[(ac + 2) * 68 + ar] = av.z;
        As[(ac + 3) * 68 + ar] = av.w;
        #pragma unroll
        for (int i = 0; i < 6; i++) {
            int idx = tid + (i << 8);
            int r = idx / 96, cc = idx - r * 96;
            Bs[r * 100 + cc] = W[(k0 + r) * NT + bn + cc];
        }
        __syncthreads();
        #pragma unroll
        for (int kk = 0; kk < 16; kk++) {
            float4 a = *(const float4*)&As[kk * 68 + (ty << 2)];
            ull b0 = *(const ull*)&Bs[kk * 100 + tx * 6];
            ull b1 = *(const ull*)&Bs[kk * 100 + tx * 6 + 2];
            ull b2 = *(const ull*)&Bs[kk * 100 + tx * 6 + 4];
            ull ap;
            ap = pk2(a.x, a.x);
            acc[0][0] = fma2(ap, b0, acc[0][0]); acc[0][1] = fma2(ap, b1, acc[0][1]); acc[0][2] = fma2(ap, b2, acc[0][2]);
            ap = pk2(a.y, a.y);
            acc[1][0] = fma2(ap, b0, acc[1][0]); acc[1][1] = fma2(ap, b1, acc[1][1]); acc[1][2] = fma2(ap, b2, acc[1][2]);
            ap = pk2(a.z, a.z);
            acc[2][0] = fma2(ap, b0, acc[2][0]); acc[2][1] = fma2(ap, b1, acc[2][1]); acc[2][2] = fma2(ap, b2, acc[2][2]);
            ap = pk2(a.w, a.w);
            acc[3][0] = fma2(ap, b0, acc[3][0]); acc[3][1] = fma2(ap, b1, acc[3][1]); acc[3][2] = fma2(ap, b2, acc[3][2]);
        }
        __syncthreads();
    }
    #pragma unroll
    for (int i = 0; i < 4; i++) {
        int r = bm + (ty << 2) + i;
        if (r < M) {
            #pragma unroll
            for (int j = 0; j < 3; j++) {
                float2 v = up2(acc[i][j]);
                int cc = bn + tx * 6 + 2 * j;
                C[(size_t)r * NT + cc]     = v.x + bias[cc];
                C[(size_t)r * NT + cc + 1] = v.y + bias[cc + 1];
            }
        }
    }
}

__global__ void gemm1_kernel(const float* __restrict__ A) {
    gemm_body<128, 192>(A, g_Wcat1, g_bcat1, g_big1, N_NODES);
}
__global__ void gemm2_kernel() {
    gemm_body<64, 96>(g_h, g_Wcat2, g_bcat2, g_big2, N_NODES);
}

// ---------------- edge kernel layer 1 (smem-We; 2 edges in flight per warp) ----------------
__global__ void edge1_kernel(const int* __restrict__ ei, const float* __restrict__ ea,
                             const float* __restrict__ We, const float* __restrict__ att) {
    __shared__ __align__(16) float sWe[16 * 64];
    __shared__ __align__(16) float sAtt[64];
    __shared__ __align__(16) float sEself[64];
    for (int i = threadIdx.x; i < 16 * 64; i += blockDim.x) sWe[i] = We[i];
    if (threadIdx.x < 64) { sAtt[threadIdx.x] = att[threadIdx.x]; sEself[threadIdx.x] = g_eself1[threadIdx.x]; }
    __syncthreads();
    const int lane = threadIdx.x & 31;
    const int sub  = lane & 15;          // 0..15 -> 4 channels each
    const int head = sub >> 3;           // 0 or 1
    const int half = lane >> 4;          // edge within pair
    const int warp = threadIdx.x >> 5;
    const int nwarps = (gridDim.x * blockDim.x) >> 5;
    const int gw = blockIdx.x * (blockDim.x >> 5) + warp;
    const int npairs = (NE_TOT + 1) >> 1;
    const float4 a4  = *(const float4*)&sAtt[4 * sub];
    const float4 es4 = *(const float4*)&sEself[4 * sub];
    for (int p0 = gw; p0 < npairs; p0 += 2 * nwarps) {
        const int p1 = p0 + nwarps;
        const bool hasB = p1 < npairs;
        int eA = p0 * 2 + half;
        int eB = hasB ? (p1 * 2 + half) : 0;
        bool vA = eA < NE_TOT;
        bool vB = hasB && (eB < NE_TOT);
        int sA = 0, dA = 0, sB = 0, dB = 0;
        bool loopA = false, loopB = false;
        if (vA) {
            if (eA < N_EDGES) { sA = ei[eA]; dA = ei[N_EDGES + eA]; }
            else              { sA = dA = eA - N_EDGES; loopA = true; }
        }
        if (vB) {
            if (eB < N_EDGES) { sB = ei[eB]; dB = ei[N_EDGES + eB]; }
            else              { sB = dB = eB - N_EDGES; loopB = true; }
        }
        int exA = (vA && !loopA) ? eA : 0;
        int exB = (vB && !loopB) ? eB : 0;
        float eavA = ea[(size_t)exA * 16 + sub];
        float eavB = ea[(size_t)exB * 16 + sub];
        float4 xlA = *(const float4*)&g_big1[(size_t)sA * 192 + 4 * sub];
        float4 xrA = *(const float4*)&g_big1[(size_t)dA * 192 + 64 + 4 * sub];
        float4 xlB = *(const float4*)&g_big1[(size_t)sB * 192 + 4 * sub];
        float4 xrB = *(const float4*)&g_big1[(size_t)dB * 192 + 64 + 4 * sub];
        float4 e4A = make_float4(0.f, 0.f, 0.f, 0.f);
        float4 e4B = make_float4(0.f, 0.f, 0.f, 0.f);
        #pragma unroll
        for (int k = 0; k < 16; k++) {
            float aA = __shfl_sync(0xffffffffu, eavA, k, 16);
            float aB = __shfl_sync(0xffffffffu, eavB, k, 16);
            float4 w4 = *(const float4*)&sWe[k * 64 + 4 * sub];   // shared by both edges
            e4A.x += aA * w4.x; e4A.y += aA * w4.y; e4A.z += aA * w4.z; e4A.w += aA * w4.w;
            e4B.x += aB * w4.x; e4B.y += aB * w4.y; e4B.z += aB * w4.z; e4B.w += aB * w4.w;
        }
        if (loopA) e4A = es4;
        if (loopB) e4B = es4;
        float4 mA, mB;
        mA.x = lrelu(xlA.x + xrA.x + e4A.x);
        mA.y = lrelu(xlA.y + xrA.y + e4A.y);
        mA.z = lrelu(xlA.z + xrA.z + e4A.z);
        mA.w = lrelu(xlA.w + xrA.w + e4A.w);
        mB.x = lrelu(xlB.x + xrB.x + e4B.x);
        mB.y = lrelu(xlB.y + xrB.y + e4B.y);
        mB.z = lrelu(xlB.z + xrB.z + e4B.z);
        mB.w = lrelu(xlB.w + xrB.w + e4B.w);
        float pA = mA.x * a4.x + mA.y * a4.y + mA.z * a4.z + mA.w * a4.w;
        float pB = mB.x * a4.x + mB.y * a4.y + mB.z * a4.z + mB.w * a4.w;
        pA += __shfl_xor_sync(0xffffffffu, pA, 4);
        pB += __shfl_xor_sync(0xffffffffu, pB, 4);
        pA += __shfl_xor_sync(0xffffffffu, pA, 2);
        pB += __shfl_xor_sync(0xffffffffu, pB, 2);
        pA += __shfl_xor_sync(0xffffffffu, pA, 1);
        pB += __shfl_xor_sync(0xffffffffu, pB, 1);
        float wA = __expf(pA);
        float wB = __expf(pB);
        if (vA) {
            if ((sub & 7) == 0) atomicAdd(&g_den1[dA * 2 + head], wA);
            red4(&g_acc1[(size_t)dA * 64 + 4 * sub],
                 make_float4(wA * xlA.x, wA * xlA.y, wA * xlA.z, wA * xlA.w));
        }
        if (vB) {
            if ((sub & 7) == 0) atomicAdd(&g_den1[dB * 2 + head], wB);
            red4(&g_acc1[(size_t)dB * 64 + 4 * sub],
                 make_float4(wB * xlB.x, wB * xlB.y, wB * xlB.z, wB * xlB.w));
        }
    }
}

// ---------------- edge kernel layer 2 (smem-We; 2 quads in flight per warp) ----------------
__global__ void edge2_kernel(const int* __restrict__ ei, const float* __restrict__ ea,
                             const float* __restrict__ We, const float* __restrict__ att) {
    __shared__ __align__(16) float sWe[16 * 32];
    __shared__ __align__(16) float sAtt[32];
    __shared__ __align__(16) float sEself[32];
    for (int i = threadIdx.x; i < 512; i += blockDim.x) sWe[i] = We[i];
    if (threadIdx.x < 32) { sAtt[threadIdx.x] = att[threadIdx.x]; sEself[threadIdx.x] = g_eself2[threadIdx.x]; }
    __syncthreads();
    const int lane = threadIdx.x & 31;
    const int grp = lane >> 3, sub = lane & 7;
    const int warp = threadIdx.x >> 5;
    const int nwarps = (gridDim.x * blockDim.x) >> 5;
    const int gw = blockIdx.x * (blockDim.x >> 5) + warp;
    const int nquads = (NE_TOT + 3) >> 2;
    const float4 a4  = *(const float4*)&sAtt[4 * sub];
    const float4 es4 = *(const float4*)&sEself[4 * sub];
    for (int q0 = gw; q0 < nquads; q0 += 2 * nwarps) {
        const int q1 = q0 + nwarps;
        const bool hasB = q1 < nquads;
        int eA = q0 * 4 + grp;
        int eB = hasB ? (q1 * 4 + grp) : 0;
        bool vA = eA < NE_TOT;
        bool vB = hasB && (eB < NE_TOT);
        int sA = 0, dA = 0, sB = 0, dB = 0;
        bool loopA = false, loopB = false;
        if (vA) {
            if (eA < N_EDGES) { sA = ei[eA]; dA = ei[N_EDGES + eA]; }
            else              { sA = dA = eA - N_EDGES; loopA = true; }
        }
        if (vB) {
            if (eB < N_EDGES) { sB = ei[eB]; dB = ei[N_EDGES + eB]; }
            else              { sB = dB = eB - N_EDGES; loopB = true; }
        }
        int exA = (vA && !loopA) ? eA : 0;
        int exB = (vB && !loopB) ? eB : 0;
        float e0A = ea[(size_t)exA * 16 + sub];
        float e1A = ea[(size_t)exA * 16 + 8 + sub];
        float e0B = ea[(size_t)exB * 16 + sub];
        float e1B = ea[(size_t)exB * 16 + 8 + sub];
        float4 xlA = *(const float4*)&g_big2[(size_t)sA * 96 + 4 * sub];
        float4 xrA = *(const float4*)&g_big2[(size_t)dA * 96 + 32 + 4 * sub];
        float4 xlB = *(const float4*)&g_big2[(size_t)sB * 96 + 4 * sub];
        float4 xrB = *(const float4*)&g_big2[(size_t)dB * 96 + 32 + 4 * sub];
        float4 e4A = make_float4(0.f, 0.f, 0.f, 0.f);
        float4 e4B = make_float4(0.f, 0.f, 0.f, 0.f);
        #pragma unroll
        for (int k = 0; k < 8; k++) {
            float aA = __shfl_sync(0xffffffffu, e0A, k, 8);
            float aB = __shfl_sync(0xffffffffu, e0B, k, 8);
            float4 w4 = *(const float4*)&sWe[k * 32 + 4 * sub];
            e4A.x += aA * w4.x; e4A.y += aA * w4.y; e4A.z += aA * w4.z; e4A.w += aA * w4.w;
            e4B.x += aB * w4.x; e4B.y += aB * w4.y; e4B.z += aB * w4.z; e4B.w += aB * w4.w;
        }
        #pragma unroll
        for (int k = 0; k < 8; k++) {
            float aA = __shfl_sync(0xffffffffu, e1A, k, 8);
            float aB = __shfl_sync(0xffffffffu, e1B, k, 8);
            float4 w4 = *(const float4*)&sWe[(8 + k) * 32 + 4 * sub];
            e4A.x += aA * w4.x; e4A.y += aA * w4.y; e4A.z += aA * w4.z; e4A.w += aA * w4.w;
            e4B.x += aB * w4.x; e4B.y += aB * w4.y; e4B.z += aB * w4.z; e4B.w += aB * w4.w;
        }
        if (loopA) e4A = es4;
        if (loopB) e4B = es4;
        float4 mA, mB;
        mA.x = lrelu(xlA.x + xrA.x + e4A.x);
        mA.y = lrelu(xlA.y + xrA.y + e4A.y);
        mA.z = lrelu(xlA.z + xrA.z + e4A.z);
        mA.w = lrelu(xlA.w + xrA.w + e4A.w);
        mB.x = lrelu(xlB.x + xrB.x + e4B.x);
        mB.y = lrelu(xlB.y + xrB.y + e4B.y);
        mB.z = lrelu(xlB.z + xrB.z + e4B.z);
        mB.w = lrelu(xlB.w + xrB.w + e4B.w);
        float pA = mA.x * a4.x + mA.y * a4.y + mA.z * a4.z + mA.w * a4.w;
        float pB = mB.x * a4.x + mB.y * a4.y + mB.z * a4.z + mB.w * a4.w;
        pA += __shfl_xor_sync(0xffffffffu, pA, 4);
        pB += __shfl_xor_sync(0xffffffffu, pB, 4);
        pA += __shfl_xor_sync(0xffffffffu, pA, 2);
        pB += __shfl_xor_sync(0xffffffffu, pB, 2);
        pA += __shfl_xor_sync(0xffffffffu, pA, 1);
        pB += __shfl_xor_sync(0xffffffffu, pB, 1);
        float wA = __expf(pA);
        float wB = __expf(pB);
        if (vA) {
            if (sub == 0) atomicAdd(&g_den2[dA], wA);
            red4(&g_acc2[(size_t)dA * 32 + 4 * sub],
                 make_float4(wA * xlA.x, wA * xlA.y, wA * xlA.z, wA * xlA.w));
        }
        if (vB) {
            if (sub == 0) atomicAdd(&g_den2[dB], wB);
            red4(&g_acc2[(size_t)dB * 32 + 4 * sub],
                 make_float4(wB * xlB.x, wB * xlB.y, wB * xlB.z, wB * xlB.w));
        }
    }
}

// ---------------- BN stats layer 1 (fused) ----------------
__global__ void final1_kernel(const float* __restrict__ bias) {
    int tid = threadIdx.x;
    int c = tid & 63;
    int h = c >> 5;
    float bb = bias[c];
    float s = 0.f, q = 0.f;
    for (int n = blockIdx.x * 4 + (tid >> 6); n < N_NODES; n += gridDim.x * 4) {
        float v = g_acc1[(size_t)n * 64 + c] / (g_den1[n * 2 + h] + 1e-16f) + bb;
        s += v; q += v * v;
    }
    __shared__ float ss[256], sq[256];
    ss[tid] = s; sq[tid] = q;
    __syncthreads();
    if (tid < 64) {
        s = ss[tid] + ss[tid + 64] + ss[tid + 128] + ss[tid + 192];
        q = sq[tid] + sq[tid + 64] + sq[tid + 128] + sq[tid + 192];
        atomicAdd(&g_bnsum[tid], s);
        atomicAdd(&g_bnsum[64 + tid], q);
    }
}

__global__ void bnfin1_kernel(const float* __restrict__ g, const float* __restrict__ b) {
    int c = threadIdx.x;
    if (c < 64) {
        float mean = g_bnsum[c] * (1.0f / N_NODES);
        float var  = g_bnsum[64 + c] * (1.0f / N_NODES) - mean * mean;
        float sc   = g[c] * rsqrtf(var + 1e-5f);
        g_bnsc1[c] = sc;
        g_bnsc1[64 + c] = b[c] - mean * sc;
    }
}

__global__ void elu1_kernel(const float* __restrict__ bias) {
    int i = blockIdx.x * blockDim.x + threadIdx.x;
    int st = gridDim.x * blockDim.x;
    for (; i < N_NODES * 64; i += st) {
        int n = i >> 6, c = i & 63;
        float v = g_acc1[i] / (g_den1[n * 2 + (c >> 5)] + 1e-16f) + bias[c];
        float t = v * g_bnsc1[c] + g_bnsc1[64 + c] + g_big1[(size_t)n * 192 + 128 + c];
        g_h[i] = t > 0.f ? t : expm1f(t);
    }
}

// ---------------- BN stats layer 2 (fused) ----------------
__global__ void final2_kernel(const float* __restrict__ bias) {
    int tid = threadIdx.x;
    int c = tid & 31;
    float bb = bias[c];
    float s = 0.f, q = 0.f;
    for (int n = blockIdx.x * 8 + (tid >> 5); n < N_NODES; n += gridDim.x * 8) {
        float v = g_acc2[(size_t)n * 32 + c] / (g_den2[n] + 1e-16f) + bb;
        s += v; q += v * v;
    }
    __shared__ float ss[256], sq[256];
    ss[tid] = s; sq[tid] = q;
    __syncthreads();
    if (tid < 32) {
        s = 0.f; q = 0.f;
        #pragma unroll
        for (int gg = 0; gg < 8; gg++) { s += ss[tid + gg * 32]; q += sq[tid + gg * 32]; }
        atomicAdd(&g_bnsum2[tid], s);
        atomicAdd(&g_bnsum2[32 + tid], q);
    }
}

__global__ void bnfin2_kernel(const float* __restrict__ g, const float* __restrict__ b) {
    int c = threadIdx.x;
    if (c < 32) {
        float mean = g_bnsum2[c] * (1.0f / N_NODES);
        float var  = g_bnsum2[32 + c] * (1.0f / N_NODES) - mean * mean;
        float sc   = g[c] * rsqrtf(var + 1e-5f);
        g_bnsc2[c] = sc;
        g_bnsc2[32 + c] = b[c] - mean * sc;
    }
}

// ---------------- elu2 + graph pooling (batch sorted; fused recompute) ----------------
__global__ void elu2pool_kernel(const int* __restrict__ batch, const float* __restrict__ bias) {
    __shared__ float ssum[NG * 32];
    __shared__ float smax[NG * 32];
    __shared__ int scnt[NG];
    int tid = threadIdx.x;
    for (int i = tid; i < NG * 32; i += blockDim.x) { ssum[i] = 0.f; smax[i] = __int_as_float(0xff800000); }
    if (tid < NG) scnt[tid] = 0;
    __syncthreads();
    int c = tid & 31;
    float bb = bias[c];
    for (int n = blockIdx.x * 8 + (tid >> 5); n < N_NODES; n += gridDim.x * 8) {
        float v = g_acc2[(size_t)n * 32 + c] / (g_den2[n] + 1e-16f) + bb;
        v = v * g_bnsc2[c] + g_bnsc2[32 + c] + g_big2[(size_t)n * 96 + 64 + c];
        v = v > 0.f ? v : expm1f(v);
        int g = batch[n];
        atomicAdd(&ssum[g * 32 + c], v);
        if (v >= 0.f) atomicMax((int*)&smax[g * 32 + c], __float_as_int(v));
        else          atomicMin((unsigned int*)&smax[g * 32 + c], __float_as_uint(v));
        if (c == 0) atomicAdd(&scnt[g], 1);
    }
    __syncthreads();
    for (int i = tid; i < NG * 32; i += blockDim.x) {
        atomicAdd(&g_psum[i], ssum[i]);
        atomicMaxF(&g_pmax[i], smax[i]);
    }
    if (tid < NG) atomicAdd(&g_cnt[tid], scnt[tid]);
}

__global__ void finalout_kernel(float* __restrict__ out) {
    int tid = threadIdx.x;
    if (tid < NG * 64) {
        int g = tid >> 6, j = tid & 63;
        int cnt = g_cnt[g];
        float r;
        if (j < 32) r = g_psum[g * 32 + j] / fmaxf((float)cnt, 1.0f);
        else        r = (cnt > 0) ? g_pmax[g * 32 + (j - 32)] : 0.0f;
        out[tid] = r;
    }
}

// ---------------- launch ----------------
extern "C" void kernel_launch(void* const* d_in, const int* in_sizes, int n_in,
                              void* d_out, int out_size) {
    const float* x     = (const float*)d_in[0];
    const int*   ei    = (const int*)d_in[1];
    const float* ea    = (const float*)d_in[2];
    const int*   batch = (const int*)d_in[3];
    const float* s1W = (const float*)d_in[4];
    const float* s1b = (const float*)d_in[5];
    const float* c1Wl = (const float*)d_in[6];
    const float* c1bl = (const float*)d_in[7];
    const float* c1Wr = (const float*)d_in[8];
    const float* c1br = (const float*)d_in[9];
    const float* c1We = (const float*)d_in[10];
    const float* c1att = (const float*)d_in[11];
    const float* c1bias = (const float*)d_in[12];
    const float* bn1g = (const float*)d_in[13];
    const float* bn1b = (const float*)d_in[14];
    const float* s2W = (const float*)d_in[15];
    const float* s2b = (const float*)d_in[16];
    const float* c2Wl = (const float*)d_in[17];
    const float* c2bl = (const float*)d_in[18];
    const float* c2Wr = (const float*)d_in[19];
    const float* c2br = (const float*)d_in[20];
    const float* c2We = (const float*)d_in[21];
    const float* c2att = (const float*)d_in[22];
    const float* c2bias = (const float*)d_in[23];
    const float* bn2g = (const float*)d_in[24];
    const float* bn2b = (const float*)d_in[25];
    float* out = (float*)d_out;

    clear_kernel<<<2048, 256>>>();
    pack1_kernel<<<32, 256>>>(c1Wl, c1bl, c1Wr, c1br, s1W, s1b);
    pack2_kernel<<<8, 256>>>(c2Wl, c2bl, c2Wr, c2br, s2W, s2b);
    easum_kernel<<<1024, 256>>>((const float4*)ea);
    eself_kernel<<<1, 64>>>(c1We, c2We);

    gemm1_kernel<<<dim3((N_NODES + 63) / 64, 2), 256>>>(x);
    edge1_kernel<<<2048, 256>>>(ei, ea, c1We, c1att);
    final1_kernel<<<512, 256>>>(c1bias);
    bnfin1_kernel<<<1, 64>>>(bn1g, bn1b);
    elu1_kernel<<<2048, 256>>>(c1bias);

    gemm2_kernel<<<dim3((N_NODES + 63) / 64, 1), 256>>>();
    edge2_kernel<<<1536, 256>>>(ei, ea, c2We, c2att);
    final2_kernel<<<512, 256>>>(c2bias);
    bnfin2_kernel<<<1, 32>>>(bn2g, bn2b);
    elu2pool_kernel<<<256, 256>>>(batch, c2bias);
    finalout_kernel<<<1, 1024>>>(out);
}

// round 13
// speedup vs baseline: 1.7544x; 1.0486x over previous
#include <cuda_runtime.h>
#include <cstdint>

#define N_NODES 50000
#define N_EDGES 800000
#define NE_TOT  (N_EDGES + N_NODES)   // 850000, self loops appended
#define NG 16

typedef unsigned long long ull;

// ---------------- scratch ----------------
__device__ __align__(16) float g_big1[N_NODES * 192];   // 0-63 xl1 | 64-127 xr1 | 128-191 hproj1
__device__ __align__(16) float g_big2[N_NODES * 96];    // 0-31 xl2 | 32-63 xr2 | 64-95 hproj2
__device__ __align__(16) float g_acc1[N_NODES * 64];
__device__ __align__(16) float g_den1[N_NODES * 2];
__device__ __align__(16) float g_acc2[N_NODES * 32];
__device__ __align__(16) float g_den2[N_NODES];
__device__ __align__(16) float g_Wcat1[128 * 192];
__device__ __align__(16) float g_bcat1[192];
__device__ __align__(16) float g_Wcat2[64 * 96];
__device__ __align__(16) float g_bcat2[96];
__device__ __align__(16) float g_easum[16];
__device__ __align__(16) float g_eself1[64];
__device__ __align__(16) float g_eself2[32];
__device__ __align__(16) float g_bnsum[128];     // [0:64) sum, [64:128) sumsq
__device__ __align__(16) float g_bnsc1[128];     // [0:64) scale, [64:128) shift
__device__ __align__(16) float g_bnsum2[64];
__device__ __align__(16) float g_bnsc2[64];
__device__ __align__(16) float g_psum[NG * 32];
__device__ __align__(16) float g_pmax[NG * 32];
__device__ int g_cnt[NG];

// ---------------- helpers ----------------
__device__ __forceinline__ ull pk2(float a, float b) {
    ull r; asm("mov.b64 %0,{%1,%2};" : "=l"(r) : "f"(a), "f"(b)); return r;
}
__device__ __forceinline__ float2 up2(ull v) {
    float2 r; asm("mov.b64 {%0,%1},%2;" : "=f"(r.x), "=f"(r.y) : "l"(v)); return r;
}
__device__ __forceinline__ ull fma2(ull a, ull b, ull c) {
    ull d; asm("fma.rn.f32x2 %0,%1,%2,%3;" : "=l"(d) : "l"(a), "l"(b), "l"(c)); return d;
}
__device__ __forceinline__ float lrelu(float v) { return v > 0.f ? v : 0.2f * v; }

__device__ __forceinline__ void red4(float* p, float4 v) {
    asm volatile("red.global.add.v4.f32 [%0], {%1,%2,%3,%4};"
                 :: "l"(p), "f"(v.x), "f"(v.y), "f"(v.z), "f"(v.w) : "memory");
}

__device__ __forceinline__ void atomicMaxF(float* addr, float v) {
    if (v >= 0.f) atomicMax((int*)addr, __float_as_int(v));
    else          atomicMin((unsigned int*)addr, __float_as_uint(v));
}

// ---------------- clear (vectorized) ----------------
__global__ void clear_kernel() {
    int i  = blockIdx.x * blockDim.x + threadIdx.x;
    int st = gridDim.x * blockDim.x;
    float4 z4 = make_float4(0.f, 0.f, 0.f, 0.f);
    float4* a1 = (float4*)g_acc1;
    float4* a2 = (float4*)g_acc2;
    for (int j = i; j < N_NODES * 16; j += st) a1[j] = z4;
    for (int j = i; j < N_NODES * 8;  j += st) a2[j] = z4;
    float2* d1 = (float2*)g_den1;
    for (int j = i; j < N_NODES; j += st) { d1[j] = make_float2(0.f, 0.f); g_den2[j] = 0.f; }
    if (i < 16)  g_easum[i] = 0.f;
    if (i < 128) g_bnsum[i] = 0.f;
    if (i < 64)  g_bnsum2[i] = 0.f;
    if (i < NG * 32) { g_psum[i] = 0.f; g_pmax[i] = __int_as_float(0xff800000); }
    if (i < NG)  g_cnt[i] = 0;
}

// ---------------- weight packing ----------------
__global__ void pack1_kernel(const float* __restrict__ Wl, const float* __restrict__ bl,
                             const float* __restrict__ Wr, const float* __restrict__ br,
                             const float* __restrict__ Ws, const float* __restrict__ bs) {
    int i = blockIdx.x * blockDim.x + threadIdx.x;
    if (i < 128 * 64) {
        int k = i >> 6, j = i & 63;
        g_Wcat1[k * 192 + j]       = Wl[i];
        g_Wcat1[k * 192 + 64 + j]  = Wr[i];
        g_Wcat1[k * 192 + 128 + j] = Ws[i];
    }
    if (i < 64) { g_bcat1[i] = bl[i]; g_bcat1[64 + i] = br[i]; g_bcat1[128 + i] = bs[i]; }
}

__global__ void pack2_kernel(const float* __restrict__ Wl, const float* __restrict__ bl,
                             const float* __restrict__ Wr, const float* __restrict__ br,
                             const float* __restrict__ Ws, const float* __restrict__ bs) {
    int i = blockIdx.x * blockDim.x + threadIdx.x;
    if (i < 64 * 32) {
        int k = i >> 5, j = i & 31;
        g_Wcat2[k * 96 + j]      = Wl[i];
        g_Wcat2[k * 96 + 32 + j] = Wr[i];
        g_Wcat2[k * 96 + 64 + j] = Ws[i];
    }
    if (i < 32) { g_bcat2[i] = bl[i]; g_bcat2[32 + i] = br[i]; g_bcat2[64 + i] = bs[i]; }
}

// ---------------- edge_attr column sums ----------------
__global__ void easum_kernel(const float4* __restrict__ ea4) {
    const int NT = N_EDGES * 4;
    int tid = blockIdx.x * blockDim.x + threadIdx.x;
    int st  = gridDim.x * blockDim.x;
    int grp = tid & 3;
    float4 s = make_float4(0.f, 0.f, 0.f, 0.f);
    int i = tid;
    for (; i + 3 * st < NT; i += 4 * st) {
        float4 v0 = ea4[i];
        float4 v1 = ea4[i + st];
        float4 v2 = ea4[i + 2 * st];
        float4 v3 = ea4[i + 3 * st];
        s.x += v0.x + v1.x + v2.x + v3.x;
        s.y += v0.y + v1.y + v2.y + v3.y;
        s.z += v0.z + v1.z + v2.z + v3.z;
        s.w += v0.w + v1.w + v2.w + v3.w;
    }
    for (; i < NT; i += st) {
        float4 v = ea4[i];
        s.x += v.x; s.y += v.y; s.z += v.z; s.w += v.w;
    }
    __shared__ float sm[16];
    if (threadIdx.x < 16) sm[threadIdx.x] = 0.f;
    __syncthreads();
    atomicAdd(&sm[grp * 4 + 0], s.x);
    atomicAdd(&sm[grp * 4 + 1], s.y);
    atomicAdd(&sm[grp * 4 + 2], s.z);
    atomicAdd(&sm[grp * 4 + 3], s.w);
    __syncthreads();
    if (threadIdx.x < 16) atomicAdd(&g_easum[threadIdx.x], sm[threadIdx.x]);
}

__global__ void eself_kernel(const float* __restrict__ We1, const float* __restrict__ We2) {
    __shared__ float m[16];
    int t = threadIdx.x;
    if (t < 16) m[t] = g_easum[t] * (1.0f / N_EDGES);
    __syncthreads();
    if (t < 64) {
        float s = 0.f;
        #pragma unroll
        for (int k = 0; k < 16; k++) s += m[k] * We1[k * 64 + t];
        g_eself1[t] = s;
    }
    if (t < 32) {
        float s = 0.f;
        #pragma unroll
        for (int k = 0; k < 16; k++) s += m[k] * We2[k * 32 + t];
        g_eself2[t] = s;
    }
}

// ---------------- tiled GEMM 1 with fma.rn.f32x2 (validated) ----------------
__global__ void gemm1_kernel(const float* __restrict__ A) {
    const int K = 128, NT = 192;
    __shared__ __align__(16) float As[16 * 68];
    __shared__ __align__(8)  float Bs[16 * 100];
    const int bm = blockIdx.x * 64;
    const int bn = blockIdx.y * 96;
    const int tid = threadIdx.x;
    const int tx = tid & 15, ty = tid >> 4;
    ull acc[4][3];
    #pragma unroll
    for (int i = 0; i < 4; i++)
        #pragma unroll
        for (int j = 0; j < 3; j++) acc[i][j] = 0ull;
    const int ar = tid >> 2, ac = (tid & 3) << 2;
    for (int k0 = 0; k0 < K; k0 += 16) {
        float4 av = make_float4(0.f, 0.f, 0.f, 0.f);
        int row = bm + ar;
        if (row < N_NODES) av = *(const float4*)&A[(size_t)row * K + k0 + ac];
        As[(ac + 0) * 68 + ar] = av.x;
        As[(ac + 1) * 68 + ar] = av.y;
        As[(ac + 2) * 68 + ar] = av.z;
        As[(ac + 3) * 68 + ar] = av.w;
        #pragma unroll
        for (int i = 0; i < 6; i++) {
            int idx = tid + (i << 8);
            int r = idx / 96, cc = idx - r * 96;
            Bs[r * 100 + cc] = g_Wcat1[(k0 + r) * NT + bn + cc];
        }
        __syncthreads();
        #pragma unroll
        for (int kk = 0; kk < 16; kk++) {
            float4 a = *(const float4*)&As[kk * 68 + (ty << 2)];
            ull b0 = *(const ull*)&Bs[kk * 100 + tx * 6];
            ull b1 = *(const ull*)&Bs[kk * 100 + tx * 6 + 2];
            ull b2 = *(const ull*)&Bs[kk * 100 + tx * 6 + 4];
            ull ap;
            ap = pk2(a.x, a.x);
            acc[0][0] = fma2(ap, b0, acc[0][0]); acc[0][1] = fma2(ap, b1, acc[0][1]); acc[0][2] = fma2(ap, b2, acc[0][2]);
            ap = pk2(a.y, a.y);
            acc[1][0] = fma2(ap, b0, acc[1][0]); acc[1][1] = fma2(ap, b1, acc[1][1]); acc[1][2] = fma2(ap, b2, acc[1][2]);
            ap = pk2(a.z, a.z);
            acc[2][0] = fma2(ap, b0, acc[2][0]); acc[2][1] = fma2(ap, b1, acc[2][1]); acc[2][2] = fma2(ap, b2, acc[2][2]);
            ap = pk2(a.w, a.w);
            acc[3][0] = fma2(ap, b0, acc[3][0]); acc[3][1] = fma2(ap, b1, acc[3][1]); acc[3][2] = fma2(ap, b2, acc[3][2]);
        }
        __syncthreads();
    }
    #pragma unroll
    for (int i = 0; i < 4; i++) {
        int r = bm + (ty << 2) + i;
        if (r < N_NODES) {
            #pragma unroll
            for (int j = 0; j < 3; j++) {
                float2 v = up2(acc[i][j]);
                int cc = bn + tx * 6 + 2 * j;
                g_big1[(size_t)r * NT + cc]     = v.x + g_bcat1[cc];
                g_big1[(size_t)r * NT + cc + 1] = v.y + g_bcat1[cc + 1];
            }
        }
    }
}

// ---------------- GEMM 2 with elu1 FUSED into the A-tile load ----------------
// A[row][c] = elu( (acc1[row][c]/den + bias1[c]) * bnsc1[c] + bnsc1[64+c] + big1[row][128+c] )
__global__ void gemm2_kernel(const float* __restrict__ bias1) {
    const int K = 64, NT = 96;
    __shared__ __align__(16) float As[16 * 68];
    __shared__ __align__(8)  float Bs[16 * 100];
    const int bm = blockIdx.x * 64;
    const int bn = 0;
    const int tid = threadIdx.x;
    const int tx = tid & 15, ty = tid >> 4;
    ull acc[4][3];
    #pragma unroll
    for (int i = 0; i < 4; i++)
        #pragma unroll
        for (int j = 0; j < 3; j++) acc[i][j] = 0ull;
    const int ar = tid >> 2, ac = (tid & 3) << 2;
    for (int k0 = 0; k0 < K; k0 += 16) {
        float4 av = make_float4(0.f, 0.f, 0.f, 0.f);
        int row = bm + ar;
        if (row < N_NODES) {
            int cc = k0 + ac;                           // 0..60, 4 cols within one head block
            float invd = 1.0f / (g_den1[row * 2 + (cc >> 5)] + 1e-16f);
            float4 a4 = *(const float4*)&g_acc1[(size_t)row * 64 + cc];
            float4 p4 = *(const float4*)&g_big1[(size_t)row * 192 + 128 + cc];
            float t;
            t = (a4.x * invd + bias1[cc + 0]) * g_bnsc1[cc + 0] + g_bnsc1[64 + cc + 0] + p4.x;
            av.x = t > 0.f ? t : expm1f(t);
            t = (a4.y * invd + bias1[cc + 1]) * g_bnsc1[cc + 1] + g_bnsc1[64 + cc + 1] + p4.y;
            av.y = t > 0.f ? t : expm1f(t);
            t = (a4.z * invd + bias1[cc + 2]) * g_bnsc1[cc + 2] + g_bnsc1[64 + cc + 2] + p4.z;
            av.z = t > 0.f ? t : expm1f(t);
            t = (a4.w * invd + bias1[cc + 3]) * g_bnsc1[cc + 3] + g_bnsc1[64 + cc + 3] + p4.w;
            av.w = t > 0.f ? t : expm1f(t);
        }
        As[(ac + 0) * 68 + ar] = av.x;
        As[(ac + 1) * 68 + ar] = av.y;
        As[(ac + 2) * 68 + ar] = av.z;
        As[(ac + 3) * 68 + ar] = av.w;
        #pragma unroll
        for (int i = 0; i < 6; i++) {
            int idx = tid + (i << 8);
            int r = idx / 96, cc = idx - r * 96;
            Bs[r * 100 + cc] = g_Wcat2[(k0 + r) * NT + bn + cc];
        }
        __syncthreads();
        #pragma unroll
        for (int kk = 0; kk < 16; kk++) {
            float4 a = *(const float4*)&As[kk * 68 + (ty << 2)];
            ull b0 = *(const ull*)&Bs[kk * 100 + tx * 6];
            ull b1 = *(const ull*)&Bs[kk * 100 + tx * 6 + 2];
            ull b2 = *(const ull*)&Bs[kk * 100 + tx * 6 + 4];
            ull ap;
            ap = pk2(a.x, a.x);
            acc[0][0] = fma2(ap, b0, acc[0][0]); acc[0][1] = fma2(ap, b1, acc[0][1]); acc[0][2] = fma2(ap, b2, acc[0][2]);
            ap = pk2(a.y, a.y);
            acc[1][0] = fma2(ap, b0, acc[1][0]); acc[1][1] = fma2(ap, b1, acc[1][1]); acc[1][2] = fma2(ap, b2, acc[1][2]);
            ap = pk2(a.z, a.z);
            acc[2][0] = fma2(ap, b0, acc[2][0]); acc[2][1] = fma2(ap, b1, acc[2][1]); acc[2][2] = fma2(ap, b2, acc[2][2]);
            ap = pk2(a.w, a.w);
            acc[3][0] = fma2(ap, b0, acc[3][0]); acc[3][1] = fma2(ap, b1, acc[3][1]); acc[3][2] = fma2(ap, b2, acc[3][2]);
        }
        __syncthreads();
    }
    #pragma unroll
    for (int i = 0; i < 4; i++) {
        int r = bm + (ty << 2) + i;
        if (r < N_NODES) {
            #pragma unroll
            for (int j = 0; j < 3; j++) {
                float2 v = up2(acc[i][j]);
                int cc = bn + tx * 6 + 2 * j;
                g_big2[(size_t)r * NT + cc]     = v.x + g_bcat2[cc];
                g_big2[(size_t)r * NT + cc + 1] = v.y + g_bcat2[cc + 1];
            }
        }
    }
}

// ---------------- edge kernel layer 1 (smem-We; 2 edges in flight; validated R12) ----------------
__global__ void edge1_kernel(const int* __restrict__ ei, const float* __restrict__ ea,
                             const float* __restrict__ We, const float* __restrict__ att) {
    __shared__ __align__(16) float sWe[16 * 64];
    __shared__ __align__(16) float sAtt[64];
    __shared__ __align__(16) float sEself[64];
    for (int i = threadIdx.x; i < 16 * 64; i += blockDim.x) sWe[i] = We[i];
    if (threadIdx.x < 64) { sAtt[threadIdx.x] = att[threadIdx.x]; sEself[threadIdx.x] = g_eself1[threadIdx.x]; }
    __syncthreads();
    const int lane = threadIdx.x & 31;
    const int sub  = lane & 15;
    const int head = sub >> 3;
    const int half = lane >> 4;
    const int warp = threadIdx.x >> 5;
    const int nwarps = (gridDim.x * blockDim.x) >> 5;
    const int gw = blockIdx.x * (blockDim.x >> 5) + warp;
    const int npairs = (NE_TOT + 1) >> 1;
    const float4 a4  = *(const float4*)&sAtt[4 * sub];
    const float4 es4 = *(const float4*)&sEself[4 * sub];
    for (int p0 = gw; p0 < npairs; p0 += 2 * nwarps) {
        const int p1 = p0 + nwarps;
        const bool hasB = p1 < npairs;
        int eA = p0 * 2 + half;
        int eB = hasB ? (p1 * 2 + half) : 0;
        bool vA = eA < NE_TOT;
        bool vB = hasB && (eB < NE_TOT);
        int sA = 0, dA = 0, sB = 0, dB = 0;
        bool loopA = false, loopB = false;
        if (vA) {
            if (eA < N_EDGES) { sA = ei[eA]; dA = ei[N_EDGES + eA]; }
            else              { sA = dA = eA - N_EDGES; loopA = true; }
        }
        if (vB) {
            if (eB < N_EDGES) { sB = ei[eB]; dB = ei[N_EDGES + eB]; }
            else              { sB = dB = eB - N_EDGES; loopB = true; }
        }
        int exA = (vA && !loopA) ? eA : 0;
        int exB = (vB && !loopB) ? eB : 0;
        float eavA = ea[(size_t)exA * 16 + sub];
        float eavB = ea[(size_t)exB * 16 + sub];
        float4 xlA = *(const float4*)&g_big1[(size_t)sA * 192 + 4 * sub];
        float4 xrA = *(const float4*)&g_big1[(size_t)dA * 192 + 64 + 4 * sub];
        float4 xlB = *(const float4*)&g_big1[(size_t)sB * 192 + 4 * sub];
        float4 xrB = *(const float4*)&g_big1[(size_t)dB * 192 + 64 + 4 * sub];
        float4 e4A = make_float4(0.f, 0.f, 0.f, 0.f);
        float4 e4B = make_float4(0.f, 0.f, 0.f, 0.f);
        #pragma unroll
        for (int k = 0; k < 16; k++) {
            float aA = __shfl_sync(0xffffffffu, eavA, k, 16);
            float aB = __shfl_sync(0xffffffffu, eavB, k, 16);
            float4 w4 = *(const float4*)&sWe[k * 64 + 4 * sub];
            e4A.x += aA * w4.x; e4A.y += aA * w4.y; e4A.z += aA * w4.z; e4A.w += aA * w4.w;
            e4B.x += aB * w4.x; e4B.y += aB * w4.y; e4B.z += aB * w4.z; e4B.w += aB * w4.w;
        }
        if (loopA) e4A = es4;
        if (loopB) e4B = es4;
        float4 mA, mB;
        mA.x = lrelu(xlA.x + xrA.x + e4A.x);
        mA.y = lrelu(xlA.y + xrA.y + e4A.y);
        mA.z = lrelu(xlA.z + xrA.z + e4A.z);
        mA.w = lrelu(xlA.w + xrA.w + e4A.w);
        mB.x = lrelu(xlB.x + xrB.x + e4B.x);
        mB.y = lrelu(xlB.y + xrB.y + e4B.y);
        mB.z = lrelu(xlB.z + xrB.z + e4B.z);
        mB.w = lrelu(xlB.w + xrB.w + e4B.w);
        float pA = mA.x * a4.x + mA.y * a4.y + mA.z * a4.z + mA.w * a4.w;
        float pB = mB.x * a4.x + mB.y * a4.y + mB.z * a4.z + mB.w * a4.w;
        pA += __shfl_xor_sync(0xffffffffu, pA, 4);
        pB += __shfl_xor_sync(0xffffffffu, pB, 4);
        pA += __shfl_xor_sync(0xffffffffu, pA, 2);
        pB += __shfl_xor_sync(0xffffffffu, pB, 2);
        pA += __shfl_xor_sync(0xffffffffu, pA, 1);
        pB += __shfl_xor_sync(0xffffffffu, pB, 1);
        float wA = __expf(pA);
        float wB = __expf(pB);
        if (vA) {
            if ((sub & 7) == 0) atomicAdd(&g_den1[dA * 2 + head], wA);
            red4(&g_acc1[(size_t)dA * 64 + 4 * sub],
                 make_float4(wA * xlA.x, wA * xlA.y, wA * xlA.z, wA * xlA.w));
        }
        if (vB) {
            if ((sub & 7) == 0) atomicAdd(&g_den1[dB * 2 + head], wB);
            red4(&g_acc1[(size_t)dB * 64 + 4 * sub],
                 make_float4(wB * xlB.x, wB * xlB.y, wB * xlB.z, wB * xlB.w));
        }
    }
}

// ---------------- edge kernel layer 2 (smem-We; 2 quads in flight; validated R12) ----------------
__global__ void edge2_kernel(const int* __restrict__ ei, const float* __restrict__ ea,
                             const float* __restrict__ We, const float* __restrict__ att) {
    __shared__ __align__(16) float sWe[16 * 32];
    __shared__ __align__(16) float sAtt[32];
    __shared__ __align__(16) float sEself[32];
    for (int i = threadIdx.x; i < 512; i += blockDim.x) sWe[i] = We[i];
    if (threadIdx.x < 32) { sAtt[threadIdx.x] = att[threadIdx.x]; sEself[threadIdx.x] = g_eself2[threadIdx.x]; }
    __syncthreads();
    const int lane = threadIdx.x & 31;
    const int grp = lane >> 3, sub = lane & 7;
    const int warp = threadIdx.x >> 5;
    const int nwarps = (gridDim.x * blockDim.x) >> 5;
    const int gw = blockIdx.x * (blockDim.x >> 5) + warp;
    const int nquads = (NE_TOT + 3) >> 2;
    const float4 a4  = *(const float4*)&sAtt[4 * sub];
    const float4 es4 = *(const float4*)&sEself[4 * sub];
    for (int q0 = gw; q0 < nquads; q0 += 2 * nwarps) {
        const int q1 = q0 + nwarps;
        const bool hasB = q1 < nquads;
        int eA = q0 * 4 + grp;
        int eB = hasB ? (q1 * 4 + grp) : 0;
        bool vA = eA < NE_TOT;
        bool vB = hasB && (eB < NE_TOT);
        int sA = 0, dA = 0, sB = 0, dB = 0;
        bool loopA = false, loopB = false;
        if (vA) {
            if (eA < N_EDGES) { sA = ei[eA]; dA = ei[N_EDGES + eA]; }
            else              { sA = dA = eA - N_EDGES; loopA = true; }
        }
        if (vB) {
            if (eB < N_EDGES) { sB = ei[eB]; dB = ei[N_EDGES + eB]; }
            else              { sB = dB = eB - N_EDGES; loopB = true; }
        }
        int exA = (vA && !loopA) ? eA : 0;
        int exB = (vB && !loopB) ? eB : 0;
        float e0A = ea[(size_t)exA * 16 + sub];
        float e1A = ea[(size_t)exA * 16 + 8 + sub];
        float e0B = ea[(size_t)exB * 16 + sub];
        float e1B = ea[(size_t)exB * 16 + 8 + sub];
        float4 xlA = *(const float4*)&g_big2[(size_t)sA * 96 + 4 * sub];
        float4 xrA = *(const float4*)&g_big2[(size_t)dA * 96 + 32 + 4 * sub];
        float4 xlB = *(const float4*)&g_big2[(size_t)sB * 96 + 4 * sub];
        float4 xrB = *(const float4*)&g_big2[(size_t)dB * 96 + 32 + 4 * sub];
        float4 e4A = make_float4(0.f, 0.f, 0.f, 0.f);
        float4 e4B = make_float4(0.f, 0.f, 0.f, 0.f);
        #pragma unroll
        for (int k = 0; k < 8; k++) {
            float aA = __shfl_sync(0xffffffffu, e0A, k, 8);
            float aB = __shfl_sync(0xffffffffu, e0B, k, 8);
            float4 w4 = *(const float4*)&sWe[k * 32 + 4 * sub];
            e4A.x += aA * w4.x; e4A.y += aA * w4.y; e4A.z += aA * w4.z; e4A.w += aA * w4.w;
            e4B.x += aB * w4.x; e4B.y += aB * w4.y; e4B.z += aB * w4.z; e4B.w += aB * w4.w;
        }
        #pragma unroll
        for (int k = 0; k < 8; k++) {
            float aA = __shfl_sync(0xffffffffu, e1A, k, 8);
            float aB = __shfl_sync(0xffffffffu, e1B, k, 8);
            float4 w4 = *(const float4*)&sWe[(8 + k) * 32 + 4 * sub];
            e4A.x += aA * w4.x; e4A.y += aA * w4.y; e4A.z += aA * w4.z; e4A.w += aA * w4.w;
            e4B.x += aB * w4.x; e4B.y += aB * w4.y; e4B.z += aB * w4.z; e4B.w += aB * w4.w;
        }
        if (loopA) e4A = es4;
        if (loopB) e4B = es4;
        float4 mA, mB;
        mA.x = lrelu(xlA.x + xrA.x + e4A.x);
        mA.y = lrelu(xlA.y + xrA.y + e4A.y);
        mA.z = lrelu(xlA.z + xrA.z + e4A.z);
        mA.w = lrelu(xlA.w + xrA.w + e4A.w);
        mB.x = lrelu(xlB.x + xrB.x + e4B.x);
        mB.y = lrelu(xlB.y + xrB.y + e4B.y);
        mB.z = lrelu(xlB.z + xrB.z + e4B.z);
        mB.w = lrelu(xlB.w + xrB.w + e4B.w);
        float pA = mA.x * a4.x + mA.y * a4.y + mA.z * a4.z + mA.w * a4.w;
        float pB = mB.x * a4.x + mB.y * a4.y + mB.z * a4.z + mB.w * a4.w;
        pA += __shfl_xor_sync(0xffffffffu, pA, 4);
        pB += __shfl_xor_sync(0xffffffffu, pB, 4);
        pA += __shfl_xor_sync(0xffffffffu, pA, 2);
        pB += __shfl_xor_sync(0xffffffffu, pB, 2);
        pA += __shfl_xor_sync(0xffffffffu, pA, 1);
        pB += __shfl_xor_sync(0xffffffffu, pB, 1);
        float wA = __expf(pA);
        float wB = __expf(pB);
        if (vA) {
            if (sub == 0) atomicAdd(&g_den2[dA], wA);
            red4(&g_acc2[(size_t)dA * 32 + 4 * sub],
                 make_float4(wA * xlA.x, wA * xlA.y, wA * xlA.z, wA * xlA.w));
        }
        if (vB) {
            if (sub == 0) atomicAdd(&g_den2[dB], wB);
            red4(&g_acc2[(size_t)dB * 32 + 4 * sub],
                 make_float4(wB * xlB.x, wB * xlB.y, wB * xlB.z, wB * xlB.w));
        }
    }
}

// ---------------- BN stats layer 1 (fused) ----------------
__global__ void final1_kernel(const float* __restrict__ bias) {
    int tid = threadIdx.x;
    int c = tid & 63;
    int h = c >> 5;
    float bb = bias[c];
    float s = 0.f, q = 0.f;
    for (int n = blockIdx.x * 4 + (tid >> 6); n < N_NODES; n += gridDim.x * 4) {
        float v = g_acc1[(size_t)n * 64 + c] / (g_den1[n * 2 + h] + 1e-16f) + bb;
        s += v; q += v * v;
    }
    __shared__ float ss[256], sq[256];
    ss[tid] = s; sq[tid] = q;
    __syncthreads();
    if (tid < 64) {
        s = ss[tid] + ss[tid + 64] + ss[tid + 128] + ss[tid + 192];
        q = sq[tid] + sq[tid + 64] + sq[tid + 128] + sq[tid + 192];
        atomicAdd(&g_bnsum[tid], s);
        atomicAdd(&g_bnsum[64 + tid], q);
    }
}

__global__ void bnfin1_kernel(const float* __restrict__ g, const float* __restrict__ b) {
    int c = threadIdx.x;
    if (c < 64) {
        float mean = g_bnsum[c] * (1.0f / N_NODES);
        float var  = g_bnsum[64 + c] * (1.0f / N_NODES) - mean * mean;
        float sc   = g[c] * rsqrtf(var + 1e-5f);
        g_bnsc1[c] = sc;
        g_bnsc1[64 + c] = b[c] - mean * sc;
    }
}

// ---------------- BN stats layer 2 (fused) ----------------
__global__ void final2_kernel(const float* __restrict__ bias) {
    int tid = threadIdx.x;
    int c = tid & 31;
    float bb = bias[c];
    float s = 0.f, q = 0.f;
    for (int n = blockIdx.x * 8 + (tid >> 5); n < N_NODES; n += gridDim.x * 8) {
        float v = g_acc2[(size_t)n * 32 + c] / (g_den2[n] + 1e-16f) + bb;
        s += v; q += v * v;
    }
    __shared__ float ss[256], sq[256];
    ss[tid] = s; sq[tid] = q;
    __syncthreads();
    if (tid < 32) {
        s = 0.f; q = 0.f;
        #pragma unroll
        for (int gg = 0; gg < 8; gg++) { s += ss[tid + gg * 32]; q += sq[tid + gg * 32]; }
        atomicAdd(&g_bnsum2[tid], s);
        atomicAdd(&g_bnsum2[32 + tid], q);
    }
}

__global__ void bnfin2_kernel(const float* __restrict__ g, const float* __restrict__ b) {
    int c = threadIdx.x;
    if (c < 32) {
        float mean = g_bnsum2[c] * (1.0f / N_NODES);
        float var  = g_bnsum2[32 + c] * (1.0f / N_NODES) - mean * mean;
        float sc   = g[c] * rsqrtf(var + 1e-5f);
        g_bnsc2[c] = sc;
        g_bnsc2[32 + c] = b[c] - mean * sc;
    }
}

// ---------------- elu2 + graph pooling (batch sorted; fused recompute) ----------------
__global__ void elu2pool_kernel(const int* __restrict__ batch, const float* __restrict__ bias) {
    __shared__ float ssum[NG * 32];
    __shared__ float smax[NG * 32];
    __shared__ int scnt[NG];
    int tid = threadIdx.x;
    for (int i = tid; i < NG * 32; i += blockDim.x) { ssum[i] = 0.f; smax[i] = __int_as_float(0xff800000); }
    if (tid < NG) scnt[tid] = 0;
    __syncthreads();
    int c = tid & 31;
    float bb = bias[c];
    for (int n = blockIdx.x * 8 + (tid >> 5); n < N_NODES; n += gridDim.x * 8) {
        float v = g_acc2[(size_t)n * 32 + c] / (g_den2[n] + 1e-16f) + bb;
        v = v * g_bnsc2[c] + g_bnsc2[32 + c] + g_big2[(size_t)n * 96 + 64 + c];
        v = v > 0.f ? v : expm1f(v);
        int g = batch[n];
        atomicAdd(&ssum[g * 32 + c], v);
        if (v >= 0.f) atomicMax((int*)&smax[g * 32 + c], __float_as_int(v));
        else          atomicMin((unsigned int*)&smax[g * 32 + c], __float_as_uint(v));
        if (c == 0) atomicAdd(&scnt[g], 1);
    }
    __syncthreads();
    for (int i = tid; i < NG * 32; i += blockDim.x) {
        atomicAdd(&g_psum[i], ssum[i]);
        atomicMaxF(&g_pmax[i], smax[i]);
    }
    if (tid < NG) atomicAdd(&g_cnt[tid], scnt[tid]);
}

__global__ void finalout_kernel(float* __restrict__ out) {
    int tid = threadIdx.x;
    if (tid < NG * 64) {
        int g = tid >> 6, j = tid & 63;
        int cnt = g_cnt[g];
        float r;
        if (j < 32) r = g_psum[g * 32 + j] / fmaxf((float)cnt, 1.0f);
        else        r = (cnt > 0) ? g_pmax[g * 32 + (j - 32)] : 0.0f;
        out[tid] = r;
    }
}

// ---------------- launch (stream-overlapped prologue) ----------------
extern "C" void kernel_launch(void* const* d_in, const int* in_sizes, int n_in,
                              void* d_out, int out_size) {
    const float* x     = (const float*)d_in[0];
    const int*   ei    = (const int*)d_in[1];
    const float* ea    = (const float*)d_in[2];
    const int*   batch = (const int*)d_in[3];
    const float* s1W = (const float*)d_in[4];
    const float* s1b = (const float*)d_in[5];
    const float* c1Wl = (const float*)d_in[6];
    const float* c1bl = (const float*)d_in[7];
    const float* c1Wr = (const float*)d_in[8];
    const float* c1br = (const float*)d_in[9];
    const float* c1We = (const float*)d_in[10];
    const float* c1att = (const float*)d_in[11];
    const float* c1bias = (const float*)d_in[12];
    const float* bn1g = (const float*)d_in[13];
    const float* bn1b = (const float*)d_in[14];
    const float* s2W = (const float*)d_in[15];
    const float* s2b = (const float*)d_in[16];
    const float* c2Wl = (const float*)d_in[17];
    const float* c2bl = (const float*)d_in[18];
    const float* c2Wr = (const float*)d_in[19];
    const float* c2br = (const float*)d_in[20];
    const float* c2We = (const float*)d_in[21];
    const float* c2att = (const float*)d_in[22];
    const float* c2bias = (const float*)d_in[23];
    const float* bn2g = (const float*)d_in[24];
    const float* bn2b = (const float*)d_in[25];
    float* out = (float*)d_out;

    static cudaStream_t sB = nullptr;
    static cudaEvent_t ev0 = nullptr, evB = nullptr;
    if (sB == nullptr) {
        cudaStreamCreateWithFlags(&sB, cudaStreamNonBlocking);
        cudaEventCreateWithFlags(&ev0, cudaEventDisableTiming);
        cudaEventCreateWithFlags(&evB, cudaEventDisableTiming);
    }

    // fork: side chain (clear + pack2 + easum -> eself) runs concurrent with pack1 -> gemm1
    cudaEventRecord(ev0, 0);
    cudaStreamWaitEvent(sB, ev0, 0);

    clear_kernel<<<2048, 256, 0, sB>>>();
    pack2_kernel<<<8, 256, 0, sB>>>(c2Wl, c2bl, c2Wr, c2br, s2W, s2b);
    easum_kernel<<<1024, 256, 0, sB>>>((const float4*)ea);
    eself_kernel<<<1, 64, 0, sB>>>(c1We, c2We);
    cudaEventRecord(evB, sB);

    pack1_kernel<<<32, 256>>>(c1Wl, c1bl, c1Wr, c1br, s1W, s1b);
    gemm1_kernel<<<dim3((N_NODES + 63) / 64, 2), 256>>>(x);

    // join before edge1 (needs clear + gemm1 + eself)
    cudaStreamWaitEvent(0, evB, 0);

    edge1_kernel<<<2048, 256>>>(ei, ea, c1We, c1att);
    final1_kernel<<<512, 256>>>(c1bias);
    bnfin1_kernel<<<1, 64>>>(bn1g, bn1b);

    gemm2_kernel<<<dim3((N_NODES + 63) / 64, 1), 256>>>(c1bias);   // elu1 fused into A load
    edge2_kernel<<<1536, 256>>>(ei, ea, c2We, c2att);
    final2_kernel<<<512, 256>>>(c2bias);
    bnfin2_kernel<<<1, 32>>>(bn2g, bn2b);
    elu2pool_kernel<<<256, 256>>>(batch, c2bias);
    finalout_kernel<<<1, 1024>>>(out);
}